// round 7
// baseline (speedup 1.0000x reference)
#include <cuda_runtime.h>
#include <cuda_bf16.h>
#include <math.h>

#define SEQ  4096
#define EMB  2048
#define NH   16
#define NKVH 4
#define HD   128
#define WIN  2048
#define QDIM (NH*HD)    /* 2048 */
#define KVDIM (NKVH*HD) /* 512  */

// -------- scratch (device globals; no allocations allowed) --------
__device__ float g_q [SEQ * QDIM];    // q proj out (fp32, rope input)
__device__ float g_k [SEQ * KVDIM];   // k proj out (fp32, rope input)
__device__ __nv_bfloat16 g_qh[SEQ*QDIM],  g_ql[SEQ*QDIM];    // rope'd+scaled q split
__device__ __nv_bfloat16 g_kh[SEQ*KVDIM], g_kl[SEQ*KVDIM];   // rope'd k split
__device__ __nv_bfloat16 g_vh[SEQ*KVDIM], g_vl[SEQ*KVDIM];   // v proj split
__device__ __nv_bfloat16 g_ath[SEQ*QDIM], g_atl[SEQ*QDIM];   // attention out split
__device__ __nv_bfloat16 g_xqh[SEQ*EMB],  g_xql[SEQ*EMB];    // input splits
__device__ __nv_bfloat16 g_xkh[SEQ*EMB],  g_xkl[SEQ*EMB];
__device__ __nv_bfloat16 g_xvh[SEQ*EMB],  g_xvl[SEQ*EMB];
__device__ __nv_bfloat16 g_wqh[EMB*QDIM], g_wql[EMB*QDIM];   // weight splits
__device__ __nv_bfloat16 g_wkh[EMB*KVDIM],g_wkl[EMB*KVDIM];
__device__ __nv_bfloat16 g_wvh[EMB*KVDIM],g_wvl[EMB*KVDIM];
__device__ __nv_bfloat16 g_woh[QDIM*EMB], g_wol[QDIM*EMB];

// ---------------- PTX helpers ----------------
#define LDSM_X4(r0,r1,r2,r3,addr) \
  asm volatile("ldmatrix.sync.aligned.m8n8.x4.shared.b16 {%0,%1,%2,%3}, [%4];" \
    : "=r"(r0),"=r"(r1),"=r"(r2),"=r"(r3) : "r"(addr))

#define LDSM_X4_T(r0,r1,r2,r3,addr) \
  asm volatile("ldmatrix.sync.aligned.m8n8.x4.trans.shared.b16 {%0,%1,%2,%3}, [%4];" \
    : "=r"(r0),"=r"(r1),"=r"(r2),"=r"(r3) : "r"(addr))

#define MMA16816(c, a0,a1,a2,a3, b0,b1) \
  asm volatile("mma.sync.aligned.m16n8k16.row.col.f32.bf16.bf16.f32 " \
    "{%0,%1,%2,%3}, {%4,%5,%6,%7}, {%8,%9}, {%0,%1,%2,%3};" \
    : "+f"((c)[0]),"+f"((c)[1]),"+f"((c)[2]),"+f"((c)[3]) \
    : "r"(a0),"r"(a1),"r"(a2),"r"(a3),"r"(b0),"r"(b1))

#define CP_ASYNC16(dst32, srcptr) \
  asm volatile("cp.async.cg.shared.global [%0], [%1], 16;" :: "r"(dst32), "l"(srcptr))
#define CP_COMMIT() asm volatile("cp.async.commit_group;")
#define CP_WAIT0()  asm volatile("cp.async.wait_group 0;")

__device__ __forceinline__ unsigned pack_bf2(__nv_bfloat16 lo16, __nv_bfloat16 hi16) {
    return ((unsigned)__bfloat16_as_ushort(hi16) << 16) | (unsigned)__bfloat16_as_ushort(lo16);
}
__device__ __forceinline__ void split2(float x0, float x1, unsigned& hi, unsigned& lo) {
    __nv_bfloat16 h0 = __float2bfloat16(x0);
    __nv_bfloat16 h1 = __float2bfloat16(x1);
    __nv_bfloat16 l0 = __float2bfloat16(x0 - __bfloat162float(h0));
    __nv_bfloat16 l1 = __float2bfloat16(x1 - __bfloat162float(h1));
    hi = pack_bf2(h0, h1);
    lo = pack_bf2(l0, l1);
}

// =====================================================================
// merged elementwise fp32 -> bf16 hi/lo split (all 7 tensors, 1 launch)
// =====================================================================
struct SplitArg { const float4* s; uint2* h; uint2* l; int nblk; };
struct SplitPack { SplitArg a[7]; };

__global__ __launch_bounds__(256) void split_all(SplitPack p)
{
    int b = blockIdx.x;
    int seg = 0;
#pragma unroll
    for (int i = 0; i < 7; i++) {
        if (b >= p.a[seg].nblk) { b -= p.a[seg].nblk; seg++; }
    }
    const SplitArg sa = p.a[seg];
    int i = b * 256 + threadIdx.x;
    float4 v = sa.s[i];
    unsigned h0, l0, h1, l1;
    split2(v.x, v.y, h0, l0);
    split2(v.z, v.w, h1, l1);
    sa.h[i] = make_uint2(h0, h1);
    sa.l[i] = make_uint2(l0, l1);
}

// =====================================================================
// split-bf16 GEMM v3: cp.async double-buffered, dynamic smem (2x38KB).
// BM=BN=128, BK=32, 256 threads, warps 2(m) x 4(n).
// blockIdx.x segmented over up to 3 independent GEMMs (shared M, K).
// =====================================================================
#define A_STRIDE 40
#define B_STRIDE 136
#define G_AH 0
#define G_AL 10240
#define G_BH 20480
#define G_BL 29184
#define G_STAGE 37888
#define SMEM_GEMM (2*G_STAGE)   /* 75776 */

struct GArg {
    const __nv_bfloat16 *Ah, *Al, *Bh, *Bl;
    float* C;
    __nv_bfloat16 *Ch, *Cl;
    int N;
};

__global__ __launch_bounds__(256) void gemm3(
    GArg a0, GArg a1, GArg a2, int t0, int t1, int M, int K)
{
    extern __shared__ char smg[];
    const unsigned smu = (unsigned)__cvta_generic_to_shared(smg);

    GArg ga; int bx = blockIdx.x, bn;
    if (bx < t0)      { ga = a0; bn = bx * 128; }
    else if (bx < t1) { ga = a1; bn = (bx - t0) * 128; }
    else              { ga = a2; bn = (bx - t1) * 128; }
    const int N = ga.N;

    const int tid  = threadIdx.x;
    const int warp = tid >> 5;
    const int lane = tid & 31;
    const int wm   = warp >> 2;
    const int wn   = warp & 3;
    const int bm   = blockIdx.y * 128;

    float acc[4][4][4];
#pragma unroll
    for (int i = 0; i < 4; i++)
#pragma unroll
        for (int j = 0; j < 4; j++)
#pragma unroll
            for (int r = 0; r < 4; r++) acc[i][j][r] = 0.f;

    // chunk maps
    const int ar0 = tid >> 2,         au0 = (tid & 3) * 8;
    const int ar1 = (tid + 256) >> 2, au1 = ((tid + 256) & 3) * 8;
    const int br0 = tid >> 4,         bu0 = (tid & 15) * 8;
    const int br1 = (tid + 256) >> 4, bu1 = ((tid + 256) & 15) * 8;

    auto issue = [&](int stage, int k0) {
        unsigned sb = smu + stage * G_STAGE;
        CP_ASYNC16(sb + G_AH + 2u*(ar0*A_STRIDE + au0), ga.Ah + (size_t)(bm + ar0)*K + k0 + au0);
        CP_ASYNC16(sb + G_AH + 2u*(ar1*A_STRIDE + au1), ga.Ah + (size_t)(bm + ar1)*K + k0 + au1);
        CP_ASYNC16(sb + G_AL + 2u*(ar0*A_STRIDE + au0), ga.Al + (size_t)(bm + ar0)*K + k0 + au0);
        CP_ASYNC16(sb + G_AL + 2u*(ar1*A_STRIDE + au1), ga.Al + (size_t)(bm + ar1)*K + k0 + au1);
        CP_ASYNC16(sb + G_BH + 2u*(br0*B_STRIDE + bu0), ga.Bh + (size_t)(k0 + br0)*N + bn + bu0);
        CP_ASYNC16(sb + G_BH + 2u*(br1*B_STRIDE + bu1), ga.Bh + (size_t)(k0 + br1)*N + bn + bu1);
        CP_ASYNC16(sb + G_BL + 2u*(br0*B_STRIDE + bu0), ga.Bl + (size_t)(k0 + br0)*N + bn + bu0);
        CP_ASYNC16(sb + G_BL + 2u*(br1*B_STRIDE + bu1), ga.Bl + (size_t)(k0 + br1)*N + bn + bu1);
    };

    issue(0, 0);
    CP_COMMIT();

    const int niter = K / 32;
    for (int it = 0; it < niter; it++) {
        CP_WAIT0();
        __syncthreads();

        const int stage = it & 1;
        if (it + 1 < niter) {
            issue(stage ^ 1, (it + 1) * 32);
            CP_COMMIT();
        }

        const unsigned sa = smu + stage * G_STAGE;

#pragma unroll
        for (int ks = 0; ks < 32; ks += 16) {
            unsigned ah[4][4], al[4][4];
#pragma unroll
            for (int mi = 0; mi < 4; mi++) {
                unsigned off = 2u * ((unsigned)((wm*64 + mi*16 + (lane & 15)) * A_STRIDE
                                               + ks + (lane >> 4) * 8));
                LDSM_X4(ah[mi][0], ah[mi][1], ah[mi][2], ah[mi][3], sa + G_AH + off);
                LDSM_X4(al[mi][0], al[mi][1], al[mi][2], al[mi][3], sa + G_AL + off);
            }
            unsigned bh[4][2], bl[4][2];
#pragma unroll
            for (int nb = 0; nb < 2; nb++) {
                unsigned off = 2u * ((unsigned)((ks + (lane & 15)) * B_STRIDE
                                               + wn*32 + nb*16 + (lane >> 4) * 8));
                unsigned r0, r1, r2, r3;
                LDSM_X4_T(r0, r1, r2, r3, sa + G_BH + off);
                bh[2*nb][0] = r0; bh[2*nb][1] = r1;
                bh[2*nb+1][0] = r2; bh[2*nb+1][1] = r3;
                LDSM_X4_T(r0, r1, r2, r3, sa + G_BL + off);
                bl[2*nb][0] = r0; bl[2*nb][1] = r1;
                bl[2*nb+1][0] = r2; bl[2*nb+1][1] = r3;
            }
#pragma unroll
            for (int mi = 0; mi < 4; mi++) {
#pragma unroll
                for (int ni = 0; ni < 4; ni++) {
                    MMA16816(acc[mi][ni], ah[mi][0],ah[mi][1],ah[mi][2],ah[mi][3],
                             bh[ni][0], bh[ni][1]);
                    MMA16816(acc[mi][ni], ah[mi][0],ah[mi][1],ah[mi][2],ah[mi][3],
                             bl[ni][0], bl[ni][1]);
                    MMA16816(acc[mi][ni], al[mi][0],al[mi][1],al[mi][2],al[mi][3],
                             bh[ni][0], bh[ni][1]);
                }
            }
        }
        __syncthreads();
    }

    const int g = lane >> 2, q = lane & 3;
#pragma unroll
    for (int mi = 0; mi < 4; mi++) {
#pragma unroll
        for (int ni = 0; ni < 4; ni++) {
            int row = bm + wm*64 + mi*16 + g;
            int col = bn + wn*32 + ni*8 + q*2;
            if (ga.C) {
                *(float2*)&ga.C[(size_t)row * N + col]       = make_float2(acc[mi][ni][0], acc[mi][ni][1]);
                *(float2*)&ga.C[(size_t)(row + 8) * N + col] = make_float2(acc[mi][ni][2], acc[mi][ni][3]);
            }
            if (ga.Ch) {
                unsigned h0, l0;
                split2(acc[mi][ni][0], acc[mi][ni][1], h0, l0);
                *(unsigned*)&ga.Ch[(size_t)row * N + col] = h0;
                *(unsigned*)&ga.Cl[(size_t)row * N + col] = l0;
                split2(acc[mi][ni][2], acc[mi][ni][3], h0, l0);
                *(unsigned*)&ga.Ch[(size_t)(row + 8) * N + col] = h0;
                *(unsigned*)&ga.Cl[(size_t)(row + 8) * N + col] = l0;
            }
        }
    }
}

// =====================================================================
// RoPE v2: rotate fp32 q/k, scale q by log2(e)/sqrt(HD), emit split bf16
// =====================================================================
__global__ __launch_bounds__(256) void rope2_kernel(
    const int* __restrict__ pos_w,
    const float* __restrict__ q, const float* __restrict__ k,
    __nv_bfloat16* __restrict__ qh, __nv_bfloat16* __restrict__ ql,
    __nv_bfloat16* __restrict__ kh, __nv_bfloat16* __restrict__ kl)
{
    const int s = blockIdx.x;
    const int tid = threadIdx.x;
    __shared__ float cs[64], sn[64];

    const float QSCALE = (float)(1.4426950408889634 * 0.08838834764831845);

    if (tid < 64) {
        bool is64 = (pos_w[1] == 0);
        int pi = is64 ? pos_w[2 * s] : pos_w[s];
        float p = (float)pi;
        float ex = (float)(2 * tid) / (float)HD;
        float inv = powf(10000.0f, -ex);
        float ang = p * inv;
        sincosf(ang, &sn[tid], &cs[tid]);
    }
    __syncthreads();

    for (int idx = tid; idx < NH * 64; idx += 256) {
        int h = idx >> 6, d = idx & 63;
        size_t base = (size_t)s * QDIM + h * HD;
        float x1 = q[base + d], x2 = q[base + d + 64];
        float c = cs[d], si = sn[d];
        float y1 = (x1 * c - x2 * si) * QSCALE;
        float y2 = (x2 * c + x1 * si) * QSCALE;
        __nv_bfloat16 h1 = __float2bfloat16(y1);
        __nv_bfloat16 h2 = __float2bfloat16(y2);
        qh[base + d]      = h1;
        qh[base + d + 64] = h2;
        ql[base + d]      = __float2bfloat16(y1 - __bfloat162float(h1));
        ql[base + d + 64] = __float2bfloat16(y2 - __bfloat162float(h2));
    }
    for (int idx = tid; idx < NKVH * 64; idx += 256) {
        int h = idx >> 6, d = idx & 63;
        size_t base = (size_t)s * KVDIM + h * HD;
        float x1 = k[base + d], x2 = k[base + d + 64];
        float c = cs[d], si = sn[d];
        float y1 = x1 * c - x2 * si;
        float y2 = x2 * c + x1 * si;
        __nv_bfloat16 h1 = __float2bfloat16(y1);
        __nv_bfloat16 h2 = __float2bfloat16(y2);
        kh[base + d]      = h1;
        kh[base + d + 64] = h2;
        kl[base + d]      = __float2bfloat16(y1 - __bfloat162float(h1));
        kl[base + d + 64] = __float2bfloat16(y2 - __bfloat162float(h2));
    }
}

// =====================================================================
// MMA flash attention v2 (unchanged from round 6 — passing, cp.async
// double-buffered K/V, split bf16 in/out).
// =====================================================================
#define SMQ_H 0
#define SMQ_L 32768
#define KVBUF0 65536
#define KVSZ   65536
#define OF_KH  0
#define OF_KL  16384
#define OF_VH  32768
#define OF_VL  49152
#define SMEM_ATTN2 196608

__device__ __forceinline__ int swz(int row, int col_b16) {
    return row * 256 + ((((col_b16 >> 3) ^ (row & 7)) << 4)) + ((col_b16 & 7) << 1);
}

__global__ __launch_bounds__(256) void attn_mma2(
    const __nv_bfloat16* __restrict__ Qh, const __nv_bfloat16* __restrict__ Ql,
    const __nv_bfloat16* __restrict__ Kh, const __nv_bfloat16* __restrict__ Kl,
    const __nv_bfloat16* __restrict__ Vh, const __nv_bfloat16* __restrict__ Vl,
    __nv_bfloat16* __restrict__ Oh, __nv_bfloat16* __restrict__ Ol)
{
    extern __shared__ char sm[];
    const unsigned smu = (unsigned)__cvta_generic_to_shared(sm);

    const int tid  = threadIdx.x;
    const int warp = tid >> 5;
    const int lane = tid & 31;
    const int g    = lane >> 2;
    const int qd   = lane & 3;
    const int qb   = blockIdx.x;
    const int h    = blockIdx.y;
    const int kvh  = h >> 2;
    const int i0   = qb * 128;

    const int kb_lo = max(0, qb * 2 - 32);
    const int kb_hi = qb * 2 + 1;

    {
#pragma unroll
        for (int rep = 0; rep < 8; rep++) {
            int chunk = tid + rep * 256;
            int row = chunk >> 4, u = chunk & 15;
            unsigned dsto = row * 256 + (((u ^ (row & 7)) << 4));
            const __nv_bfloat16* sq = Qh + (size_t)(i0 + row) * QDIM + h * HD + u * 8;
            CP_ASYNC16(smu + SMQ_H + dsto, sq);
            const __nv_bfloat16* sl = Ql + (size_t)(i0 + row) * QDIM + h * HD + u * 8;
            CP_ASYNC16(smu + SMQ_L + dsto, sl);
        }
#pragma unroll
        for (int rep = 0; rep < 4; rep++) {
            int chunk = tid + rep * 256;
            int row = chunk >> 4, u = chunk & 15;
            unsigned dsto = row * 256 + (((u ^ (row & 7)) << 4));
            size_t srco = (size_t)(kb_lo * 64 + row) * KVDIM + kvh * HD + u * 8;
            CP_ASYNC16(smu + KVBUF0 + OF_KH + dsto, Kh + srco);
            CP_ASYNC16(smu + KVBUF0 + OF_KL + dsto, Kl + srco);
            CP_ASYNC16(smu + KVBUF0 + OF_VH + dsto, Vh + srco);
            CP_ASYNC16(smu + KVBUF0 + OF_VL + dsto, Vl + srco);
        }
        CP_COMMIT();
    }

    float o[16][4];
#pragma unroll
    for (int i = 0; i < 16; i++)
#pragma unroll
        for (int c = 0; c < 4; c++) o[i][c] = 0.f;

    float m0 = -1e30f, m1 = -1e30f, l0s = 0.f, l1s = 0.f;

    const int ig0 = i0 + warp * 16 + g;
    const int ig1 = ig0 + 8;

    for (int kb = kb_lo; kb <= kb_hi; kb++) {
        CP_WAIT0();
        __syncthreads();

        const int buf = (kb - kb_lo) & 1;
        const unsigned kvb = smu + KVBUF0 + buf * KVSZ;

        if (kb + 1 <= kb_hi) {
            const unsigned nb = smu + KVBUF0 + (buf ^ 1) * KVSZ;
#pragma unroll
            for (int rep = 0; rep < 4; rep++) {
                int chunk = tid + rep * 256;
                int row = chunk >> 4, u = chunk & 15;
                unsigned dsto = row * 256 + (((u ^ (row & 7)) << 4));
                size_t srco = (size_t)((kb + 1) * 64 + row) * KVDIM + kvh * HD + u * 8;
                CP_ASYNC16(nb + OF_KH + dsto, Kh + srco);
                CP_ASYNC16(nb + OF_KL + dsto, Kl + srco);
                CP_ASYNC16(nb + OF_VH + dsto, Vh + srco);
                CP_ASYNC16(nb + OF_VL + dsto, Vl + srco);
            }
            CP_COMMIT();
        }

        float S[8][4];
#pragma unroll
        for (int i = 0; i < 8; i++)
#pragma unroll
            for (int c = 0; c < 4; c++) S[i][c] = 0.f;

#pragma unroll
        for (int kc = 0; kc < 8; kc++) {
            unsigned ah0,ah1,ah2,ah3, al0,al1,al2,al3;
            {
                int aoff = swz(warp*16 + (lane & 15), kc*16 + (lane >> 4) * 8);
                LDSM_X4(ah0,ah1,ah2,ah3, smu + SMQ_H + aoff);
                LDSM_X4(al0,al1,al2,al3, smu + SMQ_L + aoff);
            }
#pragma unroll
            for (int ntp = 0; ntp < 4; ntp++) {
                int boff = swz(ntp*16 + (lane & 15), kc*16 + (lane >> 4) * 8);
                unsigned k0,k1,k2,k3, e0,e1,e2,e3;
                LDSM_X4(k0,k1,k2,k3, kvb + OF_KH + boff);
                LDSM_X4(e0,e1,e2,e3, kvb + OF_KL + boff);
                MMA16816(S[2*ntp],   ah0,ah1,ah2,ah3, k0,k2);
                MMA16816(S[2*ntp],   ah0,ah1,ah2,ah3, e0,e2);
                MMA16816(S[2*ntp],   al0,al1,al2,al3, k0,k2);
                MMA16816(S[2*ntp+1], ah0,ah1,ah2,ah3, k1,k3);
                MMA16816(S[2*ntp+1], ah0,ah1,ah2,ah3, e1,e3);
                MMA16816(S[2*ntp+1], al0,al1,al2,al3, k1,k3);
            }
        }

        bool need_mask = (kb >= qb*2) || (kb <= qb*2 - 31);
        if (need_mask) {
#pragma unroll
            for (int nt = 0; nt < 8; nt++) {
                int j0 = kb*64 + nt*8 + 2*qd;
                S[nt][0] = ((unsigned)(ig0 - j0)     <= (unsigned)WIN) ? S[nt][0] : -1e30f;
                S[nt][1] = ((unsigned)(ig0 - j0 - 1) <= (unsigned)WIN) ? S[nt][1] : -1e30f;
                S[nt][2] = ((unsigned)(ig1 - j0)     <= (unsigned)WIN) ? S[nt][2] : -1e30f;
                S[nt][3] = ((unsigned)(ig1 - j0 - 1) <= (unsigned)WIN) ? S[nt][3] : -1e30f;
            }
        }

        float mx0 = -1e30f, mx1 = -1e30f;
#pragma unroll
        for (int nt = 0; nt < 8; nt++) {
            mx0 = fmaxf(mx0, fmaxf(S[nt][0], S[nt][1]));
            mx1 = fmaxf(mx1, fmaxf(S[nt][2], S[nt][3]));
        }
        mx0 = fmaxf(mx0, __shfl_xor_sync(0xffffffffu, mx0, 1));
        mx0 = fmaxf(mx0, __shfl_xor_sync(0xffffffffu, mx0, 2));
        mx1 = fmaxf(mx1, __shfl_xor_sync(0xffffffffu, mx1, 1));
        mx1 = fmaxf(mx1, __shfl_xor_sync(0xffffffffu, mx1, 2));

        float mn0 = fmaxf(m0, mx0);
        float mn1 = fmaxf(m1, mx1);
        float a0 = exp2f(m0 - mn0);
        float a1 = exp2f(m1 - mn1);
        float ok0 = (mn0 > -5e29f) ? 1.f : 0.f;
        float ok1 = (mn1 > -5e29f) ? 1.f : 0.f;
        m0 = mn0; m1 = mn1;
        l0s *= a0; l1s *= a1;

#pragma unroll
        for (int nt = 0; nt < 8; nt++) {
            S[nt][0] = exp2f(S[nt][0] - mn0) * ok0;
            S[nt][1] = exp2f(S[nt][1] - mn0) * ok0;
            S[nt][2] = exp2f(S[nt][2] - mn1) * ok1;
            S[nt][3] = exp2f(S[nt][3] - mn1) * ok1;
            l0s += S[nt][0] + S[nt][1];
            l1s += S[nt][2] + S[nt][3];
        }

#pragma unroll
        for (int i = 0; i < 16; i++) {
            o[i][0] *= a0; o[i][1] *= a0;
            o[i][2] *= a1; o[i][3] *= a1;
        }

        unsigned ph[4][4], pl[4][4];
#pragma unroll
        for (int t = 0; t < 4; t++) {
            split2(S[2*t][0],   S[2*t][1],   ph[t][0], pl[t][0]);
            split2(S[2*t][2],   S[2*t][3],   ph[t][1], pl[t][1]);
            split2(S[2*t+1][0], S[2*t+1][1], ph[t][2], pl[t][2]);
            split2(S[2*t+1][2], S[2*t+1][3], ph[t][3], pl[t][3]);
        }

#pragma unroll
        for (int t = 0; t < 4; t++) {
#pragma unroll
            for (int ntp = 0; ntp < 8; ntp++) {
                int voff = swz(t*16 + (lane & 15), ntp*16 + (lane >> 4) * 8);
                unsigned v0,v1,v2,v3, w0,w1,w2,w3;
                LDSM_X4_T(v0,v1,v2,v3, kvb + OF_VH + voff);
                LDSM_X4_T(w0,w1,w2,w3, kvb + OF_VL + voff);
                MMA16816(o[2*ntp],   ph[t][0],ph[t][1],ph[t][2],ph[t][3], v0,v1);
                MMA16816(o[2*ntp],   ph[t][0],ph[t][1],ph[t][2],ph[t][3], w0,w1);
                MMA16816(o[2*ntp],   pl[t][0],pl[t][1],pl[t][2],pl[t][3], v0,v1);
                MMA16816(o[2*ntp+1], ph[t][0],ph[t][1],ph[t][2],ph[t][3], v2,v3);
                MMA16816(o[2*ntp+1], ph[t][0],ph[t][1],ph[t][2],ph[t][3], w2,w3);
                MMA16816(o[2*ntp+1], pl[t][0],pl[t][1],pl[t][2],pl[t][3], v2,v3);
            }
        }
    }

    l0s += __shfl_xor_sync(0xffffffffu, l0s, 1);
    l0s += __shfl_xor_sync(0xffffffffu, l0s, 2);
    l1s += __shfl_xor_sync(0xffffffffu, l1s, 1);
    l1s += __shfl_xor_sync(0xffffffffu, l1s, 2);
    float inv0 = 1.f / l0s;
    float inv1 = 1.f / l1s;

#pragma unroll
    for (int nt = 0; nt < 16; nt++) {
        int col = h * HD + nt * 8 + 2 * qd;
        unsigned h0, l0;
        split2(o[nt][0] * inv0, o[nt][1] * inv0, h0, l0);
        *(unsigned*)&Oh[(size_t)ig0 * QDIM + col] = h0;
        *(unsigned*)&Ol[(size_t)ig0 * QDIM + col] = l0;
        split2(o[nt][2] * inv1, o[nt][3] * inv1, h0, l0);
        *(unsigned*)&Oh[(size_t)ig1 * QDIM + col] = h0;
        *(unsigned*)&Ol[(size_t)ig1 * QDIM + col] = l0;
    }
}

// =====================================================================
extern "C" void kernel_launch(void* const* d_in, const int* in_sizes, int n_in,
                              void* d_out, int out_size)
{
    const float* query = (const float*)d_in[0];
    const float* key   = (const float*)d_in[1];
    const float* value = (const float*)d_in[2];
    const int*   pos   = (const int*)d_in[3];
    const float* wq    = (const float*)d_in[4];
    const float* wk    = (const float*)d_in[5];
    const float* wv    = (const float*)d_in[6];
    const float* wo    = (const float*)d_in[7];
    float*       out   = (float*)d_out;

    float *q_s, *k_s;
    __nv_bfloat16 *qh,*ql,*kh,*kl,*vh,*vl,*ath,*atl;
    __nv_bfloat16 *xqh,*xql,*xkh,*xkl,*xvh,*xvl;
    __nv_bfloat16 *wqh,*wql,*wkh,*wkl,*wvh,*wvl,*woh,*wol;
    cudaGetSymbolAddress((void**)&q_s, g_q);   cudaGetSymbolAddress((void**)&k_s, g_k);
    cudaGetSymbolAddress((void**)&qh, g_qh);   cudaGetSymbolAddress((void**)&ql, g_ql);
    cudaGetSymbolAddress((void**)&kh, g_kh);   cudaGetSymbolAddress((void**)&kl, g_kl);
    cudaGetSymbolAddress((void**)&vh, g_vh);   cudaGetSymbolAddress((void**)&vl, g_vl);
    cudaGetSymbolAddress((void**)&ath, g_ath); cudaGetSymbolAddress((void**)&atl, g_atl);
    cudaGetSymbolAddress((void**)&xqh, g_xqh); cudaGetSymbolAddress((void**)&xql, g_xql);
    cudaGetSymbolAddress((void**)&xkh, g_xkh); cudaGetSymbolAddress((void**)&xkl, g_xkl);
    cudaGetSymbolAddress((void**)&xvh, g_xvh); cudaGetSymbolAddress((void**)&xvl, g_xvl);
    cudaGetSymbolAddress((void**)&wqh, g_wqh); cudaGetSymbolAddress((void**)&wql, g_wql);
    cudaGetSymbolAddress((void**)&wkh, g_wkh); cudaGetSymbolAddress((void**)&wkl, g_wkl);
    cudaGetSymbolAddress((void**)&wvh, g_wvh); cudaGetSymbolAddress((void**)&wvl, g_wvl);
    cudaGetSymbolAddress((void**)&woh, g_woh); cudaGetSymbolAddress((void**)&wol, g_wol);

    cudaFuncSetAttribute(attn_mma2, cudaFuncAttributeMaxDynamicSharedMemorySize, SMEM_ATTN2);
    cudaFuncSetAttribute(gemm3,     cudaFuncAttributeMaxDynamicSharedMemorySize, SMEM_GEMM);

    dim3 blk(256);

    // ---- merged pre-splits (1 launch) ----
    SplitPack sp;
    auto mk = [&](const float* s, __nv_bfloat16* h, __nv_bfloat16* l, size_t n) {
        return SplitArg{ (const float4*)s, (uint2*)h, (uint2*)l, (int)(n / 4 / 256) };
    };
    sp.a[0] = mk(query, xqh, xql, (size_t)SEQ * EMB);
    sp.a[1] = mk(key,   xkh, xkl, (size_t)SEQ * EMB);
    sp.a[2] = mk(value, xvh, xvl, (size_t)SEQ * EMB);
    sp.a[3] = mk(wq, wqh, wql, (size_t)EMB * QDIM);
    sp.a[4] = mk(wk, wkh, wkl, (size_t)EMB * KVDIM);
    sp.a[5] = mk(wv, wvh, wvl, (size_t)EMB * KVDIM);
    sp.a[6] = mk(wo, woh, wol, (size_t)QDIM * EMB);
    int total_blk = 0;
    for (int i = 0; i < 7; i++) total_blk += sp.a[i].nblk;
    split_all<<<total_blk, blk>>>(sp);

    // ---- all three projections, one launch: x = [0,16)q [16,20)k [20,24)v ----
    GArg gq = { xqh, xql, wqh, wql, q_s, nullptr, nullptr, QDIM };
    GArg gk = { xkh, xkl, wkh, wkl, k_s, nullptr, nullptr, KVDIM };
    GArg gv = { xvh, xvl, wvh, wvl, nullptr, vh, vl, KVDIM };
    gemm3<<<dim3(24, SEQ/128), blk, SMEM_GEMM>>>(gq, gk, gv, 16, 20, SEQ, EMB);

    // ---- rope + split q/k ----
    rope2_kernel<<<SEQ, blk>>>(pos, q_s, k_s, qh, ql, kh, kl);

    // ---- attention ----
    attn_mma2<<<dim3(SEQ/128, NH), blk, SMEM_ATTN2>>>(qh, ql, kh, kl, vh, vl, ath, atl);

    // ---- output projection ----
    GArg go = { ath, atl, woh, wol, out, nullptr, nullptr, EMB };
    gemm3<<<dim3(16, SEQ/128), blk, SMEM_GEMM>>>(go, go, go, 16, 16, SEQ, QDIM);
}

// round 9
// speedup vs baseline: 1.0570x; 1.0570x over previous
#include <cuda_runtime.h>
#include <cuda_bf16.h>
#include <math.h>

#define SEQ  4096
#define EMB  2048
#define NH   16
#define NKVH 4
#define HD   128
#define WIN  2048
#define QDIM (NH*HD)    /* 2048 */
#define KVDIM (NKVH*HD) /* 512  */

// -------- scratch (device globals; no allocations allowed) --------
__device__ float g_q [SEQ * QDIM];
__device__ float g_k [SEQ * KVDIM];
__device__ __nv_bfloat16 g_qh[SEQ*QDIM],  g_ql[SEQ*QDIM];
__device__ __nv_bfloat16 g_kh[SEQ*KVDIM], g_kl[SEQ*KVDIM];
__device__ __nv_bfloat16 g_vh[SEQ*KVDIM], g_vl[SEQ*KVDIM];
__device__ __nv_bfloat16 g_ath[SEQ*QDIM], g_atl[SEQ*QDIM];
__device__ __nv_bfloat16 g_xqh[SEQ*EMB],  g_xql[SEQ*EMB];
__device__ __nv_bfloat16 g_xkh[SEQ*EMB],  g_xkl[SEQ*EMB];
__device__ __nv_bfloat16 g_xvh[SEQ*EMB],  g_xvl[SEQ*EMB];
__device__ __nv_bfloat16 g_wqh[EMB*QDIM], g_wql[EMB*QDIM];
__device__ __nv_bfloat16 g_wkh[EMB*KVDIM],g_wkl[EMB*KVDIM];
__device__ __nv_bfloat16 g_wvh[EMB*KVDIM],g_wvl[EMB*KVDIM];
__device__ __nv_bfloat16 g_woh[QDIM*EMB], g_wol[QDIM*EMB];

// ---------------- PTX helpers ----------------
#define LDSM_X4(r0,r1,r2,r3,addr) \
  asm volatile("ldmatrix.sync.aligned.m8n8.x4.shared.b16 {%0,%1,%2,%3}, [%4];" \
    : "=r"(r0),"=r"(r1),"=r"(r2),"=r"(r3) : "r"(addr))

#define LDSM_X4_T(r0,r1,r2,r3,addr) \
  asm volatile("ldmatrix.sync.aligned.m8n8.x4.trans.shared.b16 {%0,%1,%2,%3}, [%4];" \
    : "=r"(r0),"=r"(r1),"=r"(r2),"=r"(r3) : "r"(addr))

#define MMA16816(c, a0,a1,a2,a3, b0,b1) \
  asm volatile("mma.sync.aligned.m16n8k16.row.col.f32.bf16.bf16.f32 " \
    "{%0,%1,%2,%3}, {%4,%5,%6,%7}, {%8,%9}, {%0,%1,%2,%3};" \
    : "+f"((c)[0]),"+f"((c)[1]),"+f"((c)[2]),"+f"((c)[3]) \
    : "r"(a0),"r"(a1),"r"(a2),"r"(a3),"r"(b0),"r"(b1))

#define CP_ASYNC16(dst32, srcptr) \
  asm volatile("cp.async.cg.shared.global [%0], [%1], 16;" :: "r"(dst32), "l"(srcptr))
#define CP_COMMIT() asm volatile("cp.async.commit_group;")
#define CP_WAIT0()  asm volatile("cp.async.wait_group 0;")
#define CP_WAIT1()  asm volatile("cp.async.wait_group 1;")

__device__ __forceinline__ unsigned pack_bf2(__nv_bfloat16 lo16, __nv_bfloat16 hi16) {
    return ((unsigned)__bfloat16_as_ushort(hi16) << 16) | (unsigned)__bfloat16_as_ushort(lo16);
}
__device__ __forceinline__ void split2(float x0, float x1, unsigned& hi, unsigned& lo) {
    __nv_bfloat16 h0 = __float2bfloat16(x0);
    __nv_bfloat16 h1 = __float2bfloat16(x1);
    __nv_bfloat16 l0 = __float2bfloat16(x0 - __bfloat162float(h0));
    __nv_bfloat16 l1 = __float2bfloat16(x1 - __bfloat162float(h1));
    hi = pack_bf2(h0, h1);
    lo = pack_bf2(l0, l1);
}

// =====================================================================
// merged elementwise fp32 -> bf16 hi/lo split (all 7 tensors, 1 launch)
// =====================================================================
struct SplitArg { const float4* s; uint2* h; uint2* l; int nblk; };
struct SplitPack { SplitArg a[7]; };

__global__ __launch_bounds__(256) void split_all(SplitPack p)
{
    int b = blockIdx.x;
    int seg = 0;
#pragma unroll
    for (int i = 0; i < 7; i++) {
        if (b >= p.a[seg].nblk) { b -= p.a[seg].nblk; seg++; }
    }
    const SplitArg sa = p.a[seg];
    int i = b * 256 + threadIdx.x;
    float4 v = sa.s[i];
    unsigned h0, l0, h1, l1;
    split2(v.x, v.y, h0, l0);
    split2(v.z, v.w, h1, l1);
    sa.h[i] = make_uint2(h0, h1);
    sa.l[i] = make_uint2(l0, l1);
}

// =====================================================================
// split-bf16 GEMM v4: CTA tile 128x256, warp tile 64x64, BK=32,
// 3-stage cp.async pipeline (wait_group 1). 256 threads, 8 warps 2m x 4n.
// =====================================================================
#define A_STRIDE 40     /* bf16 elems; row = 80B */
#define B_STRIDE 264    /* bf16 elems; row = 528B */
#define G_AH 0
#define G_AL 10240
#define G_BH 20480
#define G_BL 37376
#define G_STAGE 54272
#define SMEM_GEMM (3*G_STAGE)   /* 162816 */

struct GArg {
    const __nv_bfloat16 *Ah, *Al, *Bh, *Bl;
    float* C;
    __nv_bfloat16 *Ch, *Cl;
    int N;
};

__global__ __launch_bounds__(256) void gemm4(
    GArg a0, GArg a1, GArg a2, int t0, int t1, int K)
{
    extern __shared__ char smg[];
    const unsigned smu = (unsigned)__cvta_generic_to_shared(smg);

    GArg ga; int bx = blockIdx.x, bn;
    if (bx < t0)      { ga = a0; bn = bx * 256; }
    else if (bx < t1) { ga = a1; bn = (bx - t0) * 256; }
    else              { ga = a2; bn = (bx - t1) * 256; }
    const int N  = ga.N;
    const int bm = blockIdx.y * 128;

    const int tid  = threadIdx.x;
    const int warp = tid >> 5;
    const int lane = tid & 31;
    const int wm   = warp >> 2;   // 0..1
    const int wn   = warp & 3;    // 0..3

    float acc[4][8][4];
#pragma unroll
    for (int i = 0; i < 4; i++)
#pragma unroll
        for (int j = 0; j < 8; j++)
#pragma unroll
            for (int r = 0; r < 4; r++) acc[i][j][r] = 0.f;

    auto issue = [&](int stage, int k0) {
        unsigned sb = smu + stage * G_STAGE;
#pragma unroll
        for (int p = 0; p < 2; p++) {           // A: 512 16B chunks / half
            int idx = tid + p * 256;
            int row = idx >> 2, u = idx & 3;
            CP_ASYNC16(sb + G_AH + row*80 + u*16, ga.Ah + (size_t)(bm + row)*K + k0 + u*8);
            CP_ASYNC16(sb + G_AL + row*80 + u*16, ga.Al + (size_t)(bm + row)*K + k0 + u*8);
        }
#pragma unroll
        for (int p = 0; p < 4; p++) {           // B: 1024 16B chunks / half
            int idx = tid + p * 256;
            int row = idx >> 5, u = idx & 31;
            CP_ASYNC16(sb + G_BH + row*528 + u*16, ga.Bh + (size_t)(k0 + row)*N + bn + u*8);
            CP_ASYNC16(sb + G_BL + row*528 + u*16, ga.Bl + (size_t)(k0 + row)*N + bn + u*8);
        }
        CP_COMMIT();
    };

    issue(0, 0);
    issue(1, 32);

    const int nch = K / 32;
    for (int j = 0; j < nch; j++) {
        if (j == nch - 1) { CP_WAIT0(); } else { CP_WAIT1(); }
        __syncthreads();
        if (j + 2 < nch) issue((j + 2) % 3, (j + 2) * 32);

        const unsigned sa = smu + (j % 3) * G_STAGE;
#pragma unroll
        for (int ks = 0; ks < 32; ks += 16) {
            unsigned ah[4][4], al[4][4];
#pragma unroll
            for (int mi = 0; mi < 4; mi++) {
                unsigned off = 2u * ((unsigned)((wm*64 + mi*16 + (lane & 15)) * A_STRIDE
                                               + ks + (lane >> 4) * 8));
                LDSM_X4(ah[mi][0], ah[mi][1], ah[mi][2], ah[mi][3], sa + G_AH + off);
                LDSM_X4(al[mi][0], al[mi][1], al[mi][2], al[mi][3], sa + G_AL + off);
            }
            unsigned bh[8][2], bl[8][2];
#pragma unroll
            for (int nb = 0; nb < 4; nb++) {
                unsigned off = 2u * ((unsigned)((ks + (lane & 15)) * B_STRIDE
                                               + wn*64 + nb*16 + (lane >> 4) * 8));
                unsigned r0, r1, r2, r3;
                LDSM_X4_T(r0, r1, r2, r3, sa + G_BH + off);
                bh[2*nb][0] = r0; bh[2*nb][1] = r1;
                bh[2*nb+1][0] = r2; bh[2*nb+1][1] = r3;
                LDSM_X4_T(r0, r1, r2, r3, sa + G_BL + off);
                bl[2*nb][0] = r0; bl[2*nb][1] = r1;
                bl[2*nb+1][0] = r2; bl[2*nb+1][1] = r3;
            }
#pragma unroll
            for (int mi = 0; mi < 4; mi++) {
#pragma unroll
                for (int ni = 0; ni < 8; ni++) {
                    MMA16816(acc[mi][ni], ah[mi][0],ah[mi][1],ah[mi][2],ah[mi][3],
                             bh[ni][0], bh[ni][1]);
                    MMA16816(acc[mi][ni], ah[mi][0],ah[mi][1],ah[mi][2],ah[mi][3],
                             bl[ni][0], bl[ni][1]);
                    MMA16816(acc[mi][ni], al[mi][0],al[mi][1],al[mi][2],al[mi][3],
                             bh[ni][0], bh[ni][1]);
                }
            }
        }
    }

    const int g = lane >> 2, q = lane & 3;
#pragma unroll
    for (int mi = 0; mi < 4; mi++) {
#pragma unroll
        for (int ni = 0; ni < 8; ni++) {
            int row = bm + wm*64 + mi*16 + g;
            int col = bn + wn*64 + ni*8 + q*2;
            if (ga.C) {
                *(float2*)&ga.C[(size_t)row * N + col]       = make_float2(acc[mi][ni][0], acc[mi][ni][1]);
                *(float2*)&ga.C[(size_t)(row + 8) * N + col] = make_float2(acc[mi][ni][2], acc[mi][ni][3]);
            }
            if (ga.Ch) {
                unsigned h0, l0;
                split2(acc[mi][ni][0], acc[mi][ni][1], h0, l0);
                *(unsigned*)&ga.Ch[(size_t)row * N + col] = h0;
                *(unsigned*)&ga.Cl[(size_t)row * N + col] = l0;
                split2(acc[mi][ni][2], acc[mi][ni][3], h0, l0);
                *(unsigned*)&ga.Ch[(size_t)(row + 8) * N + col] = h0;
                *(unsigned*)&ga.Cl[(size_t)(row + 8) * N + col] = l0;
            }
        }
    }
}

// =====================================================================
// RoPE: rotate fp32 q/k, scale q by log2(e)/sqrt(HD), emit split bf16
// =====================================================================
__global__ __launch_bounds__(256) void rope2_kernel(
    const int* __restrict__ pos_w,
    const float* __restrict__ q, const float* __restrict__ k,
    __nv_bfloat16* __restrict__ qh, __nv_bfloat16* __restrict__ ql,
    __nv_bfloat16* __restrict__ kh, __nv_bfloat16* __restrict__ kl)
{
    const int s = blockIdx.x;
    const int tid = threadIdx.x;
    __shared__ float cs[64], sn[64];

    const float QSCALE = (float)(1.4426950408889634 * 0.08838834764831845);

    if (tid < 64) {
        bool is64 = (pos_w[1] == 0);
        int pi = is64 ? pos_w[2 * s] : pos_w[s];
        float p = (float)pi;
        float ex = (float)(2 * tid) / (float)HD;
        float inv = powf(10000.0f, -ex);
        float ang = p * inv;
        sincosf(ang, &sn[tid], &cs[tid]);
    }
    __syncthreads();

    for (int idx = tid; idx < NH * 64; idx += 256) {
        int h = idx >> 6, d = idx & 63;
        size_t base = (size_t)s * QDIM + h * HD;
        float x1 = q[base + d], x2 = q[base + d + 64];
        float c = cs[d], si = sn[d];
        float y1 = (x1 * c - x2 * si) * QSCALE;
        float y2 = (x2 * c + x1 * si) * QSCALE;
        __nv_bfloat16 h1 = __float2bfloat16(y1);
        __nv_bfloat16 h2 = __float2bfloat16(y2);
        qh[base + d]      = h1;
        qh[base + d + 64] = h2;
        ql[base + d]      = __float2bfloat16(y1 - __bfloat162float(h1));
        ql[base + d + 64] = __float2bfloat16(y2 - __bfloat162float(h2));
    }
    for (int idx = tid; idx < NKVH * 64; idx += 256) {
        int h = idx >> 6, d = idx & 63;
        size_t base = (size_t)s * KVDIM + h * HD;
        float x1 = k[base + d], x2 = k[base + d + 64];
        float c = cs[d], si = sn[d];
        float y1 = x1 * c - x2 * si;
        float y2 = x2 * c + x1 * si;
        __nv_bfloat16 h1 = __float2bfloat16(y1);
        __nv_bfloat16 h2 = __float2bfloat16(y2);
        kh[base + d]      = h1;
        kh[base + d + 64] = h2;
        kl[base + d]      = __float2bfloat16(y1 - __bfloat162float(h1));
        kl[base + d + 64] = __float2bfloat16(y2 - __bfloat162float(h2));
    }
}

// =====================================================================
// MMA flash attention (unchanged — 495us passing version)
// =====================================================================
#define SMQ_H 0
#define SMQ_L 32768
#define KVBUF0 65536
#define KVSZ   65536
#define OF_KH  0
#define OF_KL  16384
#define OF_VH  32768
#define OF_VL  49152
#define SMEM_ATTN2 196608

__device__ __forceinline__ int swz(int row, int col_b16) {
    return row * 256 + ((((col_b16 >> 3) ^ (row & 7)) << 4)) + ((col_b16 & 7) << 1);
}

__global__ __launch_bounds__(256) void attn_mma2(
    const __nv_bfloat16* __restrict__ Qh, const __nv_bfloat16* __restrict__ Ql,
    const __nv_bfloat16* __restrict__ Kh, const __nv_bfloat16* __restrict__ Kl,
    const __nv_bfloat16* __restrict__ Vh, const __nv_bfloat16* __restrict__ Vl,
    __nv_bfloat16* __restrict__ Oh, __nv_bfloat16* __restrict__ Ol)
{
    extern __shared__ char sm[];
    const unsigned smu = (unsigned)__cvta_generic_to_shared(sm);

    const int tid  = threadIdx.x;
    const int warp = tid >> 5;
    const int lane = tid & 31;
    const int g    = lane >> 2;
    const int qd   = lane & 3;
    const int qb   = blockIdx.x;
    const int h    = blockIdx.y;
    const int kvh  = h >> 2;
    const int i0   = qb * 128;

    const int kb_lo = max(0, qb * 2 - 32);
    const int kb_hi = qb * 2 + 1;

    {
#pragma unroll
        for (int rep = 0; rep < 8; rep++) {
            int chunk = tid + rep * 256;
            int row = chunk >> 4, u = chunk & 15;
            unsigned dsto = row * 256 + (((u ^ (row & 7)) << 4));
            const __nv_bfloat16* sq = Qh + (size_t)(i0 + row) * QDIM + h * HD + u * 8;
            CP_ASYNC16(smu + SMQ_H + dsto, sq);
            const __nv_bfloat16* sl = Ql + (size_t)(i0 + row) * QDIM + h * HD + u * 8;
            CP_ASYNC16(smu + SMQ_L + dsto, sl);
        }
#pragma unroll
        for (int rep = 0; rep < 4; rep++) {
            int chunk = tid + rep * 256;
            int row = chunk >> 4, u = chunk & 15;
            unsigned dsto = row * 256 + (((u ^ (row & 7)) << 4));
            size_t srco = (size_t)(kb_lo * 64 + row) * KVDIM + kvh * HD + u * 8;
            CP_ASYNC16(smu + KVBUF0 + OF_KH + dsto, Kh + srco);
            CP_ASYNC16(smu + KVBUF0 + OF_KL + dsto, Kl + srco);
            CP_ASYNC16(smu + KVBUF0 + OF_VH + dsto, Vh + srco);
            CP_ASYNC16(smu + KVBUF0 + OF_VL + dsto, Vl + srco);
        }
        CP_COMMIT();
    }

    float o[16][4];
#pragma unroll
    for (int i = 0; i < 16; i++)
#pragma unroll
        for (int c = 0; c < 4; c++) o[i][c] = 0.f;

    float m0 = -1e30f, m1 = -1e30f, l0s = 0.f, l1s = 0.f;

    const int ig0 = i0 + warp * 16 + g;
    const int ig1 = ig0 + 8;

    for (int kb = kb_lo; kb <= kb_hi; kb++) {
        CP_WAIT0();
        __syncthreads();

        const int buf = (kb - kb_lo) & 1;
        const unsigned kvb = smu + KVBUF0 + buf * KVSZ;

        if (kb + 1 <= kb_hi) {
            const unsigned nb = smu + KVBUF0 + (buf ^ 1) * KVSZ;
#pragma unroll
            for (int rep = 0; rep < 4; rep++) {
                int chunk = tid + rep * 256;
                int row = chunk >> 4, u = chunk & 15;
                unsigned dsto = row * 256 + (((u ^ (row & 7)) << 4));
                size_t srco = (size_t)((kb + 1) * 64 + row) * KVDIM + kvh * HD + u * 8;
                CP_ASYNC16(nb + OF_KH + dsto, Kh + srco);
                CP_ASYNC16(nb + OF_KL + dsto, Kl + srco);
                CP_ASYNC16(nb + OF_VH + dsto, Vh + srco);
                CP_ASYNC16(nb + OF_VL + dsto, Vl + srco);
            }
            CP_COMMIT();
        }

        float S[8][4];
#pragma unroll
        for (int i = 0; i < 8; i++)
#pragma unroll
            for (int c = 0; c < 4; c++) S[i][c] = 0.f;

#pragma unroll
        for (int kc = 0; kc < 8; kc++) {
            unsigned ah0,ah1,ah2,ah3, al0,al1,al2,al3;
            {
                int aoff = swz(warp*16 + (lane & 15), kc*16 + (lane >> 4) * 8);
                LDSM_X4(ah0,ah1,ah2,ah3, smu + SMQ_H + aoff);
                LDSM_X4(al0,al1,al2,al3, smu + SMQ_L + aoff);
            }
#pragma unroll
            for (int ntp = 0; ntp < 4; ntp++) {
                int boff = swz(ntp*16 + (lane & 15), kc*16 + (lane >> 4) * 8);
                unsigned k0,k1,k2,k3, e0,e1,e2,e3;
                LDSM_X4(k0,k1,k2,k3, kvb + OF_KH + boff);
                LDSM_X4(e0,e1,e2,e3, kvb + OF_KL + boff);
                MMA16816(S[2*ntp],   ah0,ah1,ah2,ah3, k0,k2);
                MMA16816(S[2*ntp],   ah0,ah1,ah2,ah3, e0,e2);
                MMA16816(S[2*ntp],   al0,al1,al2,al3, k0,k2);
                MMA16816(S[2*ntp+1], ah0,ah1,ah2,ah3, k1,k3);
                MMA16816(S[2*ntp+1], ah0,ah1,ah2,ah3, e1,e3);
                MMA16816(S[2*ntp+1], al0,al1,al2,al3, k1,k3);
            }
        }

        bool need_mask = (kb >= qb*2) || (kb <= qb*2 - 31);
        if (need_mask) {
#pragma unroll
            for (int nt = 0; nt < 8; nt++) {
                int j0 = kb*64 + nt*8 + 2*qd;
                S[nt][0] = ((unsigned)(ig0 - j0)     <= (unsigned)WIN) ? S[nt][0] : -1e30f;
                S[nt][1] = ((unsigned)(ig0 - j0 - 1) <= (unsigned)WIN) ? S[nt][1] : -1e30f;
                S[nt][2] = ((unsigned)(ig1 - j0)     <= (unsigned)WIN) ? S[nt][2] : -1e30f;
                S[nt][3] = ((unsigned)(ig1 - j0 - 1) <= (unsigned)WIN) ? S[nt][3] : -1e30f;
            }
        }

        float mx0 = -1e30f, mx1 = -1e30f;
#pragma unroll
        for (int nt = 0; nt < 8; nt++) {
            mx0 = fmaxf(mx0, fmaxf(S[nt][0], S[nt][1]));
            mx1 = fmaxf(mx1, fmaxf(S[nt][2], S[nt][3]));
        }
        mx0 = fmaxf(mx0, __shfl_xor_sync(0xffffffffu, mx0, 1));
        mx0 = fmaxf(mx0, __shfl_xor_sync(0xffffffffu, mx0, 2));
        mx1 = fmaxf(mx1, __shfl_xor_sync(0xffffffffu, mx1, 1));
        mx1 = fmaxf(mx1, __shfl_xor_sync(0xffffffffu, mx1, 2));

        float mn0 = fmaxf(m0, mx0);
        float mn1 = fmaxf(m1, mx1);
        float a0 = exp2f(m0 - mn0);
        float a1 = exp2f(m1 - mn1);
        float ok0 = (mn0 > -5e29f) ? 1.f : 0.f;
        float ok1 = (mn1 > -5e29f) ? 1.f : 0.f;
        m0 = mn0; m1 = mn1;
        l0s *= a0; l1s *= a1;

#pragma unroll
        for (int nt = 0; nt < 8; nt++) {
            S[nt][0] = exp2f(S[nt][0] - mn0) * ok0;
            S[nt][1] = exp2f(S[nt][1] - mn0) * ok0;
            S[nt][2] = exp2f(S[nt][2] - mn1) * ok1;
            S[nt][3] = exp2f(S[nt][3] - mn1) * ok1;
            l0s += S[nt][0] + S[nt][1];
            l1s += S[nt][2] + S[nt][3];
        }

#pragma unroll
        for (int i = 0; i < 16; i++) {
            o[i][0] *= a0; o[i][1] *= a0;
            o[i][2] *= a1; o[i][3] *= a1;
        }

        unsigned ph[4][4], pl[4][4];
#pragma unroll
        for (int t = 0; t < 4; t++) {
            split2(S[2*t][0],   S[2*t][1],   ph[t][0], pl[t][0]);
            split2(S[2*t][2],   S[2*t][3],   ph[t][1], pl[t][1]);
            split2(S[2*t+1][0], S[2*t+1][1], ph[t][2], pl[t][2]);
            split2(S[2*t+1][2], S[2*t+1][3], ph[t][3], pl[t][3]);
        }

#pragma unroll
        for (int t = 0; t < 4; t++) {
#pragma unroll
            for (int ntp = 0; ntp < 8; ntp++) {
                int voff = swz(t*16 + (lane & 15), ntp*16 + (lane >> 4) * 8);
                unsigned v0,v1,v2,v3, w0,w1,w2,w3;
                LDSM_X4_T(v0,v1,v2,v3, kvb + OF_VH + voff);
                LDSM_X4_T(w0,w1,w2,w3, kvb + OF_VL + voff);
                MMA16816(o[2*ntp],   ph[t][0],ph[t][1],ph[t][2],ph[t][3], v0,v1);
                MMA16816(o[2*ntp],   ph[t][0],ph[t][1],ph[t][2],ph[t][3], w0,w1);
                MMA16816(o[2*ntp],   pl[t][0],pl[t][1],pl[t][2],pl[t][3], v0,v1);
                MMA16816(o[2*ntp+1], ph[t][0],ph[t][1],ph[t][2],ph[t][3], v2,v3);
                MMA16816(o[2*ntp+1], ph[t][0],ph[t][1],ph[t][2],ph[t][3], w2,w3);
                MMA16816(o[2*ntp+1], pl[t][0],pl[t][1],pl[t][2],pl[t][3], v2,v3);
            }
        }
    }

    l0s += __shfl_xor_sync(0xffffffffu, l0s, 1);
    l0s += __shfl_xor_sync(0xffffffffu, l0s, 2);
    l1s += __shfl_xor_sync(0xffffffffu, l1s, 1);
    l1s += __shfl_xor_sync(0xffffffffu, l1s, 2);
    float inv0 = 1.f / l0s;
    float inv1 = 1.f / l1s;

#pragma unroll
    for (int nt = 0; nt < 16; nt++) {
        int col = h * HD + nt * 8 + 2 * qd;
        unsigned h0, l0;
        split2(o[nt][0] * inv0, o[nt][1] * inv0, h0, l0);
        *(unsigned*)&Oh[(size_t)ig0 * QDIM + col] = h0;
        *(unsigned*)&Ol[(size_t)ig0 * QDIM + col] = l0;
        split2(o[nt][2] * inv1, o[nt][3] * inv1, h0, l0);
        *(unsigned*)&Oh[(size_t)ig1 * QDIM + col] = h0;
        *(unsigned*)&Ol[(size_t)ig1 * QDIM + col] = l0;
    }
}

// =====================================================================
extern "C" void kernel_launch(void* const* d_in, const int* in_sizes, int n_in,
                              void* d_out, int out_size)
{
    const float* query = (const float*)d_in[0];
    const float* key   = (const float*)d_in[1];
    const float* value = (const float*)d_in[2];
    const int*   pos   = (const int*)d_in[3];
    const float* wq    = (const float*)d_in[4];
    const float* wk    = (const float*)d_in[5];
    const float* wv    = (const float*)d_in[6];
    const float* wo    = (const float*)d_in[7];
    float*       out   = (float*)d_out;

    float *q_s, *k_s;
    __nv_bfloat16 *qh,*ql,*kh,*kl,*vh,*vl,*ath,*atl;
    __nv_bfloat16 *xqh,*xql,*xkh,*xkl,*xvh,*xvl;
    __nv_bfloat16 *wqh,*wql,*wkh,*wkl,*wvh,*wvl,*woh,*wol;
    cudaGetSymbolAddress((void**)&q_s, g_q);   cudaGetSymbolAddress((void**)&k_s, g_k);
    cudaGetSymbolAddress((void**)&qh, g_qh);   cudaGetSymbolAddress((void**)&ql, g_ql);
    cudaGetSymbolAddress((void**)&kh, g_kh);   cudaGetSymbolAddress((void**)&kl, g_kl);
    cudaGetSymbolAddress((void**)&vh, g_vh);   cudaGetSymbolAddress((void**)&vl, g_vl);
    cudaGetSymbolAddress((void**)&ath, g_ath); cudaGetSymbolAddress((void**)&atl, g_atl);
    cudaGetSymbolAddress((void**)&xqh, g_xqh); cudaGetSymbolAddress((void**)&xql, g_xql);
    cudaGetSymbolAddress((void**)&xkh, g_xkh); cudaGetSymbolAddress((void**)&xkl, g_xkl);
    cudaGetSymbolAddress((void**)&xvh, g_xvh); cudaGetSymbolAddress((void**)&xvl, g_xvl);
    cudaGetSymbolAddress((void**)&wqh, g_wqh); cudaGetSymbolAddress((void**)&wql, g_wql);
    cudaGetSymbolAddress((void**)&wkh, g_wkh); cudaGetSymbolAddress((void**)&wkl, g_wkl);
    cudaGetSymbolAddress((void**)&wvh, g_wvh); cudaGetSymbolAddress((void**)&wvl, g_wvl);
    cudaGetSymbolAddress((void**)&woh, g_woh); cudaGetSymbolAddress((void**)&wol, g_wol);

    cudaFuncSetAttribute(attn_mma2, cudaFuncAttributeMaxDynamicSharedMemorySize, SMEM_ATTN2);
    cudaFuncSetAttribute(gemm4,     cudaFuncAttributeMaxDynamicSharedMemorySize, SMEM_GEMM);

    dim3 blk(256);

    // ---- merged pre-splits (1 launch) ----
    SplitPack sp;
    auto mk = [&](const float* s, __nv_bfloat16* h, __nv_bfloat16* l, size_t n) {
        return SplitArg{ (const float4*)s, (uint2*)h, (uint2*)l, (int)(n / 4 / 256) };
    };
    sp.a[0] = mk(query, xqh, xql, (size_t)SEQ * EMB);
    sp.a[1] = mk(key,   xkh, xkl, (size_t)SEQ * EMB);
    sp.a[2] = mk(value, xvh, xvl, (size_t)SEQ * EMB);
    sp.a[3] = mk(wq, wqh, wql, (size_t)EMB * QDIM);
    sp.a[4] = mk(wk, wkh, wkl, (size_t)EMB * KVDIM);
    sp.a[5] = mk(wv, wvh, wvl, (size_t)EMB * KVDIM);
    sp.a[6] = mk(wo, woh, wol, (size_t)QDIM * EMB);
    int total_blk = 0;
    for (int i = 0; i < 7; i++) total_blk += sp.a[i].nblk;
    split_all<<<total_blk, blk>>>(sp);

    // ---- q/k/v projections, one launch: x = [0,8)q [8,10)k [10,12)v ----
    GArg gq = { xqh, xql, wqh, wql, q_s, nullptr, nullptr, QDIM };
    GArg gk = { xkh, xkl, wkh, wkl, k_s, nullptr, nullptr, KVDIM };
    GArg gv = { xvh, xvl, wvh, wvl, nullptr, vh, vl, KVDIM };
    gemm4<<<dim3(12, SEQ/128), blk, SMEM_GEMM>>>(gq, gk, gv, 8, 10, EMB);

    // ---- rope + split q/k ----
    rope2_kernel<<<SEQ, blk>>>(pos, q_s, k_s, qh, ql, kh, kl);

    // ---- attention ----
    attn_mma2<<<dim3(SEQ/128, NH), blk, SMEM_ATTN2>>>(qh, ql, kh, kl, vh, vl, ath, atl);

    // ---- output projection ----
    GArg go = { ath, atl, woh, wol, out, nullptr, nullptr, EMB };
    gemm4<<<dim3(8, SEQ/128), blk, SMEM_GEMM>>>(go, go, go, 8, 8, QDIM);
}

// round 10
// speedup vs baseline: 1.0652x; 1.0078x over previous
#include <cuda_runtime.h>
#include <cuda_bf16.h>
#include <math.h>

#define SEQ  4096
#define EMB  2048
#define NH   16
#define NKVH 4
#define HD   128
#define WIN  2048
#define QDIM (NH*HD)    /* 2048 */
#define KVDIM (NKVH*HD) /* 512  */

// -------- scratch (device globals; no allocations allowed) --------
__device__ float g_q [SEQ * QDIM];
__device__ float g_k [SEQ * KVDIM];
__device__ __nv_bfloat16 g_qh[SEQ*QDIM],  g_ql[SEQ*QDIM];
__device__ __nv_bfloat16 g_kh[SEQ*KVDIM], g_kl[SEQ*KVDIM];
__device__ __nv_bfloat16 g_vh[SEQ*KVDIM], g_vl[SEQ*KVDIM];
__device__ __nv_bfloat16 g_ath[SEQ*QDIM], g_atl[SEQ*QDIM];
__device__ __nv_bfloat16 g_xqh[SEQ*EMB],  g_xql[SEQ*EMB];
__device__ __nv_bfloat16 g_xkh[SEQ*EMB],  g_xkl[SEQ*EMB];
__device__ __nv_bfloat16 g_xvh[SEQ*EMB],  g_xvl[SEQ*EMB];
__device__ __nv_bfloat16 g_wqh[EMB*QDIM], g_wql[EMB*QDIM];
__device__ __nv_bfloat16 g_wkh[EMB*KVDIM],g_wkl[EMB*KVDIM];
__device__ __nv_bfloat16 g_wvh[EMB*KVDIM],g_wvl[EMB*KVDIM];
__device__ __nv_bfloat16 g_woh[QDIM*EMB], g_wol[QDIM*EMB];

// ---------------- PTX helpers ----------------
#define LDSM_X4(r0,r1,r2,r3,addr) \
  asm volatile("ldmatrix.sync.aligned.m8n8.x4.shared.b16 {%0,%1,%2,%3}, [%4];" \
    : "=r"(r0),"=r"(r1),"=r"(r2),"=r"(r3) : "r"(addr))

#define LDSM_X4_T(r0,r1,r2,r3,addr) \
  asm volatile("ldmatrix.sync.aligned.m8n8.x4.trans.shared.b16 {%0,%1,%2,%3}, [%4];" \
    : "=r"(r0),"=r"(r1),"=r"(r2),"=r"(r3) : "r"(addr))

#define MMA16816(c, a0,a1,a2,a3, b0,b1) \
  asm volatile("mma.sync.aligned.m16n8k16.row.col.f32.bf16.bf16.f32 " \
    "{%0,%1,%2,%3}, {%4,%5,%6,%7}, {%8,%9}, {%0,%1,%2,%3};" \
    : "+f"((c)[0]),"+f"((c)[1]),"+f"((c)[2]),"+f"((c)[3]) \
    : "r"(a0),"r"(a1),"r"(a2),"r"(a3),"r"(b0),"r"(b1))

#define CP_ASYNC16(dst32, srcptr) \
  asm volatile("cp.async.cg.shared.global [%0], [%1], 16;" :: "r"(dst32), "l"(srcptr))
#define CP_COMMIT() asm volatile("cp.async.commit_group;")
#define CP_WAIT0()  asm volatile("cp.async.wait_group 0;")
#define CP_WAIT1()  asm volatile("cp.async.wait_group 1;")

__device__ __forceinline__ unsigned pack_bf2(__nv_bfloat16 lo16, __nv_bfloat16 hi16) {
    return ((unsigned)__bfloat16_as_ushort(hi16) << 16) | (unsigned)__bfloat16_as_ushort(lo16);
}
__device__ __forceinline__ void split2(float x0, float x1, unsigned& hi, unsigned& lo) {
    __nv_bfloat16 h0 = __float2bfloat16(x0);
    __nv_bfloat16 h1 = __float2bfloat16(x1);
    __nv_bfloat16 l0 = __float2bfloat16(x0 - __bfloat162float(h0));
    __nv_bfloat16 l1 = __float2bfloat16(x1 - __bfloat162float(h1));
    hi = pack_bf2(h0, h1);
    lo = pack_bf2(l0, l1);
}

// =====================================================================
// merged elementwise fp32 -> bf16 hi/lo split (all 7 tensors, 1 launch)
// =====================================================================
struct SplitArg { const float4* s; uint2* h; uint2* l; int nblk; };
struct SplitPack { SplitArg a[7]; };

__global__ __launch_bounds__(256) void split_all(SplitPack p)
{
    int b = blockIdx.x;
    int seg = 0;
#pragma unroll
    for (int i = 0; i < 7; i++) {
        if (b >= p.a[seg].nblk) { b -= p.a[seg].nblk; seg++; }
    }
    const SplitArg sa = p.a[seg];
    int i = b * 256 + threadIdx.x;
    float4 v = sa.s[i];
    unsigned h0, l0, h1, l1;
    split2(v.x, v.y, h0, l0);
    split2(v.z, v.w, h1, l1);
    sa.h[i] = make_uint2(h0, h1);
    sa.l[i] = make_uint2(l0, l1);
}

// =====================================================================
// split-bf16 GEMM v5: CTA 128x256, warp 64x64, BK=32, 3-stage cp.async,
// cross-k-step A-fragment register double-buffer (breaks LDSM/MMA
// phase-lock: A frags for ks=16 load during ks=0 MMA block).
// =====================================================================
#define A_STRIDE 40     /* bf16 elems; row = 80B */
#define B_STRIDE 264    /* bf16 elems; row = 528B */
#define G_AH 0
#define G_AL 10240
#define G_BH 20480
#define G_BL 37376
#define G_STAGE 54272
#define SMEM_GEMM (3*G_STAGE)   /* 162816 */

struct GArg {
    const __nv_bfloat16 *Ah, *Al, *Bh, *Bl;
    float* C;
    __nv_bfloat16 *Ch, *Cl;
    int N;
};

__global__ __launch_bounds__(256) void gemm5(
    GArg a0, GArg a1, GArg a2, int t0, int t1, int K)
{
    extern __shared__ char smg[];
    const unsigned smu = (unsigned)__cvta_generic_to_shared(smg);

    GArg ga; int bx = blockIdx.x, bn;
    if (bx < t0)      { ga = a0; bn = bx * 256; }
    else if (bx < t1) { ga = a1; bn = (bx - t0) * 256; }
    else              { ga = a2; bn = (bx - t1) * 256; }
    const int N  = ga.N;
    const int bm = blockIdx.y * 128;

    const int tid  = threadIdx.x;
    const int warp = tid >> 5;
    const int lane = tid & 31;
    const int wm   = warp >> 2;   // 0..1
    const int wn   = warp & 3;    // 0..3

    float acc[4][8][4];
#pragma unroll
    for (int i = 0; i < 4; i++)
#pragma unroll
        for (int j = 0; j < 8; j++)
#pragma unroll
            for (int r = 0; r < 4; r++) acc[i][j][r] = 0.f;

    auto issue = [&](int stage, int k0) {
        unsigned sb = smu + stage * G_STAGE;
#pragma unroll
        for (int p = 0; p < 2; p++) {
            int idx = tid + p * 256;
            int row = idx >> 2, u = idx & 3;
            CP_ASYNC16(sb + G_AH + row*80 + u*16, ga.Ah + (size_t)(bm + row)*K + k0 + u*8);
            CP_ASYNC16(sb + G_AL + row*80 + u*16, ga.Al + (size_t)(bm + row)*K + k0 + u*8);
        }
#pragma unroll
        for (int p = 0; p < 4; p++) {
            int idx = tid + p * 256;
            int row = idx >> 5, u = idx & 31;
            CP_ASYNC16(sb + G_BH + row*528 + u*16, ga.Bh + (size_t)(k0 + row)*N + bn + u*8);
            CP_ASYNC16(sb + G_BL + row*528 + u*16, ga.Bl + (size_t)(k0 + row)*N + bn + u*8);
        }
        CP_COMMIT();
    };

    issue(0, 0);
    issue(1, 32);

    const int a_lrow = wm*64 + (lane & 15);
    const int a_lcol = (lane >> 4) * 8;

    const int nch = K / 32;
    for (int j = 0; j < nch; j++) {
        if (j == nch - 1) { CP_WAIT0(); } else { CP_WAIT1(); }
        __syncthreads();
        if (j + 2 < nch) issue((j + 2) % 3, (j + 2) * 32);

        const unsigned sa = smu + (j % 3) * G_STAGE;

        // A-fragment double buffer: [buf][mi][frag]
        unsigned ah[2][4][4], al[2][4][4];
#pragma unroll
        for (int mi = 0; mi < 4; mi++) {
            unsigned off = 2u * ((unsigned)((a_lrow + mi*16) * A_STRIDE + a_lcol));
            LDSM_X4(ah[0][mi][0], ah[0][mi][1], ah[0][mi][2], ah[0][mi][3], sa + G_AH + off);
            LDSM_X4(al[0][mi][0], al[0][mi][1], al[0][mi][2], al[0][mi][3], sa + G_AL + off);
        }

#pragma unroll
        for (int ksi = 0; ksi < 2; ksi++) {
            const int ks = ksi * 16;
            // prefetch next k-step's A frags (hidden under this step's MMAs)
            if (ksi == 0) {
#pragma unroll
                for (int mi = 0; mi < 4; mi++) {
                    unsigned off = 2u * ((unsigned)((a_lrow + mi*16) * A_STRIDE + 16 + a_lcol));
                    LDSM_X4(ah[1][mi][0], ah[1][mi][1], ah[1][mi][2], ah[1][mi][3], sa + G_AH + off);
                    LDSM_X4(al[1][mi][0], al[1][mi][1], al[1][mi][2], al[1][mi][3], sa + G_AL + off);
                }
            }
            unsigned bh[8][2], bl[8][2];
#pragma unroll
            for (int nb = 0; nb < 4; nb++) {
                unsigned off = 2u * ((unsigned)((ks + (lane & 15)) * B_STRIDE
                                               + wn*64 + nb*16 + (lane >> 4) * 8));
                unsigned r0, r1, r2, r3;
                LDSM_X4_T(r0, r1, r2, r3, sa + G_BH + off);
                bh[2*nb][0] = r0; bh[2*nb][1] = r1;
                bh[2*nb+1][0] = r2; bh[2*nb+1][1] = r3;
                LDSM_X4_T(r0, r1, r2, r3, sa + G_BL + off);
                bl[2*nb][0] = r0; bl[2*nb][1] = r1;
                bl[2*nb+1][0] = r2; bl[2*nb+1][1] = r3;
            }
#pragma unroll
            for (int mi = 0; mi < 4; mi++) {
#pragma unroll
                for (int ni = 0; ni < 8; ni++) {
                    MMA16816(acc[mi][ni], ah[ksi][mi][0],ah[ksi][mi][1],ah[ksi][mi][2],ah[ksi][mi][3],
                             bh[ni][0], bh[ni][1]);
                    MMA16816(acc[mi][ni], ah[ksi][mi][0],ah[ksi][mi][1],ah[ksi][mi][2],ah[ksi][mi][3],
                             bl[ni][0], bl[ni][1]);
                    MMA16816(acc[mi][ni], al[ksi][mi][0],al[ksi][mi][1],al[ksi][mi][2],al[ksi][mi][3],
                             bh[ni][0], bh[ni][1]);
                }
            }
        }
    }

    const int g = lane >> 2, q = lane & 3;
#pragma unroll
    for (int mi = 0; mi < 4; mi++) {
#pragma unroll
        for (int ni = 0; ni < 8; ni++) {
            int row = bm + wm*64 + mi*16 + g;
            int col = bn + wn*64 + ni*8 + q*2;
            if (ga.C) {
                *(float2*)&ga.C[(size_t)row * N + col]       = make_float2(acc[mi][ni][0], acc[mi][ni][1]);
                *(float2*)&ga.C[(size_t)(row + 8) * N + col] = make_float2(acc[mi][ni][2], acc[mi][ni][3]);
            }
            if (ga.Ch) {
                unsigned h0, l0;
                split2(acc[mi][ni][0], acc[mi][ni][1], h0, l0);
                *(unsigned*)&ga.Ch[(size_t)row * N + col] = h0;
                *(unsigned*)&ga.Cl[(size_t)row * N + col] = l0;
                split2(acc[mi][ni][2], acc[mi][ni][3], h0, l0);
                *(unsigned*)&ga.Ch[(size_t)(row + 8) * N + col] = h0;
                *(unsigned*)&ga.Cl[(size_t)(row + 8) * N + col] = l0;
            }
        }
    }
}

// =====================================================================
// RoPE: rotate fp32 q/k, scale q by log2(e)/sqrt(HD), emit split bf16
// =====================================================================
__global__ __launch_bounds__(256) void rope2_kernel(
    const int* __restrict__ pos_w,
    const float* __restrict__ q, const float* __restrict__ k,
    __nv_bfloat16* __restrict__ qh, __nv_bfloat16* __restrict__ ql,
    __nv_bfloat16* __restrict__ kh, __nv_bfloat16* __restrict__ kl)
{
    const int s = blockIdx.x;
    const int tid = threadIdx.x;
    __shared__ float cs[64], sn[64];

    const float QSCALE = (float)(1.4426950408889634 * 0.08838834764831845);

    if (tid < 64) {
        bool is64 = (pos_w[1] == 0);
        int pi = is64 ? pos_w[2 * s] : pos_w[s];
        float p = (float)pi;
        float ex = (float)(2 * tid) / (float)HD;
        float inv = powf(10000.0f, -ex);
        float ang = p * inv;
        sincosf(ang, &sn[tid], &cs[tid]);
    }
    __syncthreads();

    for (int idx = tid; idx < NH * 64; idx += 256) {
        int h = idx >> 6, d = idx & 63;
        size_t base = (size_t)s * QDIM + h * HD;
        float x1 = q[base + d], x2 = q[base + d + 64];
        float c = cs[d], si = sn[d];
        float y1 = (x1 * c - x2 * si) * QSCALE;
        float y2 = (x2 * c + x1 * si) * QSCALE;
        __nv_bfloat16 h1 = __float2bfloat16(y1);
        __nv_bfloat16 h2 = __float2bfloat16(y2);
        qh[base + d]      = h1;
        qh[base + d + 64] = h2;
        ql[base + d]      = __float2bfloat16(y1 - __bfloat162float(h1));
        ql[base + d + 64] = __float2bfloat16(y2 - __bfloat162float(h2));
    }
    for (int idx = tid; idx < NKVH * 64; idx += 256) {
        int h = idx >> 6, d = idx & 63;
        size_t base = (size_t)s * KVDIM + h * HD;
        float x1 = k[base + d], x2 = k[base + d + 64];
        float c = cs[d], si = sn[d];
        float y1 = x1 * c - x2 * si;
        float y2 = x2 * c + x1 * si;
        __nv_bfloat16 h1 = __float2bfloat16(y1);
        __nv_bfloat16 h2 = __float2bfloat16(y2);
        kh[base + d]      = h1;
        kh[base + d + 64] = h2;
        kl[base + d]      = __float2bfloat16(y1 - __bfloat162float(h1));
        kl[base + d + 64] = __float2bfloat16(y2 - __bfloat162float(h2));
    }
}

// =====================================================================
// MMA flash attention (unchanged — 496us passing version)
// =====================================================================
#define SMQ_H 0
#define SMQ_L 32768
#define KVBUF0 65536
#define KVSZ   65536
#define OF_KH  0
#define OF_KL  16384
#define OF_VH  32768
#define OF_VL  49152
#define SMEM_ATTN2 196608

__device__ __forceinline__ int swz(int row, int col_b16) {
    return row * 256 + ((((col_b16 >> 3) ^ (row & 7)) << 4)) + ((col_b16 & 7) << 1);
}

__global__ __launch_bounds__(256) void attn_mma2(
    const __nv_bfloat16* __restrict__ Qh, const __nv_bfloat16* __restrict__ Ql,
    const __nv_bfloat16* __restrict__ Kh, const __nv_bfloat16* __restrict__ Kl,
    const __nv_bfloat16* __restrict__ Vh, const __nv_bfloat16* __restrict__ Vl,
    __nv_bfloat16* __restrict__ Oh, __nv_bfloat16* __restrict__ Ol)
{
    extern __shared__ char sm[];
    const unsigned smu = (unsigned)__cvta_generic_to_shared(sm);

    const int tid  = threadIdx.x;
    const int warp = tid >> 5;
    const int lane = tid & 31;
    const int g    = lane >> 2;
    const int qd   = lane & 3;
    const int qb   = blockIdx.x;
    const int h    = blockIdx.y;
    const int kvh  = h >> 2;
    const int i0   = qb * 128;

    const int kb_lo = max(0, qb * 2 - 32);
    const int kb_hi = qb * 2 + 1;

    {
#pragma unroll
        for (int rep = 0; rep < 8; rep++) {
            int chunk = tid + rep * 256;
            int row = chunk >> 4, u = chunk & 15;
            unsigned dsto = row * 256 + (((u ^ (row & 7)) << 4));
            const __nv_bfloat16* sq = Qh + (size_t)(i0 + row) * QDIM + h * HD + u * 8;
            CP_ASYNC16(smu + SMQ_H + dsto, sq);
            const __nv_bfloat16* sl = Ql + (size_t)(i0 + row) * QDIM + h * HD + u * 8;
            CP_ASYNC16(smu + SMQ_L + dsto, sl);
        }
#pragma unroll
        for (int rep = 0; rep < 4; rep++) {
            int chunk = tid + rep * 256;
            int row = chunk >> 4, u = chunk & 15;
            unsigned dsto = row * 256 + (((u ^ (row & 7)) << 4));
            size_t srco = (size_t)(kb_lo * 64 + row) * KVDIM + kvh * HD + u * 8;
            CP_ASYNC16(smu + KVBUF0 + OF_KH + dsto, Kh + srco);
            CP_ASYNC16(smu + KVBUF0 + OF_KL + dsto, Kl + srco);
            CP_ASYNC16(smu + KVBUF0 + OF_VH + dsto, Vh + srco);
            CP_ASYNC16(smu + KVBUF0 + OF_VL + dsto, Vl + srco);
        }
        CP_COMMIT();
    }

    float o[16][4];
#pragma unroll
    for (int i = 0; i < 16; i++)
#pragma unroll
        for (int c = 0; c < 4; c++) o[i][c] = 0.f;

    float m0 = -1e30f, m1 = -1e30f, l0s = 0.f, l1s = 0.f;

    const int ig0 = i0 + warp * 16 + g;
    const int ig1 = ig0 + 8;

    for (int kb = kb_lo; kb <= kb_hi; kb++) {
        CP_WAIT0();
        __syncthreads();

        const int buf = (kb - kb_lo) & 1;
        const unsigned kvb = smu + KVBUF0 + buf * KVSZ;

        if (kb + 1 <= kb_hi) {
            const unsigned nb = smu + KVBUF0 + (buf ^ 1) * KVSZ;
#pragma unroll
            for (int rep = 0; rep < 4; rep++) {
                int chunk = tid + rep * 256;
                int row = chunk >> 4, u = chunk & 15;
                unsigned dsto = row * 256 + (((u ^ (row & 7)) << 4));
                size_t srco = (size_t)((kb + 1) * 64 + row) * KVDIM + kvh * HD + u * 8;
                CP_ASYNC16(nb + OF_KH + dsto, Kh + srco);
                CP_ASYNC16(nb + OF_KL + dsto, Kl + srco);
                CP_ASYNC16(nb + OF_VH + dsto, Vh + srco);
                CP_ASYNC16(nb + OF_VL + dsto, Vl + srco);
            }
            CP_COMMIT();
        }

        float S[8][4];
#pragma unroll
        for (int i = 0; i < 8; i++)
#pragma unroll
            for (int c = 0; c < 4; c++) S[i][c] = 0.f;

#pragma unroll
        for (int kc = 0; kc < 8; kc++) {
            unsigned ah0,ah1,ah2,ah3, al0,al1,al2,al3;
            {
                int aoff = swz(warp*16 + (lane & 15), kc*16 + (lane >> 4) * 8);
                LDSM_X4(ah0,ah1,ah2,ah3, smu + SMQ_H + aoff);
                LDSM_X4(al0,al1,al2,al3, smu + SMQ_L + aoff);
            }
#pragma unroll
            for (int ntp = 0; ntp < 4; ntp++) {
                int boff = swz(ntp*16 + (lane & 15), kc*16 + (lane >> 4) * 8);
                unsigned k0,k1,k2,k3, e0,e1,e2,e3;
                LDSM_X4(k0,k1,k2,k3, kvb + OF_KH + boff);
                LDSM_X4(e0,e1,e2,e3, kvb + OF_KL + boff);
                MMA16816(S[2*ntp],   ah0,ah1,ah2,ah3, k0,k2);
                MMA16816(S[2*ntp],   ah0,ah1,ah2,ah3, e0,e2);
                MMA16816(S[2*ntp],   al0,al1,al2,al3, k0,k2);
                MMA16816(S[2*ntp+1], ah0,ah1,ah2,ah3, k1,k3);
                MMA16816(S[2*ntp+1], ah0,ah1,ah2,ah3, e1,e3);
                MMA16816(S[2*ntp+1], al0,al1,al2,al3, k1,k3);
            }
        }

        bool need_mask = (kb >= qb*2) || (kb <= qb*2 - 31);
        if (need_mask) {
#pragma unroll
            for (int nt = 0; nt < 8; nt++) {
                int j0 = kb*64 + nt*8 + 2*qd;
                S[nt][0] = ((unsigned)(ig0 - j0)     <= (unsigned)WIN) ? S[nt][0] : -1e30f;
                S[nt][1] = ((unsigned)(ig0 - j0 - 1) <= (unsigned)WIN) ? S[nt][1] : -1e30f;
                S[nt][2] = ((unsigned)(ig1 - j0)     <= (unsigned)WIN) ? S[nt][2] : -1e30f;
                S[nt][3] = ((unsigned)(ig1 - j0 - 1) <= (unsigned)WIN) ? S[nt][3] : -1e30f;
            }
        }

        float mx0 = -1e30f, mx1 = -1e30f;
#pragma unroll
        for (int nt = 0; nt < 8; nt++) {
            mx0 = fmaxf(mx0, fmaxf(S[nt][0], S[nt][1]));
            mx1 = fmaxf(mx1, fmaxf(S[nt][2], S[nt][3]));
        }
        mx0 = fmaxf(mx0, __shfl_xor_sync(0xffffffffu, mx0, 1));
        mx0 = fmaxf(mx0, __shfl_xor_sync(0xffffffffu, mx0, 2));
        mx1 = fmaxf(mx1, __shfl_xor_sync(0xffffffffu, mx1, 1));
        mx1 = fmaxf(mx1, __shfl_xor_sync(0xffffffffu, mx1, 2));

        float mn0 = fmaxf(m0, mx0);
        float mn1 = fmaxf(m1, mx1);
        float a0 = exp2f(m0 - mn0);
        float a1 = exp2f(m1 - mn1);
        float ok0 = (mn0 > -5e29f) ? 1.f : 0.f;
        float ok1 = (mn1 > -5e29f) ? 1.f : 0.f;
        m0 = mn0; m1 = mn1;
        l0s *= a0; l1s *= a1;

#pragma unroll
        for (int nt = 0; nt < 8; nt++) {
            S[nt][0] = exp2f(S[nt][0] - mn0) * ok0;
            S[nt][1] = exp2f(S[nt][1] - mn0) * ok0;
            S[nt][2] = exp2f(S[nt][2] - mn1) * ok1;
            S[nt][3] = exp2f(S[nt][3] - mn1) * ok1;
            l0s += S[nt][0] + S[nt][1];
            l1s += S[nt][2] + S[nt][3];
        }

#pragma unroll
        for (int i = 0; i < 16; i++) {
            o[i][0] *= a0; o[i][1] *= a0;
            o[i][2] *= a1; o[i][3] *= a1;
        }

        unsigned ph[4][4], pl[4][4];
#pragma unroll
        for (int t = 0; t < 4; t++) {
            split2(S[2*t][0],   S[2*t][1],   ph[t][0], pl[t][0]);
            split2(S[2*t][2],   S[2*t][3],   ph[t][1], pl[t][1]);
            split2(S[2*t+1][0], S[2*t+1][1], ph[t][2], pl[t][2]);
            split2(S[2*t+1][2], S[2*t+1][3], ph[t][3], pl[t][3]);
        }

#pragma unroll
        for (int t = 0; t < 4; t++) {
#pragma unroll
            for (int ntp = 0; ntp < 8; ntp++) {
                int voff = swz(t*16 + (lane & 15), ntp*16 + (lane >> 4) * 8);
                unsigned v0,v1,v2,v3, w0,w1,w2,w3;
                LDSM_X4_T(v0,v1,v2,v3, kvb + OF_VH + voff);
                LDSM_X4_T(w0,w1,w2,w3, kvb + OF_VL + voff);
                MMA16816(o[2*ntp],   ph[t][0],ph[t][1],ph[t][2],ph[t][3], v0,v1);
                MMA16816(o[2*ntp],   ph[t][0],ph[t][1],ph[t][2],ph[t][3], w0,w1);
                MMA16816(o[2*ntp],   pl[t][0],pl[t][1],pl[t][2],pl[t][3], v0,v1);
                MMA16816(o[2*ntp+1], ph[t][0],ph[t][1],ph[t][2],ph[t][3], v2,v3);
                MMA16816(o[2*ntp+1], ph[t][0],ph[t][1],ph[t][2],ph[t][3], w2,w3);
                MMA16816(o[2*ntp+1], pl[t][0],pl[t][1],pl[t][2],pl[t][3], v2,v3);
            }
        }
    }

    l0s += __shfl_xor_sync(0xffffffffu, l0s, 1);
    l0s += __shfl_xor_sync(0xffffffffu, l0s, 2);
    l1s += __shfl_xor_sync(0xffffffffu, l1s, 1);
    l1s += __shfl_xor_sync(0xffffffffu, l1s, 2);
    float inv0 = 1.f / l0s;
    float inv1 = 1.f / l1s;

#pragma unroll
    for (int nt = 0; nt < 16; nt++) {
        int col = h * HD + nt * 8 + 2 * qd;
        unsigned h0, l0;
        split2(o[nt][0] * inv0, o[nt][1] * inv0, h0, l0);
        *(unsigned*)&Oh[(size_t)ig0 * QDIM + col] = h0;
        *(unsigned*)&Ol[(size_t)ig0 * QDIM + col] = l0;
        split2(o[nt][2] * inv1, o[nt][3] * inv1, h0, l0);
        *(unsigned*)&Oh[(size_t)ig1 * QDIM + col] = h0;
        *(unsigned*)&Ol[(size_t)ig1 * QDIM + col] = l0;
    }
}

// =====================================================================
extern "C" void kernel_launch(void* const* d_in, const int* in_sizes, int n_in,
                              void* d_out, int out_size)
{
    const float* query = (const float*)d_in[0];
    const float* key   = (const float*)d_in[1];
    const float* value = (const float*)d_in[2];
    const int*   pos   = (const int*)d_in[3];
    const float* wq    = (const float*)d_in[4];
    const float* wk    = (const float*)d_in[5];
    const float* wv    = (const float*)d_in[6];
    const float* wo    = (const float*)d_in[7];
    float*       out   = (float*)d_out;

    float *q_s, *k_s;
    __nv_bfloat16 *qh,*ql,*kh,*kl,*vh,*vl,*ath,*atl;
    __nv_bfloat16 *xqh,*xql,*xkh,*xkl,*xvh,*xvl;
    __nv_bfloat16 *wqh,*wql,*wkh,*wkl,*wvh,*wvl,*woh,*wol;
    cudaGetSymbolAddress((void**)&q_s, g_q);   cudaGetSymbolAddress((void**)&k_s, g_k);
    cudaGetSymbolAddress((void**)&qh, g_qh);   cudaGetSymbolAddress((void**)&ql, g_ql);
    cudaGetSymbolAddress((void**)&kh, g_kh);   cudaGetSymbolAddress((void**)&kl, g_kl);
    cudaGetSymbolAddress((void**)&vh, g_vh);   cudaGetSymbolAddress((void**)&vl, g_vl);
    cudaGetSymbolAddress((void**)&ath, g_ath); cudaGetSymbolAddress((void**)&atl, g_atl);
    cudaGetSymbolAddress((void**)&xqh, g_xqh); cudaGetSymbolAddress((void**)&xql, g_xql);
    cudaGetSymbolAddress((void**)&xkh, g_xkh); cudaGetSymbolAddress((void**)&xkl, g_xkl);
    cudaGetSymbolAddress((void**)&xvh, g_xvh); cudaGetSymbolAddress((void**)&xvl, g_xvl);
    cudaGetSymbolAddress((void**)&wqh, g_wqh); cudaGetSymbolAddress((void**)&wql, g_wql);
    cudaGetSymbolAddress((void**)&wkh, g_wkh); cudaGetSymbolAddress((void**)&wkl, g_wkl);
    cudaGetSymbolAddress((void**)&wvh, g_wvh); cudaGetSymbolAddress((void**)&wvl, g_wvl);
    cudaGetSymbolAddress((void**)&woh, g_woh); cudaGetSymbolAddress((void**)&wol, g_wol);

    cudaFuncSetAttribute(attn_mma2, cudaFuncAttributeMaxDynamicSharedMemorySize, SMEM_ATTN2);
    cudaFuncSetAttribute(gemm5,     cudaFuncAttributeMaxDynamicSharedMemorySize, SMEM_GEMM);

    dim3 blk(256);

    // ---- merged pre-splits (1 launch) ----
    SplitPack sp;
    auto mk = [&](const float* s, __nv_bfloat16* h, __nv_bfloat16* l, size_t n) {
        return SplitArg{ (const float4*)s, (uint2*)h, (uint2*)l, (int)(n / 4 / 256) };
    };
    sp.a[0] = mk(query, xqh, xql, (size_t)SEQ * EMB);
    sp.a[1] = mk(key,   xkh, xkl, (size_t)SEQ * EMB);
    sp.a[2] = mk(value, xvh, xvl, (size_t)SEQ * EMB);
    sp.a[3] = mk(wq, wqh, wql, (size_t)EMB * QDIM);
    sp.a[4] = mk(wk, wkh, wkl, (size_t)EMB * KVDIM);
    sp.a[5] = mk(wv, wvh, wvl, (size_t)EMB * KVDIM);
    sp.a[6] = mk(wo, woh, wol, (size_t)QDIM * EMB);
    int total_blk = 0;
    for (int i = 0; i < 7; i++) total_blk += sp.a[i].nblk;
    split_all<<<total_blk, blk>>>(sp);

    // ---- q/k/v projections, one launch: x = [0,8)q [8,10)k [10,12)v ----
    GArg gq = { xqh, xql, wqh, wql, q_s, nullptr, nullptr, QDIM };
    GArg gk = { xkh, xkl, wkh, wkl, k_s, nullptr, nullptr, KVDIM };
    GArg gv = { xvh, xvl, wvh, wvl, nullptr, vh, vl, KVDIM };
    gemm5<<<dim3(12, SEQ/128), blk, SMEM_GEMM>>>(gq, gk, gv, 8, 10, EMB);

    // ---- rope + split q/k ----
    rope2_kernel<<<SEQ, blk>>>(pos, q_s, k_s, qh, ql, kh, kl);

    // ---- attention ----
    attn_mma2<<<dim3(SEQ/128, NH), blk, SMEM_ATTN2>>>(qh, ql, kh, kl, vh, vl, ath, atl);

    // ---- output projection ----
    GArg go = { ath, atl, woh, wol, out, nullptr, nullptr, EMB };
    gemm5<<<dim3(8, SEQ/128), blk, SMEM_GEMM>>>(go, go, go, 8, 8, QDIM);
}

// round 11
// speedup vs baseline: 1.1030x; 1.0355x over previous
#include <cuda_runtime.h>
#include <cuda_bf16.h>
#include <math.h>

#define SEQ  4096
#define EMB  2048
#define NH   16
#define NKVH 4
#define HD   128
#define WIN  2048
#define QDIM (NH*HD)    /* 2048 */
#define KVDIM (NKVH*HD) /* 512  */

// -------- scratch (device globals; no allocations allowed) --------
__device__ float g_q [SEQ * QDIM];
__device__ float g_k [SEQ * KVDIM];
__device__ __nv_bfloat16 g_qh[SEQ*QDIM],  g_ql[SEQ*QDIM];
__device__ __nv_bfloat16 g_kh[SEQ*KVDIM], g_kl[SEQ*KVDIM];
__device__ __nv_bfloat16 g_vh[SEQ*KVDIM], g_vl[SEQ*KVDIM];
__device__ __nv_bfloat16 g_ath[SEQ*QDIM], g_atl[SEQ*QDIM];
__device__ __nv_bfloat16 g_xqh[SEQ*EMB],  g_xql[SEQ*EMB];
__device__ __nv_bfloat16 g_xkh[SEQ*EMB],  g_xkl[SEQ*EMB];
__device__ __nv_bfloat16 g_xvh[SEQ*EMB],  g_xvl[SEQ*EMB];
__device__ __nv_bfloat16 g_wqh[EMB*QDIM], g_wql[EMB*QDIM];
__device__ __nv_bfloat16 g_wkh[EMB*KVDIM],g_wkl[EMB*KVDIM];
__device__ __nv_bfloat16 g_wvh[EMB*KVDIM],g_wvl[EMB*KVDIM];
__device__ __nv_bfloat16 g_woh[QDIM*EMB], g_wol[QDIM*EMB];

// ---------------- PTX helpers ----------------
#define LDSM_X4(r0,r1,r2,r3,addr) \
  asm volatile("ldmatrix.sync.aligned.m8n8.x4.shared.b16 {%0,%1,%2,%3}, [%4];" \
    : "=r"(r0),"=r"(r1),"=r"(r2),"=r"(r3) : "r"(addr))

#define LDSM_X4_T(r0,r1,r2,r3,addr) \
  asm volatile("ldmatrix.sync.aligned.m8n8.x4.trans.shared.b16 {%0,%1,%2,%3}, [%4];" \
    : "=r"(r0),"=r"(r1),"=r"(r2),"=r"(r3) : "r"(addr))

#define MMA16816(c, a0,a1,a2,a3, b0,b1) \
  asm volatile("mma.sync.aligned.m16n8k16.row.col.f32.bf16.bf16.f32 " \
    "{%0,%1,%2,%3}, {%4,%5,%6,%7}, {%8,%9}, {%0,%1,%2,%3};" \
    : "+f"((c)[0]),"+f"((c)[1]),"+f"((c)[2]),"+f"((c)[3]) \
    : "r"(a0),"r"(a1),"r"(a2),"r"(a3),"r"(b0),"r"(b1))

#define CP_ASYNC16(dst32, srcptr) \
  asm volatile("cp.async.cg.shared.global [%0], [%1], 16;" :: "r"(dst32), "l"(srcptr))
#define CP_COMMIT() asm volatile("cp.async.commit_group;")
#define CP_WAIT0()  asm volatile("cp.async.wait_group 0;")

__device__ __forceinline__ unsigned pack_bf2(__nv_bfloat16 lo16, __nv_bfloat16 hi16) {
    return ((unsigned)__bfloat16_as_ushort(hi16) << 16) | (unsigned)__bfloat16_as_ushort(lo16);
}
__device__ __forceinline__ void split2(float x0, float x1, unsigned& hi, unsigned& lo) {
    __nv_bfloat16 h0 = __float2bfloat16(x0);
    __nv_bfloat16 h1 = __float2bfloat16(x1);
    __nv_bfloat16 l0 = __float2bfloat16(x0 - __bfloat162float(h0));
    __nv_bfloat16 l1 = __float2bfloat16(x1 - __bfloat162float(h1));
    hi = pack_bf2(h0, h1);
    lo = pack_bf2(l0, l1);
}

// =====================================================================
// merged elementwise fp32 -> bf16 hi/lo split (all 7 tensors, 1 launch)
// =====================================================================
struct SplitArg { const float4* s; uint2* h; uint2* l; int nblk; };
struct SplitPack { SplitArg a[7]; };

__global__ __launch_bounds__(256) void split_all(SplitPack p)
{
    int b = blockIdx.x;
    int seg = 0;
#pragma unroll
    for (int i = 0; i < 7; i++) {
        if (b >= p.a[seg].nblk) { b -= p.a[seg].nblk; seg++; }
    }
    const SplitArg sa = p.a[seg];
    int i = b * 256 + threadIdx.x;
    float4 v = sa.s[i];
    unsigned h0, l0, h1, l1;
    split2(v.x, v.y, h0, l0);
    split2(v.z, v.w, h1, l1);
    sa.h[i] = make_uint2(h0, h1);
    sa.l[i] = make_uint2(l0, l1);
}

// =====================================================================
// split-bf16 GEMM v6: CTA 128x256, warp 64x64, BK=64 (32 iters over
// K=2048), 2-stage cp.async pipeline with true copy/compute overlap:
//   loop j: wait(group j) ; sync ; issue(j+1) ; compute(j)
// =====================================================================
#define A_STRIDE 72     /* bf16 elems; row = 144B (64 data + pad) */
#define B_STRIDE 264    /* bf16 elems; row = 528B (512 data + pad) */
#define G_AH 0
#define G_AL 18432
#define G_BH 36864
#define G_BL 70656
#define G_STAGE 104448
#define SMEM_GEMM (2*G_STAGE)   /* 208896 */

struct GArg {
    const __nv_bfloat16 *Ah, *Al, *Bh, *Bl;
    float* C;
    __nv_bfloat16 *Ch, *Cl;
    int N;
};

__global__ __launch_bounds__(256) void gemm6(
    GArg a0, GArg a1, GArg a2, int t0, int t1, int K)
{
    extern __shared__ char smg[];
    const unsigned smu = (unsigned)__cvta_generic_to_shared(smg);

    GArg ga; int bx = blockIdx.x, bn;
    if (bx < t0)      { ga = a0; bn = bx * 256; }
    else if (bx < t1) { ga = a1; bn = (bx - t0) * 256; }
    else              { ga = a2; bn = (bx - t1) * 256; }
    const int N  = ga.N;
    const int bm = blockIdx.y * 128;

    const int tid  = threadIdx.x;
    const int warp = tid >> 5;
    const int lane = tid & 31;
    const int wm   = warp >> 2;   // 0..1
    const int wn   = warp & 3;    // 0..3

    float acc[4][8][4];
#pragma unroll
    for (int i = 0; i < 4; i++)
#pragma unroll
        for (int j = 0; j < 8; j++)
#pragma unroll
            for (int r = 0; r < 4; r++) acc[i][j][r] = 0.f;

    auto issue = [&](int stage, int k0) {
        unsigned sb = smu + stage * G_STAGE;
        // A: 128 rows x 128B (8 x 16B) per half -> 1024 chunks -> 4/thread
#pragma unroll
        for (int p = 0; p < 4; p++) {
            int idx = tid + p * 256;
            int row = idx >> 3, u = idx & 7;
            CP_ASYNC16(sb + G_AH + row*144 + u*16, ga.Ah + (size_t)(bm + row)*K + k0 + u*8);
            CP_ASYNC16(sb + G_AL + row*144 + u*16, ga.Al + (size_t)(bm + row)*K + k0 + u*8);
        }
        // B: 64 rows x 512B (32 x 16B) per half -> 2048 chunks -> 8/thread
#pragma unroll
        for (int p = 0; p < 8; p++) {
            int idx = tid + p * 256;
            int row = idx >> 5, u = idx & 31;
            CP_ASYNC16(sb + G_BH + row*528 + u*16, ga.Bh + (size_t)(k0 + row)*N + bn + u*8);
            CP_ASYNC16(sb + G_BL + row*528 + u*16, ga.Bl + (size_t)(k0 + row)*N + bn + u*8);
        }
        CP_COMMIT();
    };

    issue(0, 0);

    const int a_lrow = wm*64 + (lane & 15);
    const int a_lcol = (lane >> 4) * 8;

    const int nch = K / 64;   // 32
    for (int j = 0; j < nch; j++) {
        CP_WAIT0();             // group j (issued previous iter, overlapped)
        __syncthreads();        // all warps done computing j-1 -> buffer (j+1)&1 free
        if (j + 1 < nch) issue((j + 1) & 1, (j + 1) * 64);

        const unsigned sa = smu + (j & 1) * G_STAGE;

        // A-fragment double buffer across the 4 k-steps
        unsigned ah[2][4][4], al[2][4][4];
#pragma unroll
        for (int mi = 0; mi < 4; mi++) {
            unsigned off = 2u * ((unsigned)((a_lrow + mi*16) * A_STRIDE + a_lcol));
            LDSM_X4(ah[0][mi][0], ah[0][mi][1], ah[0][mi][2], ah[0][mi][3], sa + G_AH + off);
            LDSM_X4(al[0][mi][0], al[0][mi][1], al[0][mi][2], al[0][mi][3], sa + G_AL + off);
        }

#pragma unroll
        for (int ksi = 0; ksi < 4; ksi++) {
            const int ks = ksi * 16;
            const int cur = ksi & 1;
            if (ksi < 3) {
#pragma unroll
                for (int mi = 0; mi < 4; mi++) {
                    unsigned off = 2u * ((unsigned)((a_lrow + mi*16) * A_STRIDE + ks + 16 + a_lcol));
                    LDSM_X4(ah[cur^1][mi][0], ah[cur^1][mi][1], ah[cur^1][mi][2], ah[cur^1][mi][3], sa + G_AH + off);
                    LDSM_X4(al[cur^1][mi][0], al[cur^1][mi][1], al[cur^1][mi][2], al[cur^1][mi][3], sa + G_AL + off);
                }
            }
            unsigned bh[8][2], bl[8][2];
#pragma unroll
            for (int nb = 0; nb < 4; nb++) {
                unsigned off = 2u * ((unsigned)((ks + (lane & 15)) * B_STRIDE
                                               + wn*64 + nb*16 + (lane >> 4) * 8));
                unsigned r0, r1, r2, r3;
                LDSM_X4_T(r0, r1, r2, r3, sa + G_BH + off);
                bh[2*nb][0] = r0; bh[2*nb][1] = r1;
                bh[2*nb+1][0] = r2; bh[2*nb+1][1] = r3;
                LDSM_X4_T(r0, r1, r2, r3, sa + G_BL + off);
                bl[2*nb][0] = r0; bl[2*nb][1] = r1;
                bl[2*nb+1][0] = r2; bl[2*nb+1][1] = r3;
            }
#pragma unroll
            for (int mi = 0; mi < 4; mi++) {
#pragma unroll
                for (int ni = 0; ni < 8; ni++) {
                    MMA16816(acc[mi][ni], ah[cur][mi][0],ah[cur][mi][1],ah[cur][mi][2],ah[cur][mi][3],
                             bh[ni][0], bh[ni][1]);
                    MMA16816(acc[mi][ni], ah[cur][mi][0],ah[cur][mi][1],ah[cur][mi][2],ah[cur][mi][3],
                             bl[ni][0], bl[ni][1]);
                    MMA16816(acc[mi][ni], al[cur][mi][0],al[cur][mi][1],al[cur][mi][2],al[cur][mi][3],
                             bh[ni][0], bh[ni][1]);
                }
            }
        }
    }

    const int g = lane >> 2, q = lane & 3;
#pragma unroll
    for (int mi = 0; mi < 4; mi++) {
#pragma unroll
        for (int ni = 0; ni < 8; ni++) {
            int row = bm + wm*64 + mi*16 + g;
            int col = bn + wn*64 + ni*8 + q*2;
            if (ga.C) {
                *(float2*)&ga.C[(size_t)row * N + col]       = make_float2(acc[mi][ni][0], acc[mi][ni][1]);
                *(float2*)&ga.C[(size_t)(row + 8) * N + col] = make_float2(acc[mi][ni][2], acc[mi][ni][3]);
            }
            if (ga.Ch) {
                unsigned h0, l0;
                split2(acc[mi][ni][0], acc[mi][ni][1], h0, l0);
                *(unsigned*)&ga.Ch[(size_t)row * N + col] = h0;
                *(unsigned*)&ga.Cl[(size_t)row * N + col] = l0;
                split2(acc[mi][ni][2], acc[mi][ni][3], h0, l0);
                *(unsigned*)&ga.Ch[(size_t)(row + 8) * N + col] = h0;
                *(unsigned*)&ga.Cl[(size_t)(row + 8) * N + col] = l0;
            }
        }
    }
}

// =====================================================================
// RoPE: rotate fp32 q/k, scale q by log2(e)/sqrt(HD), emit split bf16
// =====================================================================
__global__ __launch_bounds__(256) void rope2_kernel(
    const int* __restrict__ pos_w,
    const float* __restrict__ q, const float* __restrict__ k,
    __nv_bfloat16* __restrict__ qh, __nv_bfloat16* __restrict__ ql,
    __nv_bfloat16* __restrict__ kh, __nv_bfloat16* __restrict__ kl)
{
    const int s = blockIdx.x;
    const int tid = threadIdx.x;
    __shared__ float cs[64], sn[64];

    const float QSCALE = (float)(1.4426950408889634 * 0.08838834764831845);

    if (tid < 64) {
        bool is64 = (pos_w[1] == 0);
        int pi = is64 ? pos_w[2 * s] : pos_w[s];
        float p = (float)pi;
        float ex = (float)(2 * tid) / (float)HD;
        float inv = powf(10000.0f, -ex);
        float ang = p * inv;
        sincosf(ang, &sn[tid], &cs[tid]);
    }
    __syncthreads();

    for (int idx = tid; idx < NH * 64; idx += 256) {
        int h = idx >> 6, d = idx & 63;
        size_t base = (size_t)s * QDIM + h * HD;
        float x1 = q[base + d], x2 = q[base + d + 64];
        float c = cs[d], si = sn[d];
        float y1 = (x1 * c - x2 * si) * QSCALE;
        float y2 = (x2 * c + x1 * si) * QSCALE;
        __nv_bfloat16 h1 = __float2bfloat16(y1);
        __nv_bfloat16 h2 = __float2bfloat16(y2);
        qh[base + d]      = h1;
        qh[base + d + 64] = h2;
        ql[base + d]      = __float2bfloat16(y1 - __bfloat162float(h1));
        ql[base + d + 64] = __float2bfloat16(y2 - __bfloat162float(h2));
    }
    for (int idx = tid; idx < NKVH * 64; idx += 256) {
        int h = idx >> 6, d = idx & 63;
        size_t base = (size_t)s * KVDIM + h * HD;
        float x1 = k[base + d], x2 = k[base + d + 64];
        float c = cs[d], si = sn[d];
        float y1 = x1 * c - x2 * si;
        float y2 = x2 * c + x1 * si;
        __nv_bfloat16 h1 = __float2bfloat16(y1);
        __nv_bfloat16 h2 = __float2bfloat16(y2);
        kh[base + d]      = h1;
        kh[base + d + 64] = h2;
        kl[base + d]      = __float2bfloat16(y1 - __bfloat162float(h1));
        kl[base + d + 64] = __float2bfloat16(y2 - __bfloat162float(h2));
    }
}

// =====================================================================
// MMA flash attention (unchanged — 494us passing version)
// =====================================================================
#define SMQ_H 0
#define SMQ_L 32768
#define KVBUF0 65536
#define KVSZ   65536
#define OF_KH  0
#define OF_KL  16384
#define OF_VH  32768
#define OF_VL  49152
#define SMEM_ATTN2 196608

__device__ __forceinline__ int swz(int row, int col_b16) {
    return row * 256 + ((((col_b16 >> 3) ^ (row & 7)) << 4)) + ((col_b16 & 7) << 1);
}

__global__ __launch_bounds__(256) void attn_mma2(
    const __nv_bfloat16* __restrict__ Qh, const __nv_bfloat16* __restrict__ Ql,
    const __nv_bfloat16* __restrict__ Kh, const __nv_bfloat16* __restrict__ Kl,
    const __nv_bfloat16* __restrict__ Vh, const __nv_bfloat16* __restrict__ Vl,
    __nv_bfloat16* __restrict__ Oh, __nv_bfloat16* __restrict__ Ol)
{
    extern __shared__ char sm[];
    const unsigned smu = (unsigned)__cvta_generic_to_shared(sm);

    const int tid  = threadIdx.x;
    const int warp = tid >> 5;
    const int lane = tid & 31;
    const int g    = lane >> 2;
    const int qd   = lane & 3;
    const int qb   = blockIdx.x;
    const int h    = blockIdx.y;
    const int kvh  = h >> 2;
    const int i0   = qb * 128;

    const int kb_lo = max(0, qb * 2 - 32);
    const int kb_hi = qb * 2 + 1;

    {
#pragma unroll
        for (int rep = 0; rep < 8; rep++) {
            int chunk = tid + rep * 256;
            int row = chunk >> 4, u = chunk & 15;
            unsigned dsto = row * 256 + (((u ^ (row & 7)) << 4));
            const __nv_bfloat16* sq = Qh + (size_t)(i0 + row) * QDIM + h * HD + u * 8;
            CP_ASYNC16(smu + SMQ_H + dsto, sq);
            const __nv_bfloat16* sl = Ql + (size_t)(i0 + row) * QDIM + h * HD + u * 8;
            CP_ASYNC16(smu + SMQ_L + dsto, sl);
        }
#pragma unroll
        for (int rep = 0; rep < 4; rep++) {
            int chunk = tid + rep * 256;
            int row = chunk >> 4, u = chunk & 15;
            unsigned dsto = row * 256 + (((u ^ (row & 7)) << 4));
            size_t srco = (size_t)(kb_lo * 64 + row) * KVDIM + kvh * HD + u * 8;
            CP_ASYNC16(smu + KVBUF0 + OF_KH + dsto, Kh + srco);
            CP_ASYNC16(smu + KVBUF0 + OF_KL + dsto, Kl + srco);
            CP_ASYNC16(smu + KVBUF0 + OF_VH + dsto, Vh + srco);
            CP_ASYNC16(smu + KVBUF0 + OF_VL + dsto, Vl + srco);
        }
        CP_COMMIT();
    }

    float o[16][4];
#pragma unroll
    for (int i = 0; i < 16; i++)
#pragma unroll
        for (int c = 0; c < 4; c++) o[i][c] = 0.f;

    float m0 = -1e30f, m1 = -1e30f, l0s = 0.f, l1s = 0.f;

    const int ig0 = i0 + warp * 16 + g;
    const int ig1 = ig0 + 8;

    for (int kb = kb_lo; kb <= kb_hi; kb++) {
        CP_WAIT0();
        __syncthreads();

        const int buf = (kb - kb_lo) & 1;
        const unsigned kvb = smu + KVBUF0 + buf * KVSZ;

        if (kb + 1 <= kb_hi) {
            const unsigned nb = smu + KVBUF0 + (buf ^ 1) * KVSZ;
#pragma unroll
            for (int rep = 0; rep < 4; rep++) {
                int chunk = tid + rep * 256;
                int row = chunk >> 4, u = chunk & 15;
                unsigned dsto = row * 256 + (((u ^ (row & 7)) << 4));
                size_t srco = (size_t)((kb + 1) * 64 + row) * KVDIM + kvh * HD + u * 8;
                CP_ASYNC16(nb + OF_KH + dsto, Kh + srco);
                CP_ASYNC16(nb + OF_KL + dsto, Kl + srco);
                CP_ASYNC16(nb + OF_VH + dsto, Vh + srco);
                CP_ASYNC16(nb + OF_VL + dsto, Vl + srco);
            }
            CP_COMMIT();
        }

        float S[8][4];
#pragma unroll
        for (int i = 0; i < 8; i++)
#pragma unroll
            for (int c = 0; c < 4; c++) S[i][c] = 0.f;

#pragma unroll
        for (int kc = 0; kc < 8; kc++) {
            unsigned ah0,ah1,ah2,ah3, al0,al1,al2,al3;
            {
                int aoff = swz(warp*16 + (lane & 15), kc*16 + (lane >> 4) * 8);
                LDSM_X4(ah0,ah1,ah2,ah3, smu + SMQ_H + aoff);
                LDSM_X4(al0,al1,al2,al3, smu + SMQ_L + aoff);
            }
#pragma unroll
            for (int ntp = 0; ntp < 4; ntp++) {
                int boff = swz(ntp*16 + (lane & 15), kc*16 + (lane >> 4) * 8);
                unsigned k0,k1,k2,k3, e0,e1,e2,e3;
                LDSM_X4(k0,k1,k2,k3, kvb + OF_KH + boff);
                LDSM_X4(e0,e1,e2,e3, kvb + OF_KL + boff);
                MMA16816(S[2*ntp],   ah0,ah1,ah2,ah3, k0,k2);
                MMA16816(S[2*ntp],   ah0,ah1,ah2,ah3, e0,e2);
                MMA16816(S[2*ntp],   al0,al1,al2,al3, k0,k2);
                MMA16816(S[2*ntp+1], ah0,ah1,ah2,ah3, k1,k3);
                MMA16816(S[2*ntp+1], ah0,ah1,ah2,ah3, e1,e3);
                MMA16816(S[2*ntp+1], al0,al1,al2,al3, k1,k3);
            }
        }

        bool need_mask = (kb >= qb*2) || (kb <= qb*2 - 31);
        if (need_mask) {
#pragma unroll
            for (int nt = 0; nt < 8; nt++) {
                int j0 = kb*64 + nt*8 + 2*qd;
                S[nt][0] = ((unsigned)(ig0 - j0)     <= (unsigned)WIN) ? S[nt][0] : -1e30f;
                S[nt][1] = ((unsigned)(ig0 - j0 - 1) <= (unsigned)WIN) ? S[nt][1] : -1e30f;
                S[nt][2] = ((unsigned)(ig1 - j0)     <= (unsigned)WIN) ? S[nt][2] : -1e30f;
                S[nt][3] = ((unsigned)(ig1 - j0 - 1) <= (unsigned)WIN) ? S[nt][3] : -1e30f;
            }
        }

        float mx0 = -1e30f, mx1 = -1e30f;
#pragma unroll
        for (int nt = 0; nt < 8; nt++) {
            mx0 = fmaxf(mx0, fmaxf(S[nt][0], S[nt][1]));
            mx1 = fmaxf(mx1, fmaxf(S[nt][2], S[nt][3]));
        }
        mx0 = fmaxf(mx0, __shfl_xor_sync(0xffffffffu, mx0, 1));
        mx0 = fmaxf(mx0, __shfl_xor_sync(0xffffffffu, mx0, 2));
        mx1 = fmaxf(mx1, __shfl_xor_sync(0xffffffffu, mx1, 1));
        mx1 = fmaxf(mx1, __shfl_xor_sync(0xffffffffu, mx1, 2));

        float mn0 = fmaxf(m0, mx0);
        float mn1 = fmaxf(m1, mx1);
        float a0 = exp2f(m0 - mn0);
        float a1 = exp2f(m1 - mn1);
        float ok0 = (mn0 > -5e29f) ? 1.f : 0.f;
        float ok1 = (mn1 > -5e29f) ? 1.f : 0.f;
        m0 = mn0; m1 = mn1;
        l0s *= a0; l1s *= a1;

#pragma unroll
        for (int nt = 0; nt < 8; nt++) {
            S[nt][0] = exp2f(S[nt][0] - mn0) * ok0;
            S[nt][1] = exp2f(S[nt][1] - mn0) * ok0;
            S[nt][2] = exp2f(S[nt][2] - mn1) * ok1;
            S[nt][3] = exp2f(S[nt][3] - mn1) * ok1;
            l0s += S[nt][0] + S[nt][1];
            l1s += S[nt][2] + S[nt][3];
        }

#pragma unroll
        for (int i = 0; i < 16; i++) {
            o[i][0] *= a0; o[i][1] *= a0;
            o[i][2] *= a1; o[i][3] *= a1;
        }

        unsigned ph[4][4], pl[4][4];
#pragma unroll
        for (int t = 0; t < 4; t++) {
            split2(S[2*t][0],   S[2*t][1],   ph[t][0], pl[t][0]);
            split2(S[2*t][2],   S[2*t][3],   ph[t][1], pl[t][1]);
            split2(S[2*t+1][0], S[2*t+1][1], ph[t][2], pl[t][2]);
            split2(S[2*t+1][2], S[2*t+1][3], ph[t][3], pl[t][3]);
        }

#pragma unroll
        for (int t = 0; t < 4; t++) {
#pragma unroll
            for (int ntp = 0; ntp < 8; ntp++) {
                int voff = swz(t*16 + (lane & 15), ntp*16 + (lane >> 4) * 8);
                unsigned v0,v1,v2,v3, w0,w1,w2,w3;
                LDSM_X4_T(v0,v1,v2,v3, kvb + OF_VH + voff);
                LDSM_X4_T(w0,w1,w2,w3, kvb + OF_VL + voff);
                MMA16816(o[2*ntp],   ph[t][0],ph[t][1],ph[t][2],ph[t][3], v0,v1);
                MMA16816(o[2*ntp],   ph[t][0],ph[t][1],ph[t][2],ph[t][3], w0,w1);
                MMA16816(o[2*ntp],   pl[t][0],pl[t][1],pl[t][2],pl[t][3], v0,v1);
                MMA16816(o[2*ntp+1], ph[t][0],ph[t][1],ph[t][2],ph[t][3], v2,v3);
                MMA16816(o[2*ntp+1], ph[t][0],ph[t][1],ph[t][2],ph[t][3], w2,w3);
                MMA16816(o[2*ntp+1], pl[t][0],pl[t][1],pl[t][2],pl[t][3], v2,v3);
            }
        }
    }

    l0s += __shfl_xor_sync(0xffffffffu, l0s, 1);
    l0s += __shfl_xor_sync(0xffffffffu, l0s, 2);
    l1s += __shfl_xor_sync(0xffffffffu, l1s, 1);
    l1s += __shfl_xor_sync(0xffffffffu, l1s, 2);
    float inv0 = 1.f / l0s;
    float inv1 = 1.f / l1s;

#pragma unroll
    for (int nt = 0; nt < 16; nt++) {
        int col = h * HD + nt * 8 + 2 * qd;
        unsigned h0, l0;
        split2(o[nt][0] * inv0, o[nt][1] * inv0, h0, l0);
        *(unsigned*)&Oh[(size_t)ig0 * QDIM + col] = h0;
        *(unsigned*)&Ol[(size_t)ig0 * QDIM + col] = l0;
        split2(o[nt][2] * inv1, o[nt][3] * inv1, h0, l0);
        *(unsigned*)&Oh[(size_t)ig1 * QDIM + col] = h0;
        *(unsigned*)&Ol[(size_t)ig1 * QDIM + col] = l0;
    }
}

// =====================================================================
extern "C" void kernel_launch(void* const* d_in, const int* in_sizes, int n_in,
                              void* d_out, int out_size)
{
    const float* query = (const float*)d_in[0];
    const float* key   = (const float*)d_in[1];
    const float* value = (const float*)d_in[2];
    const int*   pos   = (const int*)d_in[3];
    const float* wq    = (const float*)d_in[4];
    const float* wk    = (const float*)d_in[5];
    const float* wv    = (const float*)d_in[6];
    const float* wo    = (const float*)d_in[7];
    float*       out   = (float*)d_out;

    float *q_s, *k_s;
    __nv_bfloat16 *qh,*ql,*kh,*kl,*vh,*vl,*ath,*atl;
    __nv_bfloat16 *xqh,*xql,*xkh,*xkl,*xvh,*xvl;
    __nv_bfloat16 *wqh,*wql,*wkh,*wkl,*wvh,*wvl,*woh,*wol;
    cudaGetSymbolAddress((void**)&q_s, g_q);   cudaGetSymbolAddress((void**)&k_s, g_k);
    cudaGetSymbolAddress((void**)&qh, g_qh);   cudaGetSymbolAddress((void**)&ql, g_ql);
    cudaGetSymbolAddress((void**)&kh, g_kh);   cudaGetSymbolAddress((void**)&kl, g_kl);
    cudaGetSymbolAddress((void**)&vh, g_vh);   cudaGetSymbolAddress((void**)&vl, g_vl);
    cudaGetSymbolAddress((void**)&ath, g_ath); cudaGetSymbolAddress((void**)&atl, g_atl);
    cudaGetSymbolAddress((void**)&xqh, g_xqh); cudaGetSymbolAddress((void**)&xql, g_xql);
    cudaGetSymbolAddress((void**)&xkh, g_xkh); cudaGetSymbolAddress((void**)&xkl, g_xkl);
    cudaGetSymbolAddress((void**)&xvh, g_xvh); cudaGetSymbolAddress((void**)&xvl, g_xvl);
    cudaGetSymbolAddress((void**)&wqh, g_wqh); cudaGetSymbolAddress((void**)&wql, g_wql);
    cudaGetSymbolAddress((void**)&wkh, g_wkh); cudaGetSymbolAddress((void**)&wkl, g_wkl);
    cudaGetSymbolAddress((void**)&wvh, g_wvh); cudaGetSymbolAddress((void**)&wvl, g_wvl);
    cudaGetSymbolAddress((void**)&woh, g_woh); cudaGetSymbolAddress((void**)&wol, g_wol);

    cudaFuncSetAttribute(attn_mma2, cudaFuncAttributeMaxDynamicSharedMemorySize, SMEM_ATTN2);
    cudaFuncSetAttribute(gemm6,     cudaFuncAttributeMaxDynamicSharedMemorySize, SMEM_GEMM);

    dim3 blk(256);

    // ---- merged pre-splits (1 launch) ----
    SplitPack sp;
    auto mk = [&](const float* s, __nv_bfloat16* h, __nv_bfloat16* l, size_t n) {
        return SplitArg{ (const float4*)s, (uint2*)h, (uint2*)l, (int)(n / 4 / 256) };
    };
    sp.a[0] = mk(query, xqh, xql, (size_t)SEQ * EMB);
    sp.a[1] = mk(key,   xkh, xkl, (size_t)SEQ * EMB);
    sp.a[2] = mk(value, xvh, xvl, (size_t)SEQ * EMB);
    sp.a[3] = mk(wq, wqh, wql, (size_t)EMB * QDIM);
    sp.a[4] = mk(wk, wkh, wkl, (size_t)EMB * KVDIM);
    sp.a[5] = mk(wv, wvh, wvl, (size_t)EMB * KVDIM);
    sp.a[6] = mk(wo, woh, wol, (size_t)QDIM * EMB);
    int total_blk = 0;
    for (int i = 0; i < 7; i++) total_blk += sp.a[i].nblk;
    split_all<<<total_blk, blk>>>(sp);

    // ---- q/k/v projections, one launch: x = [0,8)q [8,10)k [10,12)v ----
    GArg gq = { xqh, xql, wqh, wql, q_s, nullptr, nullptr, QDIM };
    GArg gk = { xkh, xkl, wkh, wkl, k_s, nullptr, nullptr, KVDIM };
    GArg gv = { xvh, xvl, wvh, wvl, nullptr, vh, vl, KVDIM };
    gemm6<<<dim3(12, SEQ/128), blk, SMEM_GEMM>>>(gq, gk, gv, 8, 10, EMB);

    // ---- rope + split q/k ----
    rope2_kernel<<<SEQ, blk>>>(pos, q_s, k_s, qh, ql, kh, kl);

    // ---- attention ----
    attn_mma2<<<dim3(SEQ/128, NH), blk, SMEM_ATTN2>>>(qh, ql, kh, kl, vh, vl, ath, atl);

    // ---- output projection ----
    GArg go = { ath, atl, woh, wol, out, nullptr, nullptr, EMB };
    gemm6<<<dim3(8, SEQ/128), blk, SMEM_GEMM>>>(go, go, go, 8, 8, QDIM);
}

// round 12
// speedup vs baseline: 1.1933x; 1.0819x over previous
#include <cuda_runtime.h>
#include <cuda_bf16.h>
#include <cuda_fp16.h>
#include <math.h>

#define SEQ  4096
#define EMB  2048
#define NH   16
#define NKVH 4
#define HD   128
#define WIN  2048
#define QDIM (NH*HD)    /* 2048 */
#define KVDIM (NKVH*HD) /* 512  */

// -------- scratch (device globals; no allocations allowed) --------
__device__ float g_q [SEQ * QDIM];
__device__ float g_k [SEQ * KVDIM];
__device__ __nv_bfloat16 g_qh[SEQ*QDIM],  g_ql[SEQ*QDIM];
__device__ __nv_bfloat16 g_kh[SEQ*KVDIM], g_kl[SEQ*KVDIM];
__device__ __half        g_vh[SEQ*KVDIM], g_vl[SEQ*KVDIM];   // V: fp16 split
__device__ __nv_bfloat16 g_ath[SEQ*QDIM], g_atl[SEQ*QDIM];
__device__ __nv_bfloat16 g_xqh[SEQ*EMB],  g_xql[SEQ*EMB];
__device__ __nv_bfloat16 g_xkh[SEQ*EMB],  g_xkl[SEQ*EMB];
__device__ __nv_bfloat16 g_xvh[SEQ*EMB],  g_xvl[SEQ*EMB];
__device__ __nv_bfloat16 g_wqh[EMB*QDIM], g_wql[EMB*QDIM];
__device__ __nv_bfloat16 g_wkh[EMB*KVDIM],g_wkl[EMB*KVDIM];
__device__ __nv_bfloat16 g_wvh[EMB*KVDIM],g_wvl[EMB*KVDIM];
__device__ __nv_bfloat16 g_woh[QDIM*EMB], g_wol[QDIM*EMB];

// ---------------- PTX helpers ----------------
#define LDSM_X4(r0,r1,r2,r3,addr) \
  asm volatile("ldmatrix.sync.aligned.m8n8.x4.shared.b16 {%0,%1,%2,%3}, [%4];" \
    : "=r"(r0),"=r"(r1),"=r"(r2),"=r"(r3) : "r"(addr))

#define LDSM_X4_T(r0,r1,r2,r3,addr) \
  asm volatile("ldmatrix.sync.aligned.m8n8.x4.trans.shared.b16 {%0,%1,%2,%3}, [%4];" \
    : "=r"(r0),"=r"(r1),"=r"(r2),"=r"(r3) : "r"(addr))

#define MMA16816(c, a0,a1,a2,a3, b0,b1) \
  asm volatile("mma.sync.aligned.m16n8k16.row.col.f32.bf16.bf16.f32 " \
    "{%0,%1,%2,%3}, {%4,%5,%6,%7}, {%8,%9}, {%0,%1,%2,%3};" \
    : "+f"((c)[0]),"+f"((c)[1]),"+f"((c)[2]),"+f"((c)[3]) \
    : "r"(a0),"r"(a1),"r"(a2),"r"(a3),"r"(b0),"r"(b1))

#define MMA16816H(c, a0,a1,a2,a3, b0,b1) \
  asm volatile("mma.sync.aligned.m16n8k16.row.col.f32.f16.f16.f32 " \
    "{%0,%1,%2,%3}, {%4,%5,%6,%7}, {%8,%9}, {%0,%1,%2,%3};" \
    : "+f"((c)[0]),"+f"((c)[1]),"+f"((c)[2]),"+f"((c)[3]) \
    : "r"(a0),"r"(a1),"r"(a2),"r"(a3),"r"(b0),"r"(b1))

#define CP_ASYNC16(dst32, srcptr) \
  asm volatile("cp.async.cg.shared.global [%0], [%1], 16;" :: "r"(dst32), "l"(srcptr))
#define CP_COMMIT() asm volatile("cp.async.commit_group;")
#define CP_WAIT0()  asm volatile("cp.async.wait_group 0;")

__device__ __forceinline__ unsigned pack_bf2(__nv_bfloat16 lo16, __nv_bfloat16 hi16) {
    return ((unsigned)__bfloat16_as_ushort(hi16) << 16) | (unsigned)__bfloat16_as_ushort(lo16);
}
__device__ __forceinline__ void split2(float x0, float x1, unsigned& hi, unsigned& lo) {
    __nv_bfloat16 h0 = __float2bfloat16(x0);
    __nv_bfloat16 h1 = __float2bfloat16(x1);
    __nv_bfloat16 l0 = __float2bfloat16(x0 - __bfloat162float(h0));
    __nv_bfloat16 l1 = __float2bfloat16(x1 - __bfloat162float(h1));
    hi = pack_bf2(h0, h1);
    lo = pack_bf2(l0, l1);
}
// fp16 split (for V)
__device__ __forceinline__ void split2h(float x0, float x1, unsigned& hi, unsigned& lo) {
    __half h0 = __float2half_rn(x0);
    __half h1 = __float2half_rn(x1);
    __half l0 = __float2half_rn(x0 - __half2float(h0));
    __half l1 = __float2half_rn(x1 - __half2float(h1));
    __half2 hv = __halves2half2(h0, h1);
    __half2 lv = __halves2half2(l0, l1);
    hi = *(unsigned*)&hv;
    lo = *(unsigned*)&lv;
}
__device__ __forceinline__ unsigned packh2(float a, float b) {
    __half2 h = __floats2half2_rn(a, b);
    return *(unsigned*)&h;
}

// =====================================================================
// merged elementwise fp32 -> bf16 hi/lo split (all 7 tensors, 1 launch)
// =====================================================================
struct SplitArg { const float4* s; uint2* h; uint2* l; int nblk; };
struct SplitPack { SplitArg a[7]; };

__global__ __launch_bounds__(256) void split_all(SplitPack p)
{
    int b = blockIdx.x;
    int seg = 0;
#pragma unroll
    for (int i = 0; i < 7; i++) {
        if (b >= p.a[seg].nblk) { b -= p.a[seg].nblk; seg++; }
    }
    const SplitArg sa = p.a[seg];
    int i = b * 256 + threadIdx.x;
    float4 v = sa.s[i];
    unsigned h0, l0, h1, l1;
    split2(v.x, v.y, h0, l0);
    split2(v.z, v.w, h1, l1);
    sa.h[i] = make_uint2(h0, h1);
    sa.l[i] = make_uint2(l0, l1);
}

// =====================================================================
// split-bf16 GEMM v7: CTA 128x128, warp 64x32, BK=32, 2-stage overlap,
// 75.8KB smem -> 2 CTAs/SM via __launch_bounds__(256,2).
// =====================================================================
#define A7_STRIDE 40    /* bf16 elems; row = 80B */
#define B7_STRIDE 136   /* bf16 elems; row = 272B */
#define G7_AH 0
#define G7_AL 10240
#define G7_BH 20480
#define G7_BL 29184
#define G7_STAGE 37888
#define SMEM_G7 (2*G7_STAGE)   /* 75776 */

struct GArg {
    const __nv_bfloat16 *Ah, *Al, *Bh, *Bl;
    float* C;
    __half *Ch, *Cl;     // fp16 split output (V only)
    int N;
};

__global__ __launch_bounds__(256, 2) void gemm7(
    GArg a0, GArg a1, GArg a2, int t0, int t1, int K)
{
    extern __shared__ char smg[];
    const unsigned smu = (unsigned)__cvta_generic_to_shared(smg);

    GArg ga; int bx = blockIdx.x, bn;
    if (bx < t0)      { ga = a0; bn = bx * 128; }
    else if (bx < t1) { ga = a1; bn = (bx - t0) * 128; }
    else              { ga = a2; bn = (bx - t1) * 128; }
    const int N  = ga.N;
    const int bm = blockIdx.y * 128;

    const int tid  = threadIdx.x;
    const int warp = tid >> 5;
    const int lane = tid & 31;
    const int wm   = warp >> 2;   // 0..1
    const int wn   = warp & 3;    // 0..3

    float acc[4][4][4];
#pragma unroll
    for (int i = 0; i < 4; i++)
#pragma unroll
        for (int j = 0; j < 4; j++)
#pragma unroll
            for (int r = 0; r < 4; r++) acc[i][j][r] = 0.f;

    auto issue = [&](int stage, int k0) {
        unsigned sb = smu + stage * G7_STAGE;
        // A: 128 rows x 4 chunks(16B) per half = 512 -> 2/thread
#pragma unroll
        for (int p = 0; p < 2; p++) {
            int idx = tid + p * 256;
            int row = idx >> 2, u = idx & 3;
            CP_ASYNC16(sb + G7_AH + row*80 + u*16, ga.Ah + (size_t)(bm + row)*K + k0 + u*8);
            CP_ASYNC16(sb + G7_AL + row*80 + u*16, ga.Al + (size_t)(bm + row)*K + k0 + u*8);
        }
        // B: 32 rows x 16 chunks per half = 512 -> 2/thread
#pragma unroll
        for (int p = 0; p < 2; p++) {
            int idx = tid + p * 256;
            int row = idx >> 4, u = idx & 15;
            CP_ASYNC16(sb + G7_BH + row*272 + u*16, ga.Bh + (size_t)(k0 + row)*N + bn + u*8);
            CP_ASYNC16(sb + G7_BL + row*272 + u*16, ga.Bl + (size_t)(k0 + row)*N + bn + u*8);
        }
        CP_COMMIT();
    };

    issue(0, 0);

    const int a_lrow = wm*64 + (lane & 15);
    const int a_lcol = (lane >> 4) * 8;

    const int nch = K / 32;
    for (int j = 0; j < nch; j++) {
        CP_WAIT0();
        __syncthreads();
        if (j + 1 < nch) issue((j + 1) & 1, (j + 1) * 32);

        const unsigned sa = smu + (j & 1) * G7_STAGE;

#pragma unroll
        for (int ks = 0; ks < 32; ks += 16) {
            unsigned ah[4][4], al[4][4];
#pragma unroll
            for (int mi = 0; mi < 4; mi++) {
                unsigned off = 2u * ((unsigned)((a_lrow + mi*16) * A7_STRIDE + ks + a_lcol));
                LDSM_X4(ah[mi][0], ah[mi][1], ah[mi][2], ah[mi][3], sa + G7_AH + off);
                LDSM_X4(al[mi][0], al[mi][1], al[mi][2], al[mi][3], sa + G7_AL + off);
            }
            unsigned bh[4][2], bl[4][2];
#pragma unroll
            for (int nb = 0; nb < 2; nb++) {
                unsigned off = 2u * ((unsigned)((ks + (lane & 15)) * B7_STRIDE
                                               + wn*32 + nb*16 + (lane >> 4) * 8));
                unsigned r0, r1, r2, r3;
                LDSM_X4_T(r0, r1, r2, r3, sa + G7_BH + off);
                bh[2*nb][0] = r0; bh[2*nb][1] = r1;
                bh[2*nb+1][0] = r2; bh[2*nb+1][1] = r3;
                LDSM_X4_T(r0, r1, r2, r3, sa + G7_BL + off);
                bl[2*nb][0] = r0; bl[2*nb][1] = r1;
                bl[2*nb+1][0] = r2; bl[2*nb+1][1] = r3;
            }
#pragma unroll
            for (int mi = 0; mi < 4; mi++) {
#pragma unroll
                for (int ni = 0; ni < 4; ni++) {
                    MMA16816(acc[mi][ni], ah[mi][0],ah[mi][1],ah[mi][2],ah[mi][3],
                             bh[ni][0], bh[ni][1]);
                    MMA16816(acc[mi][ni], ah[mi][0],ah[mi][1],ah[mi][2],ah[mi][3],
                             bl[ni][0], bl[ni][1]);
                    MMA16816(acc[mi][ni], al[mi][0],al[mi][1],al[mi][2],al[mi][3],
                             bh[ni][0], bh[ni][1]);
                }
            }
        }
    }

    const int g = lane >> 2, q = lane & 3;
#pragma unroll
    for (int mi = 0; mi < 4; mi++) {
#pragma unroll
        for (int ni = 0; ni < 4; ni++) {
            int row = bm + wm*64 + mi*16 + g;
            int col = bn + wn*32 + ni*8 + q*2;
            if (ga.C) {
                *(float2*)&ga.C[(size_t)row * N + col]       = make_float2(acc[mi][ni][0], acc[mi][ni][1]);
                *(float2*)&ga.C[(size_t)(row + 8) * N + col] = make_float2(acc[mi][ni][2], acc[mi][ni][3]);
            }
            if (ga.Ch) {
                unsigned h0, l0;
                split2h(acc[mi][ni][0], acc[mi][ni][1], h0, l0);
                *(unsigned*)&ga.Ch[(size_t)row * N + col] = h0;
                *(unsigned*)&ga.Cl[(size_t)row * N + col] = l0;
                split2h(acc[mi][ni][2], acc[mi][ni][3], h0, l0);
                *(unsigned*)&ga.Ch[(size_t)(row + 8) * N + col] = h0;
                *(unsigned*)&ga.Cl[(size_t)(row + 8) * N + col] = l0;
            }
        }
    }
}

// =====================================================================
// RoPE: rotate fp32 q/k, scale q by log2(e)/sqrt(HD), emit split bf16
// =====================================================================
__global__ __launch_bounds__(256) void rope2_kernel(
    const int* __restrict__ pos_w,
    const float* __restrict__ q, const float* __restrict__ k,
    __nv_bfloat16* __restrict__ qh, __nv_bfloat16* __restrict__ ql,
    __nv_bfloat16* __restrict__ kh, __nv_bfloat16* __restrict__ kl)
{
    const int s = blockIdx.x;
    const int tid = threadIdx.x;
    __shared__ float cs[64], sn[64];

    const float QSCALE = (float)(1.4426950408889634 * 0.08838834764831845);

    if (tid < 64) {
        bool is64 = (pos_w[1] == 0);
        int pi = is64 ? pos_w[2 * s] : pos_w[s];
        float p = (float)pi;
        float ex = (float)(2 * tid) / (float)HD;
        float inv = powf(10000.0f, -ex);
        float ang = p * inv;
        sincosf(ang, &sn[tid], &cs[tid]);
    }
    __syncthreads();

    for (int idx = tid; idx < NH * 64; idx += 256) {
        int h = idx >> 6, d = idx & 63;
        size_t base = (size_t)s * QDIM + h * HD;
        float x1 = q[base + d], x2 = q[base + d + 64];
        float c = cs[d], si = sn[d];
        float y1 = (x1 * c - x2 * si) * QSCALE;
        float y2 = (x2 * c + x1 * si) * QSCALE;
        __nv_bfloat16 h1 = __float2bfloat16(y1);
        __nv_bfloat16 h2 = __float2bfloat16(y2);
        qh[base + d]      = h1;
        qh[base + d + 64] = h2;
        ql[base + d]      = __float2bfloat16(y1 - __bfloat162float(h1));
        ql[base + d + 64] = __float2bfloat16(y2 - __bfloat162float(h2));
    }
    for (int idx = tid; idx < NKVH * 64; idx += 256) {
        int h = idx >> 6, d = idx & 63;
        size_t base = (size_t)s * KVDIM + h * HD;
        float x1 = k[base + d], x2 = k[base + d + 64];
        float c = cs[d], si = sn[d];
        float y1 = x1 * c - x2 * si;
        float y2 = x2 * c + x1 * si;
        __nv_bfloat16 h1 = __float2bfloat16(y1);
        __nv_bfloat16 h2 = __float2bfloat16(y2);
        kh[base + d]      = h1;
        kh[base + d + 64] = h2;
        kl[base + d]      = __float2bfloat16(y1 - __bfloat162float(h1));
        kl[base + d + 64] = __float2bfloat16(y2 - __bfloat162float(h2));
    }
}

// =====================================================================
// MMA flash attention v3: QK^T split-bf16 (3 MMAs), PV fp16 P (2 MMAs:
// P*Vh + P*Vl, V pre-split in fp16).
// =====================================================================
#define SMQ_H 0
#define SMQ_L 32768
#define KVBUF0 65536
#define KVSZ   65536
#define OF_KH  0
#define OF_KL  16384
#define OF_VH  32768
#define OF_VL  49152
#define SMEM_ATTN2 196608

__device__ __forceinline__ int swz(int row, int col_b16) {
    return row * 256 + ((((col_b16 >> 3) ^ (row & 7)) << 4)) + ((col_b16 & 7) << 1);
}

__global__ __launch_bounds__(256) void attn_mma3(
    const __nv_bfloat16* __restrict__ Qh, const __nv_bfloat16* __restrict__ Ql,
    const __nv_bfloat16* __restrict__ Kh, const __nv_bfloat16* __restrict__ Kl,
    const __half* __restrict__ Vh, const __half* __restrict__ Vl,
    __nv_bfloat16* __restrict__ Oh, __nv_bfloat16* __restrict__ Ol)
{
    extern __shared__ char sm[];
    const unsigned smu = (unsigned)__cvta_generic_to_shared(sm);

    const int tid  = threadIdx.x;
    const int warp = tid >> 5;
    const int lane = tid & 31;
    const int g    = lane >> 2;
    const int qd   = lane & 3;
    const int qb   = blockIdx.x;
    const int h    = blockIdx.y;
    const int kvh  = h >> 2;
    const int i0   = qb * 128;

    const int kb_lo = max(0, qb * 2 - 32);
    const int kb_hi = qb * 2 + 1;

    {
#pragma unroll
        for (int rep = 0; rep < 8; rep++) {
            int chunk = tid + rep * 256;
            int row = chunk >> 4, u = chunk & 15;
            unsigned dsto = row * 256 + (((u ^ (row & 7)) << 4));
            const __nv_bfloat16* sq = Qh + (size_t)(i0 + row) * QDIM + h * HD + u * 8;
            CP_ASYNC16(smu + SMQ_H + dsto, sq);
            const __nv_bfloat16* sl = Ql + (size_t)(i0 + row) * QDIM + h * HD + u * 8;
            CP_ASYNC16(smu + SMQ_L + dsto, sl);
        }
#pragma unroll
        for (int rep = 0; rep < 4; rep++) {
            int chunk = tid + rep * 256;
            int row = chunk >> 4, u = chunk & 15;
            unsigned dsto = row * 256 + (((u ^ (row & 7)) << 4));
            size_t srco = (size_t)(kb_lo * 64 + row) * KVDIM + kvh * HD + u * 8;
            CP_ASYNC16(smu + KVBUF0 + OF_KH + dsto, Kh + srco);
            CP_ASYNC16(smu + KVBUF0 + OF_KL + dsto, Kl + srco);
            CP_ASYNC16(smu + KVBUF0 + OF_VH + dsto, Vh + srco);
            CP_ASYNC16(smu + KVBUF0 + OF_VL + dsto, Vl + srco);
        }
        CP_COMMIT();
    }

    float o[16][4];
#pragma unroll
    for (int i = 0; i < 16; i++)
#pragma unroll
        for (int c = 0; c < 4; c++) o[i][c] = 0.f;

    float m0 = -1e30f, m1 = -1e30f, l0s = 0.f, l1s = 0.f;

    const int ig0 = i0 + warp * 16 + g;
    const int ig1 = ig0 + 8;

    for (int kb = kb_lo; kb <= kb_hi; kb++) {
        CP_WAIT0();
        __syncthreads();

        const int buf = (kb - kb_lo) & 1;
        const unsigned kvb = smu + KVBUF0 + buf * KVSZ;

        if (kb + 1 <= kb_hi) {
            const unsigned nb = smu + KVBUF0 + (buf ^ 1) * KVSZ;
#pragma unroll
            for (int rep = 0; rep < 4; rep++) {
                int chunk = tid + rep * 256;
                int row = chunk >> 4, u = chunk & 15;
                unsigned dsto = row * 256 + (((u ^ (row & 7)) << 4));
                size_t srco = (size_t)((kb + 1) * 64 + row) * KVDIM + kvh * HD + u * 8;
                CP_ASYNC16(nb + OF_KH + dsto, Kh + srco);
                CP_ASYNC16(nb + OF_KL + dsto, Kl + srco);
                CP_ASYNC16(nb + OF_VH + dsto, Vh + srco);
                CP_ASYNC16(nb + OF_VL + dsto, Vl + srco);
            }
            CP_COMMIT();
        }

        float S[8][4];
#pragma unroll
        for (int i = 0; i < 8; i++)
#pragma unroll
            for (int c = 0; c < 4; c++) S[i][c] = 0.f;

#pragma unroll
        for (int kc = 0; kc < 8; kc++) {
            unsigned ah0,ah1,ah2,ah3, al0,al1,al2,al3;
            {
                int aoff = swz(warp*16 + (lane & 15), kc*16 + (lane >> 4) * 8);
                LDSM_X4(ah0,ah1,ah2,ah3, smu + SMQ_H + aoff);
                LDSM_X4(al0,al1,al2,al3, smu + SMQ_L + aoff);
            }
#pragma unroll
            for (int ntp = 0; ntp < 4; ntp++) {
                int boff = swz(ntp*16 + (lane & 15), kc*16 + (lane >> 4) * 8);
                unsigned k0,k1,k2,k3, e0,e1,e2,e3;
                LDSM_X4(k0,k1,k2,k3, kvb + OF_KH + boff);
                LDSM_X4(e0,e1,e2,e3, kvb + OF_KL + boff);
                MMA16816(S[2*ntp],   ah0,ah1,ah2,ah3, k0,k2);
                MMA16816(S[2*ntp],   ah0,ah1,ah2,ah3, e0,e2);
                MMA16816(S[2*ntp],   al0,al1,al2,al3, k0,k2);
                MMA16816(S[2*ntp+1], ah0,ah1,ah2,ah3, k1,k3);
                MMA16816(S[2*ntp+1], ah0,ah1,ah2,ah3, e1,e3);
                MMA16816(S[2*ntp+1], al0,al1,al2,al3, k1,k3);
            }
        }

        bool need_mask = (kb >= qb*2) || (kb <= qb*2 - 31);
        if (need_mask) {
#pragma unroll
            for (int nt = 0; nt < 8; nt++) {
                int j0 = kb*64 + nt*8 + 2*qd;
                S[nt][0] = ((unsigned)(ig0 - j0)     <= (unsigned)WIN) ? S[nt][0] : -1e30f;
                S[nt][1] = ((unsigned)(ig0 - j0 - 1) <= (unsigned)WIN) ? S[nt][1] : -1e30f;
                S[nt][2] = ((unsigned)(ig1 - j0)     <= (unsigned)WIN) ? S[nt][2] : -1e30f;
                S[nt][3] = ((unsigned)(ig1 - j0 - 1) <= (unsigned)WIN) ? S[nt][3] : -1e30f;
            }
        }

        float mx0 = -1e30f, mx1 = -1e30f;
#pragma unroll
        for (int nt = 0; nt < 8; nt++) {
            mx0 = fmaxf(mx0, fmaxf(S[nt][0], S[nt][1]));
            mx1 = fmaxf(mx1, fmaxf(S[nt][2], S[nt][3]));
        }
        mx0 = fmaxf(mx0, __shfl_xor_sync(0xffffffffu, mx0, 1));
        mx0 = fmaxf(mx0, __shfl_xor_sync(0xffffffffu, mx0, 2));
        mx1 = fmaxf(mx1, __shfl_xor_sync(0xffffffffu, mx1, 1));
        mx1 = fmaxf(mx1, __shfl_xor_sync(0xffffffffu, mx1, 2));

        float mn0 = fmaxf(m0, mx0);
        float mn1 = fmaxf(m1, mx1);
        float a0 = exp2f(m0 - mn0);
        float a1 = exp2f(m1 - mn1);
        float ok0 = (mn0 > -5e29f) ? 1.f : 0.f;
        float ok1 = (mn1 > -5e29f) ? 1.f : 0.f;
        m0 = mn0; m1 = mn1;
        l0s *= a0; l1s *= a1;

#pragma unroll
        for (int nt = 0; nt < 8; nt++) {
            S[nt][0] = exp2f(S[nt][0] - mn0) * ok0;
            S[nt][1] = exp2f(S[nt][1] - mn0) * ok0;
            S[nt][2] = exp2f(S[nt][2] - mn1) * ok1;
            S[nt][3] = exp2f(S[nt][3] - mn1) * ok1;
            l0s += S[nt][0] + S[nt][1];
            l1s += S[nt][2] + S[nt][3];
        }

#pragma unroll
        for (int i = 0; i < 16; i++) {
            o[i][0] *= a0; o[i][1] *= a0;
            o[i][2] *= a1; o[i][3] *= a1;
        }

        // pack P into fp16 A-fragments (single quantization, no split)
        unsigned ph[4][4];
#pragma unroll
        for (int t = 0; t < 4; t++) {
            ph[t][0] = packh2(S[2*t][0],   S[2*t][1]);
            ph[t][1] = packh2(S[2*t][2],   S[2*t][3]);
            ph[t][2] = packh2(S[2*t+1][0], S[2*t+1][1]);
            ph[t][3] = packh2(S[2*t+1][2], S[2*t+1][3]);
        }

        // O += P * (Vh + Vl), fp16 MMAs
#pragma unroll
        for (int t = 0; t < 4; t++) {
#pragma unroll
            for (int ntp = 0; ntp < 8; ntp++) {
                int voff = swz(t*16 + (lane & 15), ntp*16 + (lane >> 4) * 8);
                unsigned v0,v1,v2,v3, w0,w1,w2,w3;
                LDSM_X4_T(v0,v1,v2,v3, kvb + OF_VH + voff);
                LDSM_X4_T(w0,w1,w2,w3, kvb + OF_VL + voff);
                MMA16816H(o[2*ntp],   ph[t][0],ph[t][1],ph[t][2],ph[t][3], v0,v1);
                MMA16816H(o[2*ntp],   ph[t][0],ph[t][1],ph[t][2],ph[t][3], w0,w1);
                MMA16816H(o[2*ntp+1], ph[t][0],ph[t][1],ph[t][2],ph[t][3], v2,v3);
                MMA16816H(o[2*ntp+1], ph[t][0],ph[t][1],ph[t][2],ph[t][3], w2,w3);
            }
        }
    }

    l0s += __shfl_xor_sync(0xffffffffu, l0s, 1);
    l0s += __shfl_xor_sync(0xffffffffu, l0s, 2);
    l1s += __shfl_xor_sync(0xffffffffu, l1s, 1);
    l1s += __shfl_xor_sync(0xffffffffu, l1s, 2);
    float inv0 = 1.f / l0s;
    float inv1 = 1.f / l1s;

#pragma unroll
    for (int nt = 0; nt < 16; nt++) {
        int col = h * HD + nt * 8 + 2 * qd;
        unsigned h0, l0;
        split2(o[nt][0] * inv0, o[nt][1] * inv0, h0, l0);
        *(unsigned*)&Oh[(size_t)ig0 * QDIM + col] = h0;
        *(unsigned*)&Ol[(size_t)ig0 * QDIM + col] = l0;
        split2(o[nt][2] * inv1, o[nt][3] * inv1, h0, l0);
        *(unsigned*)&Oh[(size_t)ig1 * QDIM + col] = h0;
        *(unsigned*)&Ol[(size_t)ig1 * QDIM + col] = l0;
    }
}

// =====================================================================
extern "C" void kernel_launch(void* const* d_in, const int* in_sizes, int n_in,
                              void* d_out, int out_size)
{
    const float* query = (const float*)d_in[0];
    const float* key   = (const float*)d_in[1];
    const float* value = (const float*)d_in[2];
    const int*   pos   = (const int*)d_in[3];
    const float* wq    = (const float*)d_in[4];
    const float* wk    = (const float*)d_in[5];
    const float* wv    = (const float*)d_in[6];
    const float* wo    = (const float*)d_in[7];
    float*       out   = (float*)d_out;

    float *q_s, *k_s;
    __nv_bfloat16 *qh,*ql,*kh,*kl,*ath,*atl;
    __half *vh,*vl;
    __nv_bfloat16 *xqh,*xql,*xkh,*xkl,*xvh,*xvl;
    __nv_bfloat16 *wqh,*wql,*wkh,*wkl,*wvh,*wvl,*woh,*wol;
    cudaGetSymbolAddress((void**)&q_s, g_q);   cudaGetSymbolAddress((void**)&k_s, g_k);
    cudaGetSymbolAddress((void**)&qh, g_qh);   cudaGetSymbolAddress((void**)&ql, g_ql);
    cudaGetSymbolAddress((void**)&kh, g_kh);   cudaGetSymbolAddress((void**)&kl, g_kl);
    cudaGetSymbolAddress((void**)&vh, g_vh);   cudaGetSymbolAddress((void**)&vl, g_vl);
    cudaGetSymbolAddress((void**)&ath, g_ath); cudaGetSymbolAddress((void**)&atl, g_atl);
    cudaGetSymbolAddress((void**)&xqh, g_xqh); cudaGetSymbolAddress((void**)&xql, g_xql);
    cudaGetSymbolAddress((void**)&xkh, g_xkh); cudaGetSymbolAddress((void**)&xkl, g_xkl);
    cudaGetSymbolAddress((void**)&xvh, g_xvh); cudaGetSymbolAddress((void**)&xvl, g_xvl);
    cudaGetSymbolAddress((void**)&wqh, g_wqh); cudaGetSymbolAddress((void**)&wql, g_wql);
    cudaGetSymbolAddress((void**)&wkh, g_wkh); cudaGetSymbolAddress((void**)&wkl, g_wkl);
    cudaGetSymbolAddress((void**)&wvh, g_wvh); cudaGetSymbolAddress((void**)&wvl, g_wvl);
    cudaGetSymbolAddress((void**)&woh, g_woh); cudaGetSymbolAddress((void**)&wol, g_wol);

    cudaFuncSetAttribute(attn_mma3, cudaFuncAttributeMaxDynamicSharedMemorySize, SMEM_ATTN2);
    cudaFuncSetAttribute(gemm7,     cudaFuncAttributeMaxDynamicSharedMemorySize, SMEM_G7);

    dim3 blk(256);

    // ---- merged pre-splits (1 launch) ----
    SplitPack sp;
    auto mk = [&](const float* s, __nv_bfloat16* h, __nv_bfloat16* l, size_t n) {
        return SplitArg{ (const float4*)s, (uint2*)h, (uint2*)l, (int)(n / 4 / 256) };
    };
    sp.a[0] = mk(query, xqh, xql, (size_t)SEQ * EMB);
    sp.a[1] = mk(key,   xkh, xkl, (size_t)SEQ * EMB);
    sp.a[2] = mk(value, xvh, xvl, (size_t)SEQ * EMB);
    sp.a[3] = mk(wq, wqh, wql, (size_t)EMB * QDIM);
    sp.a[4] = mk(wk, wkh, wkl, (size_t)EMB * KVDIM);
    sp.a[5] = mk(wv, wvh, wvl, (size_t)EMB * KVDIM);
    sp.a[6] = mk(wo, woh, wol, (size_t)QDIM * EMB);
    int total_blk = 0;
    for (int i = 0; i < 7; i++) total_blk += sp.a[i].nblk;
    split_all<<<total_blk, blk>>>(sp);

    // ---- q/k/v projections, one launch: x = [0,16)q [16,20)k [20,24)v ----
    GArg gq = { xqh, xql, wqh, wql, q_s, nullptr, nullptr, QDIM };
    GArg gk = { xkh, xkl, wkh, wkl, k_s, nullptr, nullptr, KVDIM };
    GArg gv = { xvh, xvl, wvh, wvl, nullptr, vh, vl, KVDIM };
    gemm7<<<dim3(24, SEQ/128), blk, SMEM_G7>>>(gq, gk, gv, 16, 20, EMB);

    // ---- rope + split q/k ----
    rope2_kernel<<<SEQ, blk>>>(pos, q_s, k_s, qh, ql, kh, kl);

    // ---- attention ----
    attn_mma3<<<dim3(SEQ/128, NH), blk, SMEM_ATTN2>>>(qh, ql, kh, kl, vh, vl, ath, atl);

    // ---- output projection ----
    GArg go = { ath, atl, woh, wol, out, nullptr, nullptr, EMB };
    gemm7<<<dim3(16, SEQ/128), blk, SMEM_G7>>>(go, go, go, 16, 16, QDIM);
}

// round 13
// speedup vs baseline: 1.4893x; 1.2480x over previous
#include <cuda_runtime.h>
#include <cuda_bf16.h>
#include <cuda_fp16.h>
#include <math.h>

#define SEQ  4096
#define EMB  2048
#define NH   16
#define NKVH 4
#define HD   128
#define WIN  2048
#define QDIM (NH*HD)    /* 2048 */
#define KVDIM (NKVH*HD) /* 512  */

// -------- scratch (device globals; no allocations allowed) --------
__device__ float g_q [SEQ * QDIM];
__device__ float g_k [SEQ * KVDIM];
__device__ __nv_bfloat16 g_qh[SEQ*QDIM],  g_ql[SEQ*QDIM];     // rope'd q split (bf16)
__device__ __nv_bfloat16 g_kh[SEQ*KVDIM], g_kl[SEQ*KVDIM];    // rope'd k split (bf16)
__device__ __half        g_vh[SEQ*KVDIM], g_vl[SEQ*KVDIM];    // V fp16 split
__device__ __half        g_at16[SEQ*QDIM];                    // attention out, fp16 single
__device__ __half        g_x16q[SEQ*EMB], g_x16k[SEQ*EMB], g_x16v[SEQ*EMB];  // inputs fp16 single
__device__ __half        g_wqh[EMB*QDIM], g_wql[EMB*QDIM];    // weights fp16 split
__device__ __half        g_wkh[EMB*KVDIM],g_wkl[EMB*KVDIM];
__device__ __half        g_wvh[EMB*KVDIM],g_wvl[EMB*KVDIM];
__device__ __half        g_woh[QDIM*EMB], g_wol[QDIM*EMB];

// ---------------- PTX helpers ----------------
#define LDSM_X4(r0,r1,r2,r3,addr) \
  asm volatile("ldmatrix.sync.aligned.m8n8.x4.shared.b16 {%0,%1,%2,%3}, [%4];" \
    : "=r"(r0),"=r"(r1),"=r"(r2),"=r"(r3) : "r"(addr))

#define LDSM_X4_T(r0,r1,r2,r3,addr) \
  asm volatile("ldmatrix.sync.aligned.m8n8.x4.trans.shared.b16 {%0,%1,%2,%3}, [%4];" \
    : "=r"(r0),"=r"(r1),"=r"(r2),"=r"(r3) : "r"(addr))

#define MMA16816(c, a0,a1,a2,a3, b0,b1) \
  asm volatile("mma.sync.aligned.m16n8k16.row.col.f32.bf16.bf16.f32 " \
    "{%0,%1,%2,%3}, {%4,%5,%6,%7}, {%8,%9}, {%0,%1,%2,%3};" \
    : "+f"((c)[0]),"+f"((c)[1]),"+f"((c)[2]),"+f"((c)[3]) \
    : "r"(a0),"r"(a1),"r"(a2),"r"(a3),"r"(b0),"r"(b1))

#define MMA16816H(c, a0,a1,a2,a3, b0,b1) \
  asm volatile("mma.sync.aligned.m16n8k16.row.col.f32.f16.f16.f32 " \
    "{%0,%1,%2,%3}, {%4,%5,%6,%7}, {%8,%9}, {%0,%1,%2,%3};" \
    : "+f"((c)[0]),"+f"((c)[1]),"+f"((c)[2]),"+f"((c)[3]) \
    : "r"(a0),"r"(a1),"r"(a2),"r"(a3),"r"(b0),"r"(b1))

#define CP_ASYNC16(dst32, srcptr) \
  asm volatile("cp.async.cg.shared.global [%0], [%1], 16;" :: "r"(dst32), "l"(srcptr))
#define CP_COMMIT() asm volatile("cp.async.commit_group;")
#define CP_WAIT0()  asm volatile("cp.async.wait_group 0;")

__device__ __forceinline__ unsigned pack_bf2(__nv_bfloat16 lo16, __nv_bfloat16 hi16) {
    return ((unsigned)__bfloat16_as_ushort(hi16) << 16) | (unsigned)__bfloat16_as_ushort(lo16);
}
__device__ __forceinline__ void split2(float x0, float x1, unsigned& hi, unsigned& lo) {
    __nv_bfloat16 h0 = __float2bfloat16(x0);
    __nv_bfloat16 h1 = __float2bfloat16(x1);
    __nv_bfloat16 l0 = __float2bfloat16(x0 - __bfloat162float(h0));
    __nv_bfloat16 l1 = __float2bfloat16(x1 - __bfloat162float(h1));
    hi = pack_bf2(h0, h1);
    lo = pack_bf2(l0, l1);
}
__device__ __forceinline__ void split2h(float x0, float x1, unsigned& hi, unsigned& lo) {
    __half h0 = __float2half_rn(x0);
    __half h1 = __float2half_rn(x1);
    __half l0 = __float2half_rn(x0 - __half2float(h0));
    __half l1 = __float2half_rn(x1 - __half2float(h1));
    __half2 hv = __halves2half2(h0, h1);
    __half2 lv = __halves2half2(l0, l1);
    hi = *(unsigned*)&hv;
    lo = *(unsigned*)&lv;
}
__device__ __forceinline__ unsigned packh2(float a, float b) {
    __half2 h = __floats2half2_rn(a, b);
    return *(unsigned*)&h;
}

// =====================================================================
// merged pre-pass: mode 0 = fp16 split (weights), mode 1 = fp16 single
// quantize (inputs). One launch for all 7 tensors.
// =====================================================================
struct SplitArg { const float4* s; uint2* h; uint2* l; int nblk; int mode; };
struct SplitPack { SplitArg a[7]; };

__global__ __launch_bounds__(256) void split_all(SplitPack p)
{
    int b = blockIdx.x;
    int seg = 0;
#pragma unroll
    for (int i = 0; i < 7; i++) {
        if (b >= p.a[seg].nblk) { b -= p.a[seg].nblk; seg++; }
    }
    const SplitArg sa = p.a[seg];
    int i = b * 256 + threadIdx.x;
    float4 v = sa.s[i];
    if (sa.mode == 1) {
        sa.h[i] = make_uint2(packh2(v.x, v.y), packh2(v.z, v.w));
    } else {
        unsigned h0, l0, h1, l1;
        split2h(v.x, v.y, h0, l0);
        split2h(v.z, v.w, h1, l1);
        sa.h[i] = make_uint2(h0, h1);
        sa.l[i] = make_uint2(l0, l1);
    }
}

// =====================================================================
// fp16 GEMM v8: C = A16 @ (Bh+Bl).  A single fp16, B split fp16,
// 2 MMAs per product. CTA 128x128, warp 64x32, BK=32, 2-stage overlap,
// 54KB smem -> 2 CTAs/SM.
// =====================================================================
#define A8_STRIDE 40    /* fp16 elems; row = 80B */
#define B8_STRIDE 136   /* fp16 elems; row = 272B */
#define G8_A  0
#define G8_BH 10240
#define G8_BL 18944
#define G8_STAGE 27648
#define SMEM_G8 (2*G8_STAGE)   /* 55296 */

struct GArg {
    const __half *A, *Bh, *Bl;
    float* C;
    __half *Ch, *Cl;     // fp16 split output (v-proj only)
    int N;
};

__global__ __launch_bounds__(256, 2) void gemm8(
    GArg a0, GArg a1, GArg a2, int t0, int t1, int K)
{
    extern __shared__ char smg[];
    const unsigned smu = (unsigned)__cvta_generic_to_shared(smg);

    GArg ga; int bx = blockIdx.x, bn;
    if (bx < t0)      { ga = a0; bn = bx * 128; }
    else if (bx < t1) { ga = a1; bn = (bx - t0) * 128; }
    else              { ga = a2; bn = (bx - t1) * 128; }
    const int N  = ga.N;
    const int bm = blockIdx.y * 128;

    const int tid  = threadIdx.x;
    const int warp = tid >> 5;
    const int lane = tid & 31;
    const int wm   = warp >> 2;   // 0..1
    const int wn   = warp & 3;    // 0..3

    float acc[4][4][4];
#pragma unroll
    for (int i = 0; i < 4; i++)
#pragma unroll
        for (int j = 0; j < 4; j++)
#pragma unroll
            for (int r = 0; r < 4; r++) acc[i][j][r] = 0.f;

    auto issue = [&](int stage, int k0) {
        unsigned sb = smu + stage * G8_STAGE;
        // A: 128 rows x 4 chunks(16B) = 512 -> 2/thread
#pragma unroll
        for (int p = 0; p < 2; p++) {
            int idx = tid + p * 256;
            int row = idx >> 2, u = idx & 3;
            CP_ASYNC16(sb + G8_A + row*80 + u*16, ga.A + (size_t)(bm + row)*K + k0 + u*8);
        }
        // B: 32 rows x 16 chunks per half = 512 each -> 2+2/thread
#pragma unroll
        for (int p = 0; p < 2; p++) {
            int idx = tid + p * 256;
            int row = idx >> 4, u = idx & 15;
            CP_ASYNC16(sb + G8_BH + row*272 + u*16, ga.Bh + (size_t)(k0 + row)*N + bn + u*8);
            CP_ASYNC16(sb + G8_BL + row*272 + u*16, ga.Bl + (size_t)(k0 + row)*N + bn + u*8);
        }
        CP_COMMIT();
    };

    issue(0, 0);

    const int a_lrow = wm*64 + (lane & 15);
    const int a_lcol = (lane >> 4) * 8;

    const int nch = K / 32;
    for (int j = 0; j < nch; j++) {
        CP_WAIT0();
        __syncthreads();
        if (j + 1 < nch) issue((j + 1) & 1, (j + 1) * 32);

        const unsigned sa = smu + (j & 1) * G8_STAGE;

#pragma unroll
        for (int ks = 0; ks < 32; ks += 16) {
            unsigned ah[4][4];
#pragma unroll
            for (int mi = 0; mi < 4; mi++) {
                unsigned off = 2u * ((unsigned)((a_lrow + mi*16) * A8_STRIDE + ks + a_lcol));
                LDSM_X4(ah[mi][0], ah[mi][1], ah[mi][2], ah[mi][3], sa + G8_A + off);
            }
            unsigned bh[4][2], bl[4][2];
#pragma unroll
            for (int nb = 0; nb < 2; nb++) {
                unsigned off = 2u * ((unsigned)((ks + (lane & 15)) * B8_STRIDE
                                               + wn*32 + nb*16 + (lane >> 4) * 8));
                unsigned r0, r1, r2, r3;
                LDSM_X4_T(r0, r1, r2, r3, sa + G8_BH + off);
                bh[2*nb][0] = r0; bh[2*nb][1] = r1;
                bh[2*nb+1][0] = r2; bh[2*nb+1][1] = r3;
                LDSM_X4_T(r0, r1, r2, r3, sa + G8_BL + off);
                bl[2*nb][0] = r0; bl[2*nb][1] = r1;
                bl[2*nb+1][0] = r2; bl[2*nb+1][1] = r3;
            }
#pragma unroll
            for (int mi = 0; mi < 4; mi++) {
#pragma unroll
                for (int ni = 0; ni < 4; ni++) {
                    MMA16816H(acc[mi][ni], ah[mi][0],ah[mi][1],ah[mi][2],ah[mi][3],
                              bh[ni][0], bh[ni][1]);
                    MMA16816H(acc[mi][ni], ah[mi][0],ah[mi][1],ah[mi][2],ah[mi][3],
                              bl[ni][0], bl[ni][1]);
                }
            }
        }
    }

    const int g = lane >> 2, q = lane & 3;
#pragma unroll
    for (int mi = 0; mi < 4; mi++) {
#pragma unroll
        for (int ni = 0; ni < 4; ni++) {
            int row = bm + wm*64 + mi*16 + g;
            int col = bn + wn*32 + ni*8 + q*2;
            if (ga.C) {
                *(float2*)&ga.C[(size_t)row * N + col]       = make_float2(acc[mi][ni][0], acc[mi][ni][1]);
                *(float2*)&ga.C[(size_t)(row + 8) * N + col] = make_float2(acc[mi][ni][2], acc[mi][ni][3]);
            }
            if (ga.Ch) {
                unsigned h0, l0;
                split2h(acc[mi][ni][0], acc[mi][ni][1], h0, l0);
                *(unsigned*)&ga.Ch[(size_t)row * N + col] = h0;
                *(unsigned*)&ga.Cl[(size_t)row * N + col] = l0;
                split2h(acc[mi][ni][2], acc[mi][ni][3], h0, l0);
                *(unsigned*)&ga.Ch[(size_t)(row + 8) * N + col] = h0;
                *(unsigned*)&ga.Cl[(size_t)(row + 8) * N + col] = l0;
            }
        }
    }
}

// =====================================================================
// RoPE: rotate fp32 q/k, scale q by log2(e)/sqrt(HD), emit split bf16
// =====================================================================
__global__ __launch_bounds__(256) void rope2_kernel(
    const int* __restrict__ pos_w,
    const float* __restrict__ q, const float* __restrict__ k,
    __nv_bfloat16* __restrict__ qh, __nv_bfloat16* __restrict__ ql,
    __nv_bfloat16* __restrict__ kh, __nv_bfloat16* __restrict__ kl)
{
    const int s = blockIdx.x;
    const int tid = threadIdx.x;
    __shared__ float cs[64], sn[64];

    const float QSCALE = (float)(1.4426950408889634 * 0.08838834764831845);

    if (tid < 64) {
        bool is64 = (pos_w[1] == 0);
        int pi = is64 ? pos_w[2 * s] : pos_w[s];
        float p = (float)pi;
        float ex = (float)(2 * tid) / (float)HD;
        float inv = powf(10000.0f, -ex);
        float ang = p * inv;
        sincosf(ang, &sn[tid], &cs[tid]);
    }
    __syncthreads();

    for (int idx = tid; idx < NH * 64; idx += 256) {
        int h = idx >> 6, d = idx & 63;
        size_t base = (size_t)s * QDIM + h * HD;
        float x1 = q[base + d], x2 = q[base + d + 64];
        float c = cs[d], si = sn[d];
        float y1 = (x1 * c - x2 * si) * QSCALE;
        float y2 = (x2 * c + x1 * si) * QSCALE;
        __nv_bfloat16 h1 = __float2bfloat16(y1);
        __nv_bfloat16 h2 = __float2bfloat16(y2);
        qh[base + d]      = h1;
        qh[base + d + 64] = h2;
        ql[base + d]      = __float2bfloat16(y1 - __bfloat162float(h1));
        ql[base + d + 64] = __float2bfloat16(y2 - __bfloat162float(h2));
    }
    for (int idx = tid; idx < NKVH * 64; idx += 256) {
        int h = idx >> 6, d = idx & 63;
        size_t base = (size_t)s * KVDIM + h * HD;
        float x1 = k[base + d], x2 = k[base + d + 64];
        float c = cs[d], si = sn[d];
        float y1 = x1 * c - x2 * si;
        float y2 = x2 * c + x1 * si;
        __nv_bfloat16 h1 = __float2bfloat16(y1);
        __nv_bfloat16 h2 = __float2bfloat16(y2);
        kh[base + d]      = h1;
        kh[base + d + 64] = h2;
        kl[base + d]      = __float2bfloat16(y1 - __bfloat162float(h1));
        kl[base + d + 64] = __float2bfloat16(y2 - __bfloat162float(h2));
    }
}

// =====================================================================
// MMA flash attention v3 (R12 version, 394us) — epilogue now writes
// single fp16 output (A operand of o-proj).
// =====================================================================
#define SMQ_H 0
#define SMQ_L 32768
#define KVBUF0 65536
#define KVSZ   65536
#define OF_KH  0
#define OF_KL  16384
#define OF_VH  32768
#define OF_VL  49152
#define SMEM_ATTN2 196608

__device__ __forceinline__ int swz(int row, int col_b16) {
    return row * 256 + ((((col_b16 >> 3) ^ (row & 7)) << 4)) + ((col_b16 & 7) << 1);
}

__global__ __launch_bounds__(256) void attn_mma3(
    const __nv_bfloat16* __restrict__ Qh, const __nv_bfloat16* __restrict__ Ql,
    const __nv_bfloat16* __restrict__ Kh, const __nv_bfloat16* __restrict__ Kl,
    const __half* __restrict__ Vh, const __half* __restrict__ Vl,
    __half* __restrict__ O16)
{
    extern __shared__ char sm[];
    const unsigned smu = (unsigned)__cvta_generic_to_shared(sm);

    const int tid  = threadIdx.x;
    const int warp = tid >> 5;
    const int lane = tid & 31;
    const int g    = lane >> 2;
    const int qd   = lane & 3;
    const int qb   = blockIdx.x;
    const int h    = blockIdx.y;
    const int kvh  = h >> 2;
    const int i0   = qb * 128;

    const int kb_lo = max(0, qb * 2 - 32);
    const int kb_hi = qb * 2 + 1;

    {
#pragma unroll
        for (int rep = 0; rep < 8; rep++) {
            int chunk = tid + rep * 256;
            int row = chunk >> 4, u = chunk & 15;
            unsigned dsto = row * 256 + (((u ^ (row & 7)) << 4));
            const __nv_bfloat16* sq = Qh + (size_t)(i0 + row) * QDIM + h * HD + u * 8;
            CP_ASYNC16(smu + SMQ_H + dsto, sq);
            const __nv_bfloat16* sl = Ql + (size_t)(i0 + row) * QDIM + h * HD + u * 8;
            CP_ASYNC16(smu + SMQ_L + dsto, sl);
        }
#pragma unroll
        for (int rep = 0; rep < 4; rep++) {
            int chunk = tid + rep * 256;
            int row = chunk >> 4, u = chunk & 15;
            unsigned dsto = row * 256 + (((u ^ (row & 7)) << 4));
            size_t srco = (size_t)(kb_lo * 64 + row) * KVDIM + kvh * HD + u * 8;
            CP_ASYNC16(smu + KVBUF0 + OF_KH + dsto, Kh + srco);
            CP_ASYNC16(smu + KVBUF0 + OF_KL + dsto, Kl + srco);
            CP_ASYNC16(smu + KVBUF0 + OF_VH + dsto, Vh + srco);
            CP_ASYNC16(smu + KVBUF0 + OF_VL + dsto, Vl + srco);
        }
        CP_COMMIT();
    }

    float o[16][4];
#pragma unroll
    for (int i = 0; i < 16; i++)
#pragma unroll
        for (int c = 0; c < 4; c++) o[i][c] = 0.f;

    float m0 = -1e30f, m1 = -1e30f, l0s = 0.f, l1s = 0.f;

    const int ig0 = i0 + warp * 16 + g;
    const int ig1 = ig0 + 8;

    for (int kb = kb_lo; kb <= kb_hi; kb++) {
        CP_WAIT0();
        __syncthreads();

        const int buf = (kb - kb_lo) & 1;
        const unsigned kvb = smu + KVBUF0 + buf * KVSZ;

        if (kb + 1 <= kb_hi) {
            const unsigned nb = smu + KVBUF0 + (buf ^ 1) * KVSZ;
#pragma unroll
            for (int rep = 0; rep < 4; rep++) {
                int chunk = tid + rep * 256;
                int row = chunk >> 4, u = chunk & 15;
                unsigned dsto = row * 256 + (((u ^ (row & 7)) << 4));
                size_t srco = (size_t)((kb + 1) * 64 + row) * KVDIM + kvh * HD + u * 8;
                CP_ASYNC16(nb + OF_KH + dsto, Kh + srco);
                CP_ASYNC16(nb + OF_KL + dsto, Kl + srco);
                CP_ASYNC16(nb + OF_VH + dsto, Vh + srco);
                CP_ASYNC16(nb + OF_VL + dsto, Vl + srco);
            }
            CP_COMMIT();
        }

        float S[8][4];
#pragma unroll
        for (int i = 0; i < 8; i++)
#pragma unroll
            for (int c = 0; c < 4; c++) S[i][c] = 0.f;

#pragma unroll
        for (int kc = 0; kc < 8; kc++) {
            unsigned ah0,ah1,ah2,ah3, al0,al1,al2,al3;
            {
                int aoff = swz(warp*16 + (lane & 15), kc*16 + (lane >> 4) * 8);
                LDSM_X4(ah0,ah1,ah2,ah3, smu + SMQ_H + aoff);
                LDSM_X4(al0,al1,al2,al3, smu + SMQ_L + aoff);
            }
#pragma unroll
            for (int ntp = 0; ntp < 4; ntp++) {
                int boff = swz(ntp*16 + (lane & 15), kc*16 + (lane >> 4) * 8);
                unsigned k0,k1,k2,k3, e0,e1,e2,e3;
                LDSM_X4(k0,k1,k2,k3, kvb + OF_KH + boff);
                LDSM_X4(e0,e1,e2,e3, kvb + OF_KL + boff);
                MMA16816(S[2*ntp],   ah0,ah1,ah2,ah3, k0,k2);
                MMA16816(S[2*ntp],   ah0,ah1,ah2,ah3, e0,e2);
                MMA16816(S[2*ntp],   al0,al1,al2,al3, k0,k2);
                MMA16816(S[2*ntp+1], ah0,ah1,ah2,ah3, k1,k3);
                MMA16816(S[2*ntp+1], ah0,ah1,ah2,ah3, e1,e3);
                MMA16816(S[2*ntp+1], al0,al1,al2,al3, k1,k3);
            }
        }

        bool need_mask = (kb >= qb*2) || (kb <= qb*2 - 31);
        if (need_mask) {
#pragma unroll
            for (int nt = 0; nt < 8; nt++) {
                int j0 = kb*64 + nt*8 + 2*qd;
                S[nt][0] = ((unsigned)(ig0 - j0)     <= (unsigned)WIN) ? S[nt][0] : -1e30f;
                S[nt][1] = ((unsigned)(ig0 - j0 - 1) <= (unsigned)WIN) ? S[nt][1] : -1e30f;
                S[nt][2] = ((unsigned)(ig1 - j0)     <= (unsigned)WIN) ? S[nt][2] : -1e30f;
                S[nt][3] = ((unsigned)(ig1 - j0 - 1) <= (unsigned)WIN) ? S[nt][3] : -1e30f;
            }
        }

        float mx0 = -1e30f, mx1 = -1e30f;
#pragma unroll
        for (int nt = 0; nt < 8; nt++) {
            mx0 = fmaxf(mx0, fmaxf(S[nt][0], S[nt][1]));
            mx1 = fmaxf(mx1, fmaxf(S[nt][2], S[nt][3]));
        }
        mx0 = fmaxf(mx0, __shfl_xor_sync(0xffffffffu, mx0, 1));
        mx0 = fmaxf(mx0, __shfl_xor_sync(0xffffffffu, mx0, 2));
        mx1 = fmaxf(mx1, __shfl_xor_sync(0xffffffffu, mx1, 1));
        mx1 = fmaxf(mx1, __shfl_xor_sync(0xffffffffu, mx1, 2));

        float mn0 = fmaxf(m0, mx0);
        float mn1 = fmaxf(m1, mx1);
        float a0 = exp2f(m0 - mn0);
        float a1 = exp2f(m1 - mn1);
        float ok0 = (mn0 > -5e29f) ? 1.f : 0.f;
        float ok1 = (mn1 > -5e29f) ? 1.f : 0.f;
        m0 = mn0; m1 = mn1;
        l0s *= a0; l1s *= a1;

#pragma unroll
        for (int nt = 0; nt < 8; nt++) {
            S[nt][0] = exp2f(S[nt][0] - mn0) * ok0;
            S[nt][1] = exp2f(S[nt][1] - mn0) * ok0;
            S[nt][2] = exp2f(S[nt][2] - mn1) * ok1;
            S[nt][3] = exp2f(S[nt][3] - mn1) * ok1;
            l0s += S[nt][0] + S[nt][1];
            l1s += S[nt][2] + S[nt][3];
        }

#pragma unroll
        for (int i = 0; i < 16; i++) {
            o[i][0] *= a0; o[i][1] *= a0;
            o[i][2] *= a1; o[i][3] *= a1;
        }

        unsigned ph[4][4];
#pragma unroll
        for (int t = 0; t < 4; t++) {
            ph[t][0] = packh2(S[2*t][0],   S[2*t][1]);
            ph[t][1] = packh2(S[2*t][2],   S[2*t][3]);
            ph[t][2] = packh2(S[2*t+1][0], S[2*t+1][1]);
            ph[t][3] = packh2(S[2*t+1][2], S[2*t+1][3]);
        }

#pragma unroll
        for (int t = 0; t < 4; t++) {
#pragma unroll
            for (int ntp = 0; ntp < 8; ntp++) {
                int voff = swz(t*16 + (lane & 15), ntp*16 + (lane >> 4) * 8);
                unsigned v0,v1,v2,v3, w0,w1,w2,w3;
                LDSM_X4_T(v0,v1,v2,v3, kvb + OF_VH + voff);
                LDSM_X4_T(w0,w1,w2,w3, kvb + OF_VL + voff);
                MMA16816H(o[2*ntp],   ph[t][0],ph[t][1],ph[t][2],ph[t][3], v0,v1);
                MMA16816H(o[2*ntp],   ph[t][0],ph[t][1],ph[t][2],ph[t][3], w0,w1);
                MMA16816H(o[2*ntp+1], ph[t][0],ph[t][1],ph[t][2],ph[t][3], v2,v3);
                MMA16816H(o[2*ntp+1], ph[t][0],ph[t][1],ph[t][2],ph[t][3], w2,w3);
            }
        }
    }

    l0s += __shfl_xor_sync(0xffffffffu, l0s, 1);
    l0s += __shfl_xor_sync(0xffffffffu, l0s, 2);
    l1s += __shfl_xor_sync(0xffffffffu, l1s, 1);
    l1s += __shfl_xor_sync(0xffffffffu, l1s, 2);
    float inv0 = 1.f / l0s;
    float inv1 = 1.f / l1s;

#pragma unroll
    for (int nt = 0; nt < 16; nt++) {
        int col = h * HD + nt * 8 + 2 * qd;
        *(unsigned*)&O16[(size_t)ig0 * QDIM + col] = packh2(o[nt][0] * inv0, o[nt][1] * inv0);
        *(unsigned*)&O16[(size_t)ig1 * QDIM + col] = packh2(o[nt][2] * inv1, o[nt][3] * inv1);
    }
}

// =====================================================================
extern "C" void kernel_launch(void* const* d_in, const int* in_sizes, int n_in,
                              void* d_out, int out_size)
{
    const float* query = (const float*)d_in[0];
    const float* key   = (const float*)d_in[1];
    const float* value = (const float*)d_in[2];
    const int*   pos   = (const int*)d_in[3];
    const float* wq    = (const float*)d_in[4];
    const float* wk    = (const float*)d_in[5];
    const float* wv    = (const float*)d_in[6];
    const float* wo    = (const float*)d_in[7];
    float*       out   = (float*)d_out;

    float *q_s, *k_s;
    __nv_bfloat16 *qh,*ql,*kh,*kl;
    __half *vh,*vl,*at16,*x16q,*x16k,*x16v;
    __half *wqh,*wql,*wkh,*wkl,*wvh,*wvl,*woh,*wol;
    cudaGetSymbolAddress((void**)&q_s, g_q);     cudaGetSymbolAddress((void**)&k_s, g_k);
    cudaGetSymbolAddress((void**)&qh, g_qh);     cudaGetSymbolAddress((void**)&ql, g_ql);
    cudaGetSymbolAddress((void**)&kh, g_kh);     cudaGetSymbolAddress((void**)&kl, g_kl);
    cudaGetSymbolAddress((void**)&vh, g_vh);     cudaGetSymbolAddress((void**)&vl, g_vl);
    cudaGetSymbolAddress((void**)&at16, g_at16);
    cudaGetSymbolAddress((void**)&x16q, g_x16q); cudaGetSymbolAddress((void**)&x16k, g_x16k);
    cudaGetSymbolAddress((void**)&x16v, g_x16v);
    cudaGetSymbolAddress((void**)&wqh, g_wqh);   cudaGetSymbolAddress((void**)&wql, g_wql);
    cudaGetSymbolAddress((void**)&wkh, g_wkh);   cudaGetSymbolAddress((void**)&wkl, g_wkl);
    cudaGetSymbolAddress((void**)&wvh, g_wvh);   cudaGetSymbolAddress((void**)&wvl, g_wvl);
    cudaGetSymbolAddress((void**)&woh, g_woh);   cudaGetSymbolAddress((void**)&wol, g_wol);

    cudaFuncSetAttribute(attn_mma3, cudaFuncAttributeMaxDynamicSharedMemorySize, SMEM_ATTN2);
    cudaFuncSetAttribute(gemm8,     cudaFuncAttributeMaxDynamicSharedMemorySize, SMEM_G8);

    dim3 blk(256);

    // ---- merged pre-pass: quantize inputs (mode 1), split weights (mode 0) ----
    SplitPack sp;
    auto mk = [&](const float* s, __half* h, __half* l, size_t n, int mode) {
        return SplitArg{ (const float4*)s, (uint2*)h, (uint2*)l, (int)(n / 4 / 256), mode };
    };
    sp.a[0] = mk(query, x16q, nullptr, (size_t)SEQ * EMB, 1);
    sp.a[1] = mk(key,   x16k, nullptr, (size_t)SEQ * EMB, 1);
    sp.a[2] = mk(value, x16v, nullptr, (size_t)SEQ * EMB, 1);
    sp.a[3] = mk(wq, wqh, wql, (size_t)EMB * QDIM, 0);
    sp.a[4] = mk(wk, wkh, wkl, (size_t)EMB * KVDIM, 0);
    sp.a[5] = mk(wv, wvh, wvl, (size_t)EMB * KVDIM, 0);
    sp.a[6] = mk(wo, woh, wol, (size_t)QDIM * EMB, 0);
    int total_blk = 0;
    for (int i = 0; i < 7; i++) total_blk += sp.a[i].nblk;
    split_all<<<total_blk, blk>>>(sp);

    // ---- q/k/v projections, one launch: x = [0,16)q [16,20)k [20,24)v ----
    GArg gq = { x16q, wqh, wql, q_s, nullptr, nullptr, QDIM };
    GArg gk = { x16k, wkh, wkl, k_s, nullptr, nullptr, KVDIM };
    GArg gv = { x16v, wvh, wvl, nullptr, vh, vl, KVDIM };
    gemm8<<<dim3(24, SEQ/128), blk, SMEM_G8>>>(gq, gk, gv, 16, 20, EMB);

    // ---- rope + split q/k ----
    rope2_kernel<<<SEQ, blk>>>(pos, q_s, k_s, qh, ql, kh, kl);

    // ---- attention ----
    attn_mma3<<<dim3(SEQ/128, NH), blk, SMEM_ATTN2>>>(qh, ql, kh, kl, vh, vl, at16);

    // ---- output projection ----
    GArg go = { at16, woh, wol, out, nullptr, nullptr, EMB };
    gemm8<<<dim3(16, SEQ/128), blk, SMEM_G8>>>(go, go, go, 16, 16, QDIM);
}

// round 14
// speedup vs baseline: 2.5925x; 1.7407x over previous
#include <cuda_runtime.h>
#include <cuda_fp16.h>
#include <math.h>

#define SEQ  4096
#define EMB  2048
#define NH   16
#define NKVH 4
#define HD   128
#define WIN  2048
#define QDIM (NH*HD)    /* 2048 */
#define KVDIM (NKVH*HD) /* 512  */

// -------- scratch (device globals; no allocations allowed) --------
__device__ float  g_q [SEQ * QDIM];     // q proj out fp32 (rope input)
__device__ float  g_k [SEQ * KVDIM];    // k proj out fp32 (rope input)
__device__ __half g_q16[SEQ*QDIM];      // rope'd+scaled q, fp16
__device__ __half g_k16[SEQ*KVDIM];     // rope'd k, fp16
__device__ __half g_v16[SEQ*KVDIM];     // v proj out, fp16
__device__ __half g_at16[SEQ*QDIM];     // attention out, fp16
__device__ __half g_x16q[SEQ*EMB], g_x16k[SEQ*EMB], g_x16v[SEQ*EMB];
__device__ __half g_w16q[EMB*QDIM], g_w16k[EMB*KVDIM], g_w16v[EMB*KVDIM], g_w16o[QDIM*EMB];

// ---------------- PTX helpers ----------------
#define LDSM_X4(r0,r1,r2,r3,addr) \
  asm volatile("ldmatrix.sync.aligned.m8n8.x4.shared.b16 {%0,%1,%2,%3}, [%4];" \
    : "=r"(r0),"=r"(r1),"=r"(r2),"=r"(r3) : "r"(addr))

#define LDSM_X4_T(r0,r1,r2,r3,addr) \
  asm volatile("ldmatrix.sync.aligned.m8n8.x4.trans.shared.b16 {%0,%1,%2,%3}, [%4];" \
    : "=r"(r0),"=r"(r1),"=r"(r2),"=r"(r3) : "r"(addr))

#define MMA16816H(c, a0,a1,a2,a3, b0,b1) \
  asm volatile("mma.sync.aligned.m16n8k16.row.col.f32.f16.f16.f32 " \
    "{%0,%1,%2,%3}, {%4,%5,%6,%7}, {%8,%9}, {%0,%1,%2,%3};" \
    : "+f"((c)[0]),"+f"((c)[1]),"+f"((c)[2]),"+f"((c)[3]) \
    : "r"(a0),"r"(a1),"r"(a2),"r"(a3),"r"(b0),"r"(b1))

#define CP_ASYNC16(dst32, srcptr) \
  asm volatile("cp.async.cg.shared.global [%0], [%1], 16;" :: "r"(dst32), "l"(srcptr))
#define CP_COMMIT() asm volatile("cp.async.commit_group;")
#define CP_WAIT0()  asm volatile("cp.async.wait_group 0;")

__device__ __forceinline__ unsigned packh2(float a, float b) {
    __half2 h = __floats2half2_rn(a, b);
    return *(unsigned*)&h;
}

// =====================================================================
// merged pre-pass: quantize all 7 tensors to fp16 (1 launch)
// =====================================================================
struct QArg { const float4* s; uint2* d; int nblk; };
struct QPack { QArg a[7]; };

__global__ __launch_bounds__(256) void quant_all(QPack p)
{
    int b = blockIdx.x;
    int seg = 0;
#pragma unroll
    for (int i = 0; i < 7; i++) {
        if (b >= p.a[seg].nblk) { b -= p.a[seg].nblk; seg++; }
    }
    const QArg sa = p.a[seg];
    int i = b * 256 + threadIdx.x;
    float4 v = sa.s[i];
    sa.d[i] = make_uint2(packh2(v.x, v.y), packh2(v.z, v.w));
}

// =====================================================================
// fp16 GEMM v9: C = A16 @ B16, 1 MMA per product.
// CTA 128x128, warp 64x32, BK=32, 2-stage overlap, 2 CTAs/SM.
// =====================================================================
#define A9_STRIDE 40    /* fp16 elems; row = 80B */
#define B9_STRIDE 136   /* fp16 elems; row = 272B */
#define G9_A  0
#define G9_B  10240
#define G9_STAGE 18944
#define SMEM_G9 (2*G9_STAGE)   /* 37888 */

struct GArg {
    const __half *A, *B;
    float* C;
    __half* C16;
    int N;
};

__global__ __launch_bounds__(256, 2) void gemm9(
    GArg a0, GArg a1, GArg a2, int t0, int t1, int K)
{
    extern __shared__ char smg[];
    const unsigned smu = (unsigned)__cvta_generic_to_shared(smg);

    GArg ga; int bx = blockIdx.x, bn;
    if (bx < t0)      { ga = a0; bn = bx * 128; }
    else if (bx < t1) { ga = a1; bn = (bx - t0) * 128; }
    else              { ga = a2; bn = (bx - t1) * 128; }
    const int N  = ga.N;
    const int bm = blockIdx.y * 128;

    const int tid  = threadIdx.x;
    const int warp = tid >> 5;
    const int lane = tid & 31;
    const int wm   = warp >> 2;   // 0..1
    const int wn   = warp & 3;    // 0..3

    float acc[4][4][4];
#pragma unroll
    for (int i = 0; i < 4; i++)
#pragma unroll
        for (int j = 0; j < 4; j++)
#pragma unroll
            for (int r = 0; r < 4; r++) acc[i][j][r] = 0.f;

    auto issue = [&](int stage, int k0) {
        unsigned sb = smu + stage * G9_STAGE;
#pragma unroll
        for (int p = 0; p < 2; p++) {          // A: 512 chunks -> 2/thread
            int idx = tid + p * 256;
            int row = idx >> 2, u = idx & 3;
            CP_ASYNC16(sb + G9_A + row*80 + u*16, ga.A + (size_t)(bm + row)*K + k0 + u*8);
        }
#pragma unroll
        for (int p = 0; p < 2; p++) {          // B: 512 chunks -> 2/thread
            int idx = tid + p * 256;
            int row = idx >> 4, u = idx & 15;
            CP_ASYNC16(sb + G9_B + row*272 + u*16, ga.B + (size_t)(k0 + row)*N + bn + u*8);
        }
        CP_COMMIT();
    };

    issue(0, 0);

    const int a_lrow = wm*64 + (lane & 15);
    const int a_lcol = (lane >> 4) * 8;

    const int nch = K / 32;
    for (int j = 0; j < nch; j++) {
        CP_WAIT0();
        __syncthreads();
        if (j + 1 < nch) issue((j + 1) & 1, (j + 1) * 32);

        const unsigned sa = smu + (j & 1) * G9_STAGE;

#pragma unroll
        for (int ks = 0; ks < 32; ks += 16) {
            unsigned ah[4][4];
#pragma unroll
            for (int mi = 0; mi < 4; mi++) {
                unsigned off = 2u * ((unsigned)((a_lrow + mi*16) * A9_STRIDE + ks + a_lcol));
                LDSM_X4(ah[mi][0], ah[mi][1], ah[mi][2], ah[mi][3], sa + G9_A + off);
            }
            unsigned bh[4][2];
#pragma unroll
            for (int nb = 0; nb < 2; nb++) {
                unsigned off = 2u * ((unsigned)((ks + (lane & 15)) * B9_STRIDE
                                               + wn*32 + nb*16 + (lane >> 4) * 8));
                unsigned r0, r1, r2, r3;
                LDSM_X4_T(r0, r1, r2, r3, sa + G9_B + off);
                bh[2*nb][0] = r0; bh[2*nb][1] = r1;
                bh[2*nb+1][0] = r2; bh[2*nb+1][1] = r3;
            }
#pragma unroll
            for (int mi = 0; mi < 4; mi++) {
#pragma unroll
                for (int ni = 0; ni < 4; ni++) {
                    MMA16816H(acc[mi][ni], ah[mi][0],ah[mi][1],ah[mi][2],ah[mi][3],
                              bh[ni][0], bh[ni][1]);
                }
            }
        }
    }

    const int g = lane >> 2, q = lane & 3;
#pragma unroll
    for (int mi = 0; mi < 4; mi++) {
#pragma unroll
        for (int ni = 0; ni < 4; ni++) {
            int row = bm + wm*64 + mi*16 + g;
            int col = bn + wn*32 + ni*8 + q*2;
            if (ga.C) {
                *(float2*)&ga.C[(size_t)row * N + col]       = make_float2(acc[mi][ni][0], acc[mi][ni][1]);
                *(float2*)&ga.C[(size_t)(row + 8) * N + col] = make_float2(acc[mi][ni][2], acc[mi][ni][3]);
            }
            if (ga.C16) {
                *(unsigned*)&ga.C16[(size_t)row * N + col]       = packh2(acc[mi][ni][0], acc[mi][ni][1]);
                *(unsigned*)&ga.C16[(size_t)(row + 8) * N + col] = packh2(acc[mi][ni][2], acc[mi][ni][3]);
            }
        }
    }
}

// =====================================================================
// RoPE: rotate fp32 q/k, scale q by log2(e)/sqrt(HD), emit fp16
// =====================================================================
__global__ __launch_bounds__(256) void rope3_kernel(
    const int* __restrict__ pos_w,
    const float* __restrict__ q, const float* __restrict__ k,
    __half* __restrict__ q16, __half* __restrict__ k16)
{
    const int s = blockIdx.x;
    const int tid = threadIdx.x;
    __shared__ float cs[64], sn[64];

    const float QSCALE = (float)(1.4426950408889634 * 0.08838834764831845);

    if (tid < 64) {
        bool is64 = (pos_w[1] == 0);
        int pi = is64 ? pos_w[2 * s] : pos_w[s];
        float p = (float)pi;
        float ex = (float)(2 * tid) / (float)HD;
        float inv = powf(10000.0f, -ex);
        float ang = p * inv;
        sincosf(ang, &sn[tid], &cs[tid]);
    }
    __syncthreads();

    for (int idx = tid; idx < NH * 64; idx += 256) {
        int h = idx >> 6, d = idx & 63;
        size_t base = (size_t)s * QDIM + h * HD;
        float x1 = q[base + d], x2 = q[base + d + 64];
        float c = cs[d], si = sn[d];
        q16[base + d]      = __float2half_rn((x1 * c - x2 * si) * QSCALE);
        q16[base + d + 64] = __float2half_rn((x2 * c + x1 * si) * QSCALE);
    }
    for (int idx = tid; idx < NKVH * 64; idx += 256) {
        int h = idx >> 6, d = idx & 63;
        size_t base = (size_t)s * KVDIM + h * HD;
        float x1 = k[base + d], x2 = k[base + d + 64];
        float c = cs[d], si = sn[d];
        k16[base + d]      = __float2half_rn(x1 * c - x2 * si);
        k16[base + d + 64] = __float2half_rn(x2 * c + x1 * si);
    }
}

// =====================================================================
// MMA flash attention v4: all fp16, 1 MMA per product.
// smem: Q 32KB + 2 x (K 16KB + V 16KB) = 96KB.
// =====================================================================
#define SMQ    0
#define KVBUF0 32768
#define KVSZ   32768
#define OF_K   0
#define OF_V   16384
#define SMEM_ATTN4 98304

__device__ __forceinline__ int swz(int row, int col_b16) {
    return row * 256 + ((((col_b16 >> 3) ^ (row & 7)) << 4)) + ((col_b16 & 7) << 1);
}

__global__ __launch_bounds__(256) void attn_mma4(
    const __half* __restrict__ Q16, const __half* __restrict__ K16,
    const __half* __restrict__ V16, __half* __restrict__ O16)
{
    extern __shared__ char sm[];
    const unsigned smu = (unsigned)__cvta_generic_to_shared(sm);

    const int tid  = threadIdx.x;
    const int warp = tid >> 5;
    const int lane = tid & 31;
    const int g    = lane >> 2;
    const int qd   = lane & 3;
    const int qb   = blockIdx.x;
    const int h    = blockIdx.y;
    const int kvh  = h >> 2;
    const int i0   = qb * 128;

    const int kb_lo = max(0, qb * 2 - 32);
    const int kb_hi = qb * 2 + 1;

    {
        // Q: 128 rows x 16 units = 2048 chunks -> 8/thread
#pragma unroll
        for (int rep = 0; rep < 8; rep++) {
            int chunk = tid + rep * 256;
            int row = chunk >> 4, u = chunk & 15;
            unsigned dsto = row * 256 + (((u ^ (row & 7)) << 4));
            CP_ASYNC16(smu + SMQ + dsto, Q16 + (size_t)(i0 + row) * QDIM + h * HD + u * 8);
        }
        // K,V: 64 rows x 16 units = 1024 chunks each -> 4 reps
#pragma unroll
        for (int rep = 0; rep < 4; rep++) {
            int chunk = tid + rep * 256;
            int row = chunk >> 4, u = chunk & 15;
            unsigned dsto = row * 256 + (((u ^ (row & 7)) << 4));
            size_t srco = (size_t)(kb_lo * 64 + row) * KVDIM + kvh * HD + u * 8;
            CP_ASYNC16(smu + KVBUF0 + OF_K + dsto, K16 + srco);
            CP_ASYNC16(smu + KVBUF0 + OF_V + dsto, V16 + srco);
        }
        CP_COMMIT();
    }

    float o[16][4];
#pragma unroll
    for (int i = 0; i < 16; i++)
#pragma unroll
        for (int c = 0; c < 4; c++) o[i][c] = 0.f;

    float m0 = -1e30f, m1 = -1e30f, l0s = 0.f, l1s = 0.f;

    const int ig0 = i0 + warp * 16 + g;
    const int ig1 = ig0 + 8;

    for (int kb = kb_lo; kb <= kb_hi; kb++) {
        CP_WAIT0();
        __syncthreads();

        const int buf = (kb - kb_lo) & 1;
        const unsigned kvb = smu + KVBUF0 + buf * KVSZ;

        if (kb + 1 <= kb_hi) {
            const unsigned nb = smu + KVBUF0 + (buf ^ 1) * KVSZ;
#pragma unroll
            for (int rep = 0; rep < 4; rep++) {
                int chunk = tid + rep * 256;
                int row = chunk >> 4, u = chunk & 15;
                unsigned dsto = row * 256 + (((u ^ (row & 7)) << 4));
                size_t srco = (size_t)((kb + 1) * 64 + row) * KVDIM + kvh * HD + u * 8;
                CP_ASYNC16(nb + OF_K + dsto, K16 + srco);
                CP_ASYNC16(nb + OF_V + dsto, V16 + srco);
            }
            CP_COMMIT();
        }

        float S[8][4];
#pragma unroll
        for (int i = 0; i < 8; i++)
#pragma unroll
            for (int c = 0; c < 4; c++) S[i][c] = 0.f;

#pragma unroll
        for (int kc = 0; kc < 8; kc++) {
            unsigned a0,a1,a2,a3;
            {
                int aoff = swz(warp*16 + (lane & 15), kc*16 + (lane >> 4) * 8);
                LDSM_X4(a0,a1,a2,a3, smu + SMQ + aoff);
            }
#pragma unroll
            for (int ntp = 0; ntp < 4; ntp++) {
                int boff = swz(ntp*16 + (lane & 15), kc*16 + (lane >> 4) * 8);
                unsigned k0,k1,k2,k3;
                LDSM_X4(k0,k1,k2,k3, kvb + OF_K + boff);
                MMA16816H(S[2*ntp],   a0,a1,a2,a3, k0,k2);
                MMA16816H(S[2*ntp+1], a0,a1,a2,a3, k1,k3);
            }
        }

        bool need_mask = (kb >= qb*2) || (kb <= qb*2 - 31);
        if (need_mask) {
#pragma unroll
            for (int nt = 0; nt < 8; nt++) {
                int j0 = kb*64 + nt*8 + 2*qd;
                S[nt][0] = ((unsigned)(ig0 - j0)     <= (unsigned)WIN) ? S[nt][0] : -1e30f;
                S[nt][1] = ((unsigned)(ig0 - j0 - 1) <= (unsigned)WIN) ? S[nt][1] : -1e30f;
                S[nt][2] = ((unsigned)(ig1 - j0)     <= (unsigned)WIN) ? S[nt][2] : -1e30f;
                S[nt][3] = ((unsigned)(ig1 - j0 - 1) <= (unsigned)WIN) ? S[nt][3] : -1e30f;
            }
        }

        float mx0 = -1e30f, mx1 = -1e30f;
#pragma unroll
        for (int nt = 0; nt < 8; nt++) {
            mx0 = fmaxf(mx0, fmaxf(S[nt][0], S[nt][1]));
            mx1 = fmaxf(mx1, fmaxf(S[nt][2], S[nt][3]));
        }
        mx0 = fmaxf(mx0, __shfl_xor_sync(0xffffffffu, mx0, 1));
        mx0 = fmaxf(mx0, __shfl_xor_sync(0xffffffffu, mx0, 2));
        mx1 = fmaxf(mx1, __shfl_xor_sync(0xffffffffu, mx1, 1));
        mx1 = fmaxf(mx1, __shfl_xor_sync(0xffffffffu, mx1, 2));

        float mn0 = fmaxf(m0, mx0);
        float mn1 = fmaxf(m1, mx1);
        float a0 = exp2f(m0 - mn0);
        float a1 = exp2f(m1 - mn1);
        float ok0 = (mn0 > -5e29f) ? 1.f : 0.f;
        float ok1 = (mn1 > -5e29f) ? 1.f : 0.f;
        m0 = mn0; m1 = mn1;
        l0s *= a0; l1s *= a1;

#pragma unroll
        for (int nt = 0; nt < 8; nt++) {
            S[nt][0] = exp2f(S[nt][0] - mn0) * ok0;
            S[nt][1] = exp2f(S[nt][1] - mn0) * ok0;
            S[nt][2] = exp2f(S[nt][2] - mn1) * ok1;
            S[nt][3] = exp2f(S[nt][3] - mn1) * ok1;
            l0s += S[nt][0] + S[nt][1];
            l1s += S[nt][2] + S[nt][3];
        }

#pragma unroll
        for (int i = 0; i < 16; i++) {
            o[i][0] *= a0; o[i][1] *= a0;
            o[i][2] *= a1; o[i][3] *= a1;
        }

        unsigned ph[4][4];
#pragma unroll
        for (int t = 0; t < 4; t++) {
            ph[t][0] = packh2(S[2*t][0],   S[2*t][1]);
            ph[t][1] = packh2(S[2*t][2],   S[2*t][3]);
            ph[t][2] = packh2(S[2*t+1][0], S[2*t+1][1]);
            ph[t][3] = packh2(S[2*t+1][2], S[2*t+1][3]);
        }

#pragma unroll
        for (int t = 0; t < 4; t++) {
#pragma unroll
            for (int ntp = 0; ntp < 8; ntp++) {
                int voff = swz(t*16 + (lane & 15), ntp*16 + (lane >> 4) * 8);
                unsigned v0,v1,v2,v3;
                LDSM_X4_T(v0,v1,v2,v3, kvb + OF_V + voff);
                MMA16816H(o[2*ntp],   ph[t][0],ph[t][1],ph[t][2],ph[t][3], v0,v1);
                MMA16816H(o[2*ntp+1], ph[t][0],ph[t][1],ph[t][2],ph[t][3], v2,v3);
            }
        }
    }

    l0s += __shfl_xor_sync(0xffffffffu, l0s, 1);
    l0s += __shfl_xor_sync(0xffffffffu, l0s, 2);
    l1s += __shfl_xor_sync(0xffffffffu, l1s, 1);
    l1s += __shfl_xor_sync(0xffffffffu, l1s, 2);
    float inv0 = 1.f / l0s;
    float inv1 = 1.f / l1s;

#pragma unroll
    for (int nt = 0; nt < 16; nt++) {
        int col = h * HD + nt * 8 + 2 * qd;
        *(unsigned*)&O16[(size_t)ig0 * QDIM + col] = packh2(o[nt][0] * inv0, o[nt][1] * inv0);
        *(unsigned*)&O16[(size_t)ig1 * QDIM + col] = packh2(o[nt][2] * inv1, o[nt][3] * inv1);
    }
}

// =====================================================================
extern "C" void kernel_launch(void* const* d_in, const int* in_sizes, int n_in,
                              void* d_out, int out_size)
{
    const float* query = (const float*)d_in[0];
    const float* key   = (const float*)d_in[1];
    const float* value = (const float*)d_in[2];
    const int*   pos   = (const int*)d_in[3];
    const float* wq    = (const float*)d_in[4];
    const float* wk    = (const float*)d_in[5];
    const float* wv    = (const float*)d_in[6];
    const float* wo    = (const float*)d_in[7];
    float*       out   = (float*)d_out;

    float *q_s, *k_s;
    __half *q16,*k16,*v16,*at16,*x16q,*x16k,*x16v;
    __half *w16q,*w16k,*w16v,*w16o;
    cudaGetSymbolAddress((void**)&q_s, g_q);     cudaGetSymbolAddress((void**)&k_s, g_k);
    cudaGetSymbolAddress((void**)&q16, g_q16);   cudaGetSymbolAddress((void**)&k16, g_k16);
    cudaGetSymbolAddress((void**)&v16, g_v16);   cudaGetSymbolAddress((void**)&at16, g_at16);
    cudaGetSymbolAddress((void**)&x16q, g_x16q); cudaGetSymbolAddress((void**)&x16k, g_x16k);
    cudaGetSymbolAddress((void**)&x16v, g_x16v);
    cudaGetSymbolAddress((void**)&w16q, g_w16q); cudaGetSymbolAddress((void**)&w16k, g_w16k);
    cudaGetSymbolAddress((void**)&w16v, g_w16v); cudaGetSymbolAddress((void**)&w16o, g_w16o);

    cudaFuncSetAttribute(attn_mma4, cudaFuncAttributeMaxDynamicSharedMemorySize, SMEM_ATTN4);
    cudaFuncSetAttribute(gemm9,     cudaFuncAttributeMaxDynamicSharedMemorySize, SMEM_G9);

    dim3 blk(256);

    // ---- merged quantize pre-pass (1 launch, 7 tensors) ----
    QPack sp;
    auto mk = [&](const float* s, __half* d, size_t n) {
        return QArg{ (const float4*)s, (uint2*)d, (int)(n / 4 / 256) };
    };
    sp.a[0] = mk(query, x16q, (size_t)SEQ * EMB);
    sp.a[1] = mk(key,   x16k, (size_t)SEQ * EMB);
    sp.a[2] = mk(value, x16v, (size_t)SEQ * EMB);
    sp.a[3] = mk(wq, w16q, (size_t)EMB * QDIM);
    sp.a[4] = mk(wk, w16k, (size_t)EMB * KVDIM);
    sp.a[5] = mk(wv, w16v, (size_t)EMB * KVDIM);
    sp.a[6] = mk(wo, w16o, (size_t)QDIM * EMB);
    int total_blk = 0;
    for (int i = 0; i < 7; i++) total_blk += sp.a[i].nblk;
    quant_all<<<total_blk, blk>>>(sp);

    // ---- q/k/v projections, one launch: x = [0,16)q [16,20)k [20,24)v ----
    GArg gq = { x16q, w16q, q_s, nullptr, QDIM };
    GArg gk = { x16k, w16k, k_s, nullptr, KVDIM };
    GArg gv = { x16v, w16v, nullptr, v16, KVDIM };
    gemm9<<<dim3(24, SEQ/128), blk, SMEM_G9>>>(gq, gk, gv, 16, 20, EMB);

    // ---- rope -> fp16 q/k ----
    rope3_kernel<<<SEQ, blk>>>(pos, q_s, k_s, q16, k16);

    // ---- attention ----
    attn_mma4<<<dim3(SEQ/128, NH), blk, SMEM_ATTN4>>>(q16, k16, v16, at16);

    // ---- output projection ----
    GArg go = { at16, w16o, out, nullptr, EMB };
    gemm9<<<dim3(16, SEQ/128), blk, SMEM_G9>>>(go, go, go, 16, 16, QDIM);
}

// round 15
// speedup vs baseline: 2.7343x; 1.0547x over previous
#include <cuda_runtime.h>
#include <cuda_fp16.h>
#include <math.h>

#define SEQ  4096
#define EMB  2048
#define NH   16
#define NKVH 4
#define HD   128
#define WIN  2048
#define QDIM (NH*HD)    /* 2048 */
#define KVDIM (NKVH*HD) /* 512  */

// -------- scratch (device globals; no allocations allowed) --------
__device__ float  g_q [SEQ * QDIM];
__device__ float  g_k [SEQ * KVDIM];
__device__ __half g_q16[SEQ*QDIM];
__device__ __half g_k16[SEQ*KVDIM];
__device__ __half g_v16[SEQ*KVDIM];
__device__ __half g_at16[SEQ*QDIM];
__device__ __half g_x16q[SEQ*EMB], g_x16k[SEQ*EMB], g_x16v[SEQ*EMB];
__device__ __half g_w16q[EMB*QDIM], g_w16k[EMB*KVDIM], g_w16v[EMB*KVDIM], g_w16o[QDIM*EMB];

// ---------------- PTX helpers ----------------
#define LDSM_X4(r0,r1,r2,r3,addr) \
  asm volatile("ldmatrix.sync.aligned.m8n8.x4.shared.b16 {%0,%1,%2,%3}, [%4];" \
    : "=r"(r0),"=r"(r1),"=r"(r2),"=r"(r3) : "r"(addr))

#define LDSM_X4_T(r0,r1,r2,r3,addr) \
  asm volatile("ldmatrix.sync.aligned.m8n8.x4.trans.shared.b16 {%0,%1,%2,%3}, [%4];" \
    : "=r"(r0),"=r"(r1),"=r"(r2),"=r"(r3) : "r"(addr))

#define MMA16816H(c, a0,a1,a2,a3, b0,b1) \
  asm volatile("mma.sync.aligned.m16n8k16.row.col.f32.f16.f16.f32 " \
    "{%0,%1,%2,%3}, {%4,%5,%6,%7}, {%8,%9}, {%0,%1,%2,%3};" \
    : "+f"((c)[0]),"+f"((c)[1]),"+f"((c)[2]),"+f"((c)[3]) \
    : "r"(a0),"r"(a1),"r"(a2),"r"(a3),"r"(b0),"r"(b1))

#define CP_ASYNC16(dst32, srcptr) \
  asm volatile("cp.async.cg.shared.global [%0], [%1], 16;" :: "r"(dst32), "l"(srcptr))
#define CP_COMMIT() asm volatile("cp.async.commit_group;")
#define CP_WAIT0()  asm volatile("cp.async.wait_group 0;")

__device__ __forceinline__ unsigned packh2(float a, float b) {
    __half2 h = __floats2half2_rn(a, b);
    return *(unsigned*)&h;
}

// =====================================================================
// merged pre-pass: quantize all 7 tensors to fp16 (1 launch)
// =====================================================================
struct QArg { const float4* s; uint2* d; int nblk; };
struct QPack { QArg a[7]; };

__global__ __launch_bounds__(256) void quant_all(QPack p)
{
    int b = blockIdx.x;
    int seg = 0;
#pragma unroll
    for (int i = 0; i < 7; i++) {
        if (b >= p.a[seg].nblk) { b -= p.a[seg].nblk; seg++; }
    }
    const QArg sa = p.a[seg];
    int i = b * 256 + threadIdx.x;
    float4 v = sa.s[i];
    sa.d[i] = make_uint2(packh2(v.x, v.y), packh2(v.z, v.w));
}

// =====================================================================
// fp16 GEMM v10: C = A16 @ B16, 1 MMA/product, BK=64 (half the iters),
// CTA 128x128, warp 64x32, 2-stage overlap, 70KB smem -> 2 CTAs/SM.
// =====================================================================
#define A9_STRIDE 72    /* fp16 elems; row = 144B (128 data + pad) */
#define B9_STRIDE 136   /* fp16 elems; row = 272B */
#define G9_A  0
#define G9_B  18432
#define G9_STAGE 35840
#define SMEM_G9 (2*G9_STAGE)   /* 71680 */

struct GArg {
    const __half *A, *B;
    float* C;
    __half* C16;
    int N;
};

__global__ __launch_bounds__(256, 2) void gemm10(
    GArg a0, GArg a1, GArg a2, int t0, int t1, int K)
{
    extern __shared__ char smg[];
    const unsigned smu = (unsigned)__cvta_generic_to_shared(smg);

    GArg ga; int bx = blockIdx.x, bn;
    if (bx < t0)      { ga = a0; bn = bx * 128; }
    else if (bx < t1) { ga = a1; bn = (bx - t0) * 128; }
    else              { ga = a2; bn = (bx - t1) * 128; }
    const int N  = ga.N;
    const int bm = blockIdx.y * 128;

    const int tid  = threadIdx.x;
    const int warp = tid >> 5;
    const int lane = tid & 31;
    const int wm   = warp >> 2;   // 0..1
    const int wn   = warp & 3;    // 0..3

    float acc[4][4][4];
#pragma unroll
    for (int i = 0; i < 4; i++)
#pragma unroll
        for (int j = 0; j < 4; j++)
#pragma unroll
            for (int r = 0; r < 4; r++) acc[i][j][r] = 0.f;

    auto issue = [&](int stage, int k0) {
        unsigned sb = smu + stage * G9_STAGE;
        // A: 128 rows x 8 chunks = 1024 -> 4/thread
#pragma unroll
        for (int p = 0; p < 4; p++) {
            int idx = tid + p * 256;
            int row = idx >> 3, u = idx & 7;
            CP_ASYNC16(sb + G9_A + row*144 + u*16, ga.A + (size_t)(bm + row)*K + k0 + u*8);
        }
        // B: 64 rows x 16 chunks = 1024 -> 4/thread
#pragma unroll
        for (int p = 0; p < 4; p++) {
            int idx = tid + p * 256;
            int row = idx >> 4, u = idx & 15;
            CP_ASYNC16(sb + G9_B + row*272 + u*16, ga.B + (size_t)(k0 + row)*N + bn + u*8);
        }
        CP_COMMIT();
    };

    issue(0, 0);

    const int a_lrow = wm*64 + (lane & 15);
    const int a_lcol = (lane >> 4) * 8;

    const int nch = K / 64;
    for (int j = 0; j < nch; j++) {
        CP_WAIT0();
        __syncthreads();
        if (j + 1 < nch) issue((j + 1) & 1, (j + 1) * 64);

        const unsigned sa = smu + (j & 1) * G9_STAGE;

#pragma unroll
        for (int ks = 0; ks < 64; ks += 16) {
            unsigned ah[4][4];
#pragma unroll
            for (int mi = 0; mi < 4; mi++) {
                unsigned off = 2u * ((unsigned)((a_lrow + mi*16) * A9_STRIDE + ks + a_lcol));
                LDSM_X4(ah[mi][0], ah[mi][1], ah[mi][2], ah[mi][3], sa + G9_A + off);
            }
            unsigned bh[4][2];
#pragma unroll
            for (int nb = 0; nb < 2; nb++) {
                unsigned off = 2u * ((unsigned)((ks + (lane & 15)) * B9_STRIDE
                                               + wn*32 + nb*16 + (lane >> 4) * 8));
                unsigned r0, r1, r2, r3;
                LDSM_X4_T(r0, r1, r2, r3, sa + G9_B + off);
                bh[2*nb][0] = r0; bh[2*nb][1] = r1;
                bh[2*nb+1][0] = r2; bh[2*nb+1][1] = r3;
            }
#pragma unroll
            for (int mi = 0; mi < 4; mi++) {
#pragma unroll
                for (int ni = 0; ni < 4; ni++) {
                    MMA16816H(acc[mi][ni], ah[mi][0],ah[mi][1],ah[mi][2],ah[mi][3],
                              bh[ni][0], bh[ni][1]);
                }
            }
        }
    }

    const int g = lane >> 2, q = lane & 3;
#pragma unroll
    for (int mi = 0; mi < 4; mi++) {
#pragma unroll
        for (int ni = 0; ni < 4; ni++) {
            int row = bm + wm*64 + mi*16 + g;
            int col = bn + wn*32 + ni*8 + q*2;
            if (ga.C) {
                *(float2*)&ga.C[(size_t)row * N + col]       = make_float2(acc[mi][ni][0], acc[mi][ni][1]);
                *(float2*)&ga.C[(size_t)(row + 8) * N + col] = make_float2(acc[mi][ni][2], acc[mi][ni][3]);
            }
            if (ga.C16) {
                *(unsigned*)&ga.C16[(size_t)row * N + col]       = packh2(acc[mi][ni][0], acc[mi][ni][1]);
                *(unsigned*)&ga.C16[(size_t)(row + 8) * N + col] = packh2(acc[mi][ni][2], acc[mi][ni][3]);
            }
        }
    }
}

// =====================================================================
// RoPE: rotate fp32 q/k, scale q by log2(e)/sqrt(HD), emit fp16
// =====================================================================
__global__ __launch_bounds__(256) void rope3_kernel(
    const int* __restrict__ pos_w,
    const float* __restrict__ q, const float* __restrict__ k,
    __half* __restrict__ q16, __half* __restrict__ k16)
{
    const int s = blockIdx.x;
    const int tid = threadIdx.x;
    __shared__ float cs[64], sn[64];

    const float QSCALE = (float)(1.4426950408889634 * 0.08838834764831845);

    if (tid < 64) {
        bool is64 = (pos_w[1] == 0);
        int pi = is64 ? pos_w[2 * s] : pos_w[s];
        float p = (float)pi;
        float ex = (float)(2 * tid) / (float)HD;
        float inv = powf(10000.0f, -ex);
        float ang = p * inv;
        sincosf(ang, &sn[tid], &cs[tid]);
    }
    __syncthreads();

    for (int idx = tid; idx < NH * 64; idx += 256) {
        int h = idx >> 6, d = idx & 63;
        size_t base = (size_t)s * QDIM + h * HD;
        float x1 = q[base + d], x2 = q[base + d + 64];
        float c = cs[d], si = sn[d];
        q16[base + d]      = __float2half_rn((x1 * c - x2 * si) * QSCALE);
        q16[base + d + 64] = __float2half_rn((x2 * c + x1 * si) * QSCALE);
    }
    for (int idx = tid; idx < NKVH * 64; idx += 256) {
        int h = idx >> 6, d = idx & 63;
        size_t base = (size_t)s * KVDIM + h * HD;
        float x1 = k[base + d], x2 = k[base + d + 64];
        float c = cs[d], si = sn[d];
        k16[base + d]      = __float2half_rn(x1 * c - x2 * si);
        k16[base + d + 64] = __float2half_rn(x2 * c + x1 * si);
    }
}

// =====================================================================
// MMA flash attention v5: all fp16, 1 MMA/product, K-block = 128
// (half the softmax passes / loop iterations of v4).
// smem: Q 32KB + 2 x (K 32KB + V 32KB) = 160KB.
// =====================================================================
#define SMQ    0
#define KVBUF0 32768
#define KVSZ   65536
#define OF_K   0
#define OF_V   32768
#define SMEM_ATTN5 163840

__device__ __forceinline__ int swz(int row, int col_b16) {
    return row * 256 + ((((col_b16 >> 3) ^ (row & 7)) << 4)) + ((col_b16 & 7) << 1);
}

__global__ __launch_bounds__(256) void attn_mma5(
    const __half* __restrict__ Q16, const __half* __restrict__ K16,
    const __half* __restrict__ V16, __half* __restrict__ O16)
{
    extern __shared__ char sm[];
    const unsigned smu = (unsigned)__cvta_generic_to_shared(sm);

    const int tid  = threadIdx.x;
    const int warp = tid >> 5;
    const int lane = tid & 31;
    const int g    = lane >> 2;
    const int qd   = lane & 3;
    const int qb   = blockIdx.x;
    const int h    = blockIdx.y;
    const int kvh  = h >> 2;
    const int i0   = qb * 128;

    const int kb_lo = max(0, qb - 16);   // WIN/128 = 16
    const int kb_hi = qb;

    {
        // Q: 2048 chunks -> 8/thread
#pragma unroll
        for (int rep = 0; rep < 8; rep++) {
            int chunk = tid + rep * 256;
            int row = chunk >> 4, u = chunk & 15;
            unsigned dsto = row * 256 + (((u ^ (row & 7)) << 4));
            CP_ASYNC16(smu + SMQ + dsto, Q16 + (size_t)(i0 + row) * QDIM + h * HD + u * 8);
        }
        // K,V: 128 rows x 16 units = 2048 chunks each -> 8 reps each
#pragma unroll
        for (int rep = 0; rep < 8; rep++) {
            int chunk = tid + rep * 256;
            int row = chunk >> 4, u = chunk & 15;
            unsigned dsto = row * 256 + (((u ^ (row & 7)) << 4));
            size_t srco = (size_t)(kb_lo * 128 + row) * KVDIM + kvh * HD + u * 8;
            CP_ASYNC16(smu + KVBUF0 + OF_K + dsto, K16 + srco);
            CP_ASYNC16(smu + KVBUF0 + OF_V + dsto, V16 + srco);
        }
        CP_COMMIT();
    }

    float o[16][4];
#pragma unroll
    for (int i = 0; i < 16; i++)
#pragma unroll
        for (int c = 0; c < 4; c++) o[i][c] = 0.f;

    float m0 = -1e30f, m1 = -1e30f, l0s = 0.f, l1s = 0.f;

    const int ig0 = i0 + warp * 16 + g;
    const int ig1 = ig0 + 8;

    for (int kb = kb_lo; kb <= kb_hi; kb++) {
        CP_WAIT0();
        __syncthreads();

        const int buf = (kb - kb_lo) & 1;
        const unsigned kvb = smu + KVBUF0 + buf * KVSZ;

        if (kb + 1 <= kb_hi) {
            const unsigned nb = smu + KVBUF0 + (buf ^ 1) * KVSZ;
#pragma unroll
            for (int rep = 0; rep < 8; rep++) {
                int chunk = tid + rep * 256;
                int row = chunk >> 4, u = chunk & 15;
                unsigned dsto = row * 256 + (((u ^ (row & 7)) << 4));
                size_t srco = (size_t)((kb + 1) * 128 + row) * KVDIM + kvh * HD + u * 8;
                CP_ASYNC16(nb + OF_K + dsto, K16 + srco);
                CP_ASYNC16(nb + OF_V + dsto, V16 + srco);
            }
            CP_COMMIT();
        }

        // ---- S = Q K^T over 128 keys ----
        float S[16][4];
#pragma unroll
        for (int i = 0; i < 16; i++)
#pragma unroll
            for (int c = 0; c < 4; c++) S[i][c] = 0.f;

#pragma unroll
        for (int kc = 0; kc < 8; kc++) {
            unsigned a0,a1,a2,a3;
            {
                int aoff = swz(warp*16 + (lane & 15), kc*16 + (lane >> 4) * 8);
                LDSM_X4(a0,a1,a2,a3, smu + SMQ + aoff);
            }
#pragma unroll
            for (int ntp = 0; ntp < 8; ntp++) {
                int boff = swz(ntp*16 + (lane & 15), kc*16 + (lane >> 4) * 8);
                unsigned k0,k1,k2,k3;
                LDSM_X4(k0,k1,k2,k3, kvb + OF_K + boff);
                MMA16816H(S[2*ntp],   a0,a1,a2,a3, k0,k2);
                MMA16816H(S[2*ntp+1], a0,a1,a2,a3, k1,k3);
            }
        }

        // ---- mask (only boundary blocks) ----
        bool need_mask = (kb == qb) || (kb == qb - 16);
        if (need_mask) {
#pragma unroll
            for (int nt = 0; nt < 16; nt++) {
                int j0 = kb*128 + nt*8 + 2*qd;
                S[nt][0] = ((unsigned)(ig0 - j0)     <= (unsigned)WIN) ? S[nt][0] : -1e30f;
                S[nt][1] = ((unsigned)(ig0 - j0 - 1) <= (unsigned)WIN) ? S[nt][1] : -1e30f;
                S[nt][2] = ((unsigned)(ig1 - j0)     <= (unsigned)WIN) ? S[nt][2] : -1e30f;
                S[nt][3] = ((unsigned)(ig1 - j0 - 1) <= (unsigned)WIN) ? S[nt][3] : -1e30f;
            }
        }

        // ---- online softmax ----
        float mx0 = -1e30f, mx1 = -1e30f;
#pragma unroll
        for (int nt = 0; nt < 16; nt++) {
            mx0 = fmaxf(mx0, fmaxf(S[nt][0], S[nt][1]));
            mx1 = fmaxf(mx1, fmaxf(S[nt][2], S[nt][3]));
        }
        mx0 = fmaxf(mx0, __shfl_xor_sync(0xffffffffu, mx0, 1));
        mx0 = fmaxf(mx0, __shfl_xor_sync(0xffffffffu, mx0, 2));
        mx1 = fmaxf(mx1, __shfl_xor_sync(0xffffffffu, mx1, 1));
        mx1 = fmaxf(mx1, __shfl_xor_sync(0xffffffffu, mx1, 2));

        float mn0 = fmaxf(m0, mx0);
        float mn1 = fmaxf(m1, mx1);
        float a0 = exp2f(m0 - mn0);
        float a1 = exp2f(m1 - mn1);
        float ok0 = (mn0 > -5e29f) ? 1.f : 0.f;
        float ok1 = (mn1 > -5e29f) ? 1.f : 0.f;
        m0 = mn0; m1 = mn1;
        l0s *= a0; l1s *= a1;

#pragma unroll
        for (int nt = 0; nt < 16; nt++) {
            S[nt][0] = exp2f(S[nt][0] - mn0) * ok0;
            S[nt][1] = exp2f(S[nt][1] - mn0) * ok0;
            S[nt][2] = exp2f(S[nt][2] - mn1) * ok1;
            S[nt][3] = exp2f(S[nt][3] - mn1) * ok1;
            l0s += S[nt][0] + S[nt][1];
            l1s += S[nt][2] + S[nt][3];
        }

#pragma unroll
        for (int i = 0; i < 16; i++) {
            o[i][0] *= a0; o[i][1] *= a0;
            o[i][2] *= a1; o[i][3] *= a1;
        }

        // ---- pack P (fp16 A-frags), 8 key-chunks ----
        unsigned ph[8][4];
#pragma unroll
        for (int t = 0; t < 8; t++) {
            ph[t][0] = packh2(S[2*t][0],   S[2*t][1]);
            ph[t][1] = packh2(S[2*t][2],   S[2*t][3]);
            ph[t][2] = packh2(S[2*t+1][0], S[2*t+1][1]);
            ph[t][3] = packh2(S[2*t+1][2], S[2*t+1][3]);
        }

        // ---- O += P V ----
#pragma unroll
        for (int t = 0; t < 8; t++) {
#pragma unroll
            for (int ntp = 0; ntp < 8; ntp++) {
                int voff = swz(t*16 + (lane & 15), ntp*16 + (lane >> 4) * 8);
                unsigned v0,v1,v2,v3;
                LDSM_X4_T(v0,v1,v2,v3, kvb + OF_V + voff);
                MMA16816H(o[2*ntp],   ph[t][0],ph[t][1],ph[t][2],ph[t][3], v0,v1);
                MMA16816H(o[2*ntp+1], ph[t][0],ph[t][1],ph[t][2],ph[t][3], v2,v3);
            }
        }
    }

    l0s += __shfl_xor_sync(0xffffffffu, l0s, 1);
    l0s += __shfl_xor_sync(0xffffffffu, l0s, 2);
    l1s += __shfl_xor_sync(0xffffffffu, l1s, 1);
    l1s += __shfl_xor_sync(0xffffffffu, l1s, 2);
    float inv0 = 1.f / l0s;
    float inv1 = 1.f / l1s;

#pragma unroll
    for (int nt = 0; nt < 16; nt++) {
        int col = h * HD + nt * 8 + 2 * qd;
        *(unsigned*)&O16[(size_t)ig0 * QDIM + col] = packh2(o[nt][0] * inv0, o[nt][1] * inv0);
        *(unsigned*)&O16[(size_t)ig1 * QDIM + col] = packh2(o[nt][2] * inv1, o[nt][3] * inv1);
    }
}

// =====================================================================
extern "C" void kernel_launch(void* const* d_in, const int* in_sizes, int n_in,
                              void* d_out, int out_size)
{
    const float* query = (const float*)d_in[0];
    const float* key   = (const float*)d_in[1];
    const float* value = (const float*)d_in[2];
    const int*   pos   = (const int*)d_in[3];
    const float* wq    = (const float*)d_in[4];
    const float* wk    = (const float*)d_in[5];
    const float* wv    = (const float*)d_in[6];
    const float* wo    = (const float*)d_in[7];
    float*       out   = (float*)d_out;

    float *q_s, *k_s;
    __half *q16,*k16,*v16,*at16,*x16q,*x16k,*x16v;
    __half *w16q,*w16k,*w16v,*w16o;
    cudaGetSymbolAddress((void**)&q_s, g_q);     cudaGetSymbolAddress((void**)&k_s, g_k);
    cudaGetSymbolAddress((void**)&q16, g_q16);   cudaGetSymbolAddress((void**)&k16, g_k16);
    cudaGetSymbolAddress((void**)&v16, g_v16);   cudaGetSymbolAddress((void**)&at16, g_at16);
    cudaGetSymbolAddress((void**)&x16q, g_x16q); cudaGetSymbolAddress((void**)&x16k, g_x16k);
    cudaGetSymbolAddress((void**)&x16v, g_x16v);
    cudaGetSymbolAddress((void**)&w16q, g_w16q); cudaGetSymbolAddress((void**)&w16k, g_w16k);
    cudaGetSymbolAddress((void**)&w16v, g_w16v); cudaGetSymbolAddress((void**)&w16o, g_w16o);

    cudaFuncSetAttribute(attn_mma5, cudaFuncAttributeMaxDynamicSharedMemorySize, SMEM_ATTN5);
    cudaFuncSetAttribute(gemm10,    cudaFuncAttributeMaxDynamicSharedMemorySize, SMEM_G9);

    dim3 blk(256);

    // ---- merged quantize pre-pass (1 launch, 7 tensors) ----
    QPack sp;
    auto mk = [&](const float* s, __half* d, size_t n) {
        return QArg{ (const float4*)s, (uint2*)d, (int)(n / 4 / 256) };
    };
    sp.a[0] = mk(query, x16q, (size_t)SEQ * EMB);
    sp.a[1] = mk(key,   x16k, (size_t)SEQ * EMB);
    sp.a[2] = mk(value, x16v, (size_t)SEQ * EMB);
    sp.a[3] = mk(wq, w16q, (size_t)EMB * QDIM);
    sp.a[4] = mk(wk, w16k, (size_t)EMB * KVDIM);
    sp.a[5] = mk(wv, w16v, (size_t)EMB * KVDIM);
    sp.a[6] = mk(wo, w16o, (size_t)QDIM * EMB);
    int total_blk = 0;
    for (int i = 0; i < 7; i++) total_blk += sp.a[i].nblk;
    quant_all<<<total_blk, blk>>>(sp);

    // ---- q/k/v projections, one launch: x = [0,16)q [16,20)k [20,24)v ----
    GArg gq = { x16q, w16q, q_s, nullptr, QDIM };
    GArg gk = { x16k, w16k, k_s, nullptr, KVDIM };
    GArg gv = { x16v, w16v, nullptr, v16, KVDIM };
    gemm10<<<dim3(24, SEQ/128), blk, SMEM_G9>>>(gq, gk, gv, 16, 20, EMB);

    // ---- rope -> fp16 q/k ----
    rope3_kernel<<<SEQ, blk>>>(pos, q_s, k_s, q16, k16);

    // ---- attention ----
    attn_mma5<<<dim3(SEQ/128, NH), blk, SMEM_ATTN5>>>(q16, k16, v16, at16);

    // ---- output projection ----
    GArg go = { at16, w16o, out, nullptr, EMB };
    gemm10<<<dim3(16, SEQ/128), blk, SMEM_G9>>>(go, go, go, 16, 16, QDIM);
}